// round 10
// baseline (speedup 1.0000x reference)
#include <cuda_runtime.h>
#include <cuda_fp16.h>
#include <math.h>
#include <stdint.h>

#define NF 65536
#define NB 8
#define JQ 64
#define NSEC 224
#define NCHAN 289
#define LG 768
#define GTAPS 1537
#define KPHI 1024
#define INV_N (1.0f/65536.0f)
#define ZCUT 7.4395f       // e^{-0.5*z^2} ~ 1e-12
#define TS2 80             // full-res SO sections per batch (j2<=4)

// ---------------- static device storage ----------------
static __device__ float2  TW[NF];
static __device__ float   GF[GTAPS];
static __device__ float2  d_xtmp[  8u*65536u];
static __device__ float2  d_xf  [  8u*65536u];
static __device__ float2  d_p1a [ 512u*65536u];
static __device__ float2  d_p1b [ 512u*65536u];
static __device__ __half2 d_p2  [(size_t)640u*65536u];  // SO passA->passB (fp16, 4x true)
static __device__ __half2 d_u1f [ 512u*65536u];         // FFT(|U1|) fp16, scaled 1/4
static __device__ float   d_sp1 [  512u*4096u];
static __device__ float   d_sp2 [ 1792u*4096u];

static __device__ const float2 W16T[16] = {
  { 1.0f, 0.0f},
  { 0.9238795325112867f, 0.3826834323650898f},
  { 0.7071067811865476f, 0.7071067811865476f},
  { 0.3826834323650898f, 0.9238795325112867f},
  { 0.0f, 1.0f},
  {-0.3826834323650898f, 0.9238795325112867f},
  {-0.7071067811865476f, 0.7071067811865476f},
  {-0.9238795325112867f, 0.3826834323650898f},
  {-1.0f, 0.0f},
  {-0.9238795325112867f,-0.3826834323650898f},
  {-0.7071067811865476f,-0.7071067811865476f},
  {-0.3826834323650898f,-0.9238795325112867f},
  { 0.0f,-1.0f},
  { 0.3826834323650898f,-0.9238795325112867f},
  { 0.7071067811865476f,-0.7071067811865476f},
  { 0.9238795325112867f,-0.3826834323650898f}
};

// ---------------- helpers ----------------
__device__ __forceinline__ float2 cadd(float2 a, float2 b){ return make_float2(a.x+b.x, a.y+b.y); }
__device__ __forceinline__ float2 csub(float2 a, float2 b){ return make_float2(a.x-b.x, a.y-b.y); }
__device__ __forceinline__ float2 cmul(float2 a, float2 b){ return make_float2(a.x*b.x-a.y*b.y, a.x*b.y+a.y*b.x); }
__device__ __forceinline__ float2 h2f(__half2 h){ return __half22float2(h); }
__device__ __forceinline__ __half2 f2h(float2 v){ return __float22half2_rn(v); }
__device__ __forceinline__ float cmag(float2 z){
  float x2 = z.x*z.x + z.y*z.y + 1e-36f;
  return x2 * rsqrtf(x2);
}
template<int S> __device__ __forceinline__ float2 mul_i(float2 a){
  return (S>0) ? make_float2(-a.y, a.x) : make_float2(a.y, -a.x);
}
template<int S> __device__ __forceinline__ void dft4(float2&a, float2&b, float2&c, float2&d){
  float2 t0=cadd(a,c), t1=csub(a,c), t2=cadd(b,d), t3=mul_i<S>(csub(b,d));
  a=cadd(t0,t2); c=csub(t0,t2); b=cadd(t1,t3); d=csub(t1,t3);
}
template<int S> __device__ __forceinline__ float2 w16(int m){
  float2 w = W16T[m];
  if (S < 0) w.y = -w.y;
  return w;
}
template<int S> __device__ __forceinline__ void fft16(float2 v[16]){
  #pragma unroll
  for (int n0=0; n0<4; n0++) dft4<S>(v[n0], v[n0+4], v[n0+8], v[n0+12]);
  #pragma unroll
  for (int n0=1; n0<4; n0++)
    #pragma unroll
    for (int k1=1; k1<4; k1++)
      v[n0+4*k1] = cmul(v[n0+4*k1], w16<S>(n0*k1));
  float2 o[16];
  #pragma unroll
  for (int k1=0; k1<4; k1++){
    float2 a=v[4*k1+0], b=v[4*k1+1], c=v[4*k1+2], d=v[4*k1+3];
    dft4<S>(a,b,c,d);
    o[k1]=a; o[k1+4]=b; o[k1+8]=c; o[k1+12]=d;
  }
  #pragma unroll
  for (int i=0;i<16;i++) v[i]=o[i];
}

template<int S> __device__ __forceinline__ void fft256_pad(float2 v[16], int i, float2* sm){
  fft16<S>(v);
  #pragma unroll
  for (int k1=1;k1<16;k1++){
    float2 w = TW[(i*k1*256)&65535];
    if (S<0) w.y = -w.y;
    v[k1] = cmul(v[k1], w);
  }
  #pragma unroll
  for (int k1=0;k1<16;k1++) sm[k1*16+i] = v[k1];
  __syncthreads();
  #pragma unroll
  for (int n0=0;n0<16;n0++) v[n0] = sm[i*16+n0];
  fft16<S>(v);
}

template<int S> __device__ __forceinline__ void fft256_swz(float2 v[16], int i, float2* sm){
  fft16<S>(v);
  #pragma unroll
  for (int k1=1;k1<16;k1++){
    float2 w = TW[(i*k1*256)&65535];
    if (S<0) w.y = -w.y;
    v[k1] = cmul(v[k1], w);
  }
  #pragma unroll
  for (int k1=0;k1<16;k1++) sm[k1*16 + ((i+k1)&15)] = v[k1];
  __syncwarp();
  #pragma unroll
  for (int n0=0;n0<16;n0++) v[n0] = sm[i*16 + ((n0+i)&15)];
  fft16<S>(v);
}

__device__ __forceinline__ void conv_partial(const float* u_s, const float* gf_s,
                                             int bx, int m, float* sp)
{
  float acc = 0.0f;
  #pragma unroll
  for (int f2=0; f2<16; f2++){
    const int q = bx*16 + f2 + 768;
    #pragma unroll
    for (int d=-3; d<=3; d++){
      int tap = d*256 + q;
      if (tap >= 0 && tap <= 1536)
        acc += gf_s[tap] * u_s[f2*257 + ((m + d) & 255)];
    }
  }
  sp[bx*256 + m] = acc;
}

// ---------------- setup kernels ----------------
__global__ void k_tw(){
  int k = blockIdx.x*blockDim.x + threadIdx.x;
  double a = 6.283185307179586476925286766559 * (double)k / 65536.0;
  TW[k] = make_float2((float)cos(a), (float)sin(a));
}
// lowpass taps: hoist the 1024 Gaussian weights into smem once per block
__global__ void k_g(){
  __shared__ float ps[KPHI+1];
  const int tid = threadIdx.x;
  const float invden = 1.0f/(65536.0f*(0.35f/256.0f));
  for (int k=tid; k<=KPHI; k+=256){
    float z = (float)k * invden;
    ps[k] = 2.0f*expf(-0.5f*z*z);
  }
  __syncthreads();
  int i = blockIdx.x*256 + tid;
  if (i >= GTAPS) return;
  int tt = i - LG; if (tt < 0) tt = -tt;
  float acc = 1.0f;
  for (int k=1; k<=KPHI; k++)
    acc += ps[k] * TW[(k*tt) & 65535].x;
  GF[i] = acc * INV_N;
}

// ---------------- FFT pass kernels ----------------
__global__ void __launch_bounds__(256) k_fwd_col_x(const float* __restrict__ x,
                                                   float2* __restrict__ out)
{
  __shared__ float2 sm[16*257];
  const int f = threadIdx.x & 15, i = threadIdx.x >> 4;
  const int col = blockIdx.x*16 + f;
  const size_t base = (size_t)blockIdx.y * NF;
  float2 v[16];
  #pragma unroll
  for (int r=0;r<16;r++) v[r] = make_float2(x[base + (r*16+i)*256 + col], 0.0f);
  fft256_pad<-1>(v, i, sm + f*257);
  #pragma unroll
  for (int k2=0;k2<16;k2++){
    int K1 = k2*16 + i;
    float2 w = TW[(col*K1)&65535]; w.y = -w.y;
    out[base + K1*256 + col] = cmul(v[k2], w);
  }
}

__global__ void __launch_bounds__(256) k_fwd_row(const float2* __restrict__ in,
                                                 float2* __restrict__ out)
{
  __shared__ float2 sm[16*256];
  const int i = threadIdx.x & 15, f = threadIdx.x >> 4;
  const int row = blockIdx.x*16 + f;
  const size_t base = (size_t)blockIdx.y * NF;
  float2 v[16];
  #pragma unroll
  for (int r=0;r<16;r++) v[r] = in[base + row*256 + r*16 + i];
  fft256_swz<-1>(v, i, sm + f*256);
  #pragma unroll
  for (int k2=0;k2<16;k2++) out[base + row*256 + k2*16 + i] = v[k2];
}

__global__ void __launch_bounds__(256) k_fwd_row_u1(const float2* __restrict__ in,
                                                    __half2* __restrict__ out)
{
  __shared__ float2 sm[16*256];
  const int i = threadIdx.x & 15, f = threadIdx.x >> 4;
  const int row = blockIdx.x*16 + f;
  const size_t base = (size_t)blockIdx.y * NF;
  float2 v[16];
  #pragma unroll
  for (int r=0;r<16;r++) v[r] = in[base + row*256 + r*16 + i];
  fft256_swz<-1>(v, i, sm + f*256);
  #pragma unroll
  for (int k2=0;k2<16;k2++){
    float2 o = v[k2];
    out[base + row*256 + k2*16 + i] = f2h(make_float2(o.x*0.25f, o.y*0.25f));
  }
}

__global__ void __launch_bounds__(256) k_invA1(const float2* __restrict__ in,
                                               float2* __restrict__ out)
{
  __shared__ float2 sm[16*256];
  const int i = threadIdx.x & 15, f = threadIdx.x >> 4;
  const int K1 = blockIdx.x*16 + f;
  const int ti = blockIdx.y;
  const int b = ti >> 6, ch = ti & 63;
  const float xi   = 0.35f * exp2f(-(float)ch * 0.125f);
  const float invs = 8.0f / xi;
  const float2* src = in + (size_t)b*NF;

  float2 v[16];
  #pragma unroll
  for (int r=0;r<16;r++){
    int k = (r*16 + i)*256 + K1;
    float fn = (k < 32768) ? (float)k * INV_N : ((float)k - 65536.0f) * INV_N;
    float z = (fn - xi) * invs;
    if (fabsf(z) < ZCUT){
      float g = expf(-0.5f*z*z);
      float2 X = src[K1*256 + (r*16+i)];
      float s = g * INV_N;
      v[r] = make_float2(X.x*s, X.y*s);
    } else v[r] = make_float2(0.0f, 0.0f);
  }
  fft256_swz<1>(v, i, sm + f*256);
  #pragma unroll
  for (int k2=0;k2<16;k2++){
    int n2 = k2*16 + i;
    out[(size_t)ti*NF + K1*256 + n2] = cmul(v[k2], TW[(n2*K1)&65535]);
  }
}

// SO inverse pass A (full-res sections only, j2<=4). s = g*16/N.
__global__ void __launch_bounds__(256) k_invA2(const __half2* __restrict__ in,
                                               __half2* __restrict__ out)
{
  __shared__ float2 sm[16*256];
  const int i = threadIdx.x & 15, f = threadIdx.x >> 4;
  const int K1 = blockIdx.x*16 + f;
  const int ti = blockIdx.y;
  const int b = ti / TS2;
  const int s0 = ti - b*TS2;
  int j2 = 1;
  #pragma unroll
  for (int q=1; q<4; q++) if (s0 >= 4*q*(q+1)) j2 = q+1;
  const int ch = s0 - 4*j2*(j2-1);
  const float xi   = 0.35f * exp2f(-(float)j2);
  const float invs = 1.0f / (0.6f * xi);
  const __half2* src = in + ((size_t)b*JQ + ch)*NF;

  float2 v[16];
  #pragma unroll
  for (int r=0;r<16;r++){
    int k = (r*16 + i)*256 + K1;
    float fn = (k < 32768) ? (float)k * INV_N : ((float)k - 65536.0f) * INV_N;
    float z = (fn - xi) * invs;
    if (fabsf(z) < ZCUT){
      float g = expf(-0.5f*z*z);
      float2 X = h2f(src[K1*256 + (r*16+i)]);
      float s = g * (16.0f*INV_N);
      v[r] = make_float2(X.x*s, X.y*s);
    } else v[r] = make_float2(0.0f, 0.0f);
  }
  fft256_swz<1>(v, i, sm + f*256);
  #pragma unroll
  for (int k2=0;k2<16;k2++){
    int n2 = k2*16 + i;
    out[(size_t)ti*NF + K1*256 + n2] = f2h(cmul(v[k2], TW[(n2*K1)&65535]));
  }
}

__global__ void __launch_bounds__(256) k_fo_b(const float2* __restrict__ T,
                                              float2* __restrict__ out,
                                              float* __restrict__ sp1)
{
  __shared__ __align__(16) char smraw[16*257*sizeof(float2)];
  float2* sm   = (float2*)smraw;
  float*  u_s  = (float*)smraw;
  float*  gf_s = (float*)smraw + 16*257;

  const int f = threadIdx.x & 15, i = threadIdx.x >> 4;
  const int tid = threadIdx.x;
  const int n2 = blockIdx.x*16 + f;
  const size_t base = (size_t)blockIdx.y * NF;
  float2 v[16];
  #pragma unroll
  for (int r=0;r<16;r++) v[r] = T[base + (r*16+i)*256 + n2];
  fft256_pad<1>(v, i, sm + f*257);
  __syncthreads();
  #pragma unroll
  for (int k2=0;k2<16;k2++)
    u_s[f*257 + k2*16 + i] = cmag(v[k2]);
  for (int t=tid; t<GTAPS; t+=256) gf_s[t] = GF[t];
  __syncthreads();
  conv_partial(u_s, gf_s, blockIdx.x, tid, sp1 + (size_t)blockIdx.y*4096);
  __syncthreads();
  #pragma unroll
  for (int r=0;r<16;r++) v[r] = make_float2(u_s[f*257 + r*16 + i], 0.0f);
  __syncthreads();
  fft256_pad<-1>(v, i, sm + f*257);
  #pragma unroll
  for (int k2=0;k2<16;k2++){
    int K1 = k2*16 + i;
    float2 w = TW[(n2*K1)&65535]; w.y = -w.y;
    out[base + K1*256 + n2] = cmul(v[k2], w);
  }
}

__global__ void __launch_bounds__(256) k_invB_abs(const __half2* __restrict__ T,
                                                  float* __restrict__ sp2)
{
  __shared__ __align__(16) char smraw[16*257*sizeof(float2)];
  float2* sm   = (float2*)smraw;
  float*  u_s  = (float*)smraw;
  float*  gf_s = (float*)smraw + 16*257;

  const int f = threadIdx.x & 15, i = threadIdx.x >> 4;
  const int tid = threadIdx.x;
  const int n2 = blockIdx.x*16 + f;
  const int ti = blockIdx.y;
  const int b = ti / TS2, s0 = ti - b*TS2;
  const size_t base = (size_t)ti * NF;
  float2 v[16];
  #pragma unroll
  for (int r=0;r<16;r++) v[r] = h2f(T[base + (r*16+i)*256 + n2]);
  fft256_pad<1>(v, i, sm + f*257);
  __syncthreads();
  #pragma unroll
  for (int k2=0;k2<16;k2++)
    u_s[f*257 + k2*16 + i] = 0.25f*cmag(v[k2]);
  for (int t=tid; t<GTAPS; t+=256) gf_s[t] = GF[t];
  __syncthreads();
  conv_partial(u_s, gf_s, blockIdx.x, tid, sp2 + (size_t)(b*NSEC + s0)*4096);
}

// Fused decimated SO, N'=4096 (j2 in {6,7}).
__global__ void __launch_bounds__(256) k_so4096(const __half2* __restrict__ u1f,
                                                float* __restrict__ sp2)
{
  extern __shared__ char dyn[];
  float2* sm  = (float2*)dyn;               // 16*257 f2
  float2* sA  = (float2*)dyn + 4112;        // 256*17 f2
  float*  sU  = (float*)dyn;                // 4096+128 floats (overlay sm)
  float*  g16 = (float*)dyn + 4300;         // 97 floats

  const int t = threadIdx.x;
  const int f = t & 15, i = t >> 4;
  const int s0 = 120 + blockIdx.x;          // 120..223
  const int b  = blockIdx.y;
  const int j2 = (s0 >= 168) ? 7 : 6;
  const int ch = s0 - 4*j2*(j2-1);
  const float xi   = 0.35f * exp2f(-(float)j2);
  const float invs = 1.0f/(0.6f*xi);
  const float kcf  = xi * 65536.0f;
  const __half2* src = u1f + ((size_t)b*JQ + ch)*NF;

  float2 v[16];
  #pragma unroll
  for (int r=0;r<16;r++){
    int kp = r*256 + i*16 + f;
    int d  = (int)floorf((kcf - (float)kp) * (1.0f/4096.0f) + 0.5f);
    int k  = (kp + (d << 12)) & 65535;
    float fn = (k < 32768) ? (float)k*INV_N : ((float)k - 65536.0f)*INV_N;
    float z = (fn - xi)*invs;
    if (fabsf(z) < ZCUT){
      float g = expf(-0.5f*z*z);
      float2 X = h2f(src[(k & 255)*256 + (k >> 8)]);
      float s = g * (4.0f*INV_N);
      v[r] = make_float2(X.x*s, X.y*s);
    } else v[r] = make_float2(0.0f, 0.0f);
  }
  fft256_pad<1>(v, i, sm + f*257);
  #pragma unroll
  for (int k2=0;k2<16;k2++){
    int a = k2*16 + i;
    sA[a*17 + f] = cmul(v[k2], TW[(a*f*16)&65535]);
  }
  __syncthreads();

  {
    float2 w[16];
    #pragma unroll
    for (int kB=0;kB<16;kB++) w[kB] = sA[t*17 + kB];
    fft16<1>(w);
    #pragma unroll
    for (int bb=0;bb<16;bb++){
      int m = t + 256*bb;
      sU[m + (m>>5)] = cmag(w[bb]);
    }
  }
  if (t < 97) g16[t] = GF[16*t];
  __syncthreads();

  float acc = 0.0f;
  for (int j=0;j<97;j++){
    int m = (16*t + j - 48) & 4095;
    acc += g16[j] * sU[m + (m>>5)];
  }
  float* o = sp2 + (size_t)(b*NSEC + s0)*4096;
  o[t] = 16.0f*acc;
  #pragma unroll
  for (int k=1;k<16;k++) o[k*256 + t] = 0.0f;
}

// Fused decimated SO, N'=8192, M=8 (j2 == 5). 256x32 four-step.
__global__ void __launch_bounds__(256) k_so8192(const __half2* __restrict__ u1f,
                                                float* __restrict__ sp2)
{
  extern __shared__ char dyn[];
  // region0: 8704 floats = sm (16*257 f2 = 8224 fl) / later sU (8448 fl) + g8 (193 fl)
  // region1: sA = 256*33 f2 at float-offset 8704
  float2* sm  = (float2*)dyn;
  float*  sU  = (float*)dyn;
  float*  g8  = (float*)dyn + 8450;
  float2* sA  = (float2*)dyn + 4352;

  const int t = threadIdx.x;
  const int f = t & 15, i = t >> 4;
  const int s0 = TS2 + blockIdx.x;          // 80..119
  const int ch = s0 - TS2;
  const int b  = blockIdx.y;
  const float xi   = 0.35f * exp2f(-5.0f);
  const float invs = 1.0f/(0.6f*xi);
  const float kcf  = xi * 65536.0f;
  const __half2* src = u1f + ((size_t)b*JQ + ch)*NF;

  // pass A: two rounds of 16 x 256-pt inverse FFTs over kA (kB = R*16+f)
  #pragma unroll
  for (int R=0; R<2; R++){
    const int kB = R*16 + f;
    float2 v[16];
    #pragma unroll
    for (int r=0;r<16;r++){
      int kA = r*16 + i;
      int kp = kA*32 + kB;
      int d  = (int)floorf((kcf - (float)kp) * (1.0f/8192.0f) + 0.5f);
      int k  = (kp + (d << 13)) & 65535;
      float fn = (k < 32768) ? (float)k*INV_N : ((float)k - 65536.0f)*INV_N;
      float z = (fn - xi)*invs;
      if (fabsf(z) < ZCUT){
        float g = expf(-0.5f*z*z);
        float2 X = h2f(src[(k & 255)*256 + (k >> 8)]);
        float s = g * (4.0f*INV_N);
        v[r] = make_float2(X.x*s, X.y*s);
      } else v[r] = make_float2(0.0f, 0.0f);
    }
    fft256_pad<1>(v, i, sm + f*257);
    #pragma unroll
    for (int k2=0;k2<16;k2++){
      int a = k2*16 + i;
      sA[a*33 + kB] = cmul(v[k2], TW[(a*kB*8)&65535]);   // e^{+2pi i a kB/8192}
    }
    __syncthreads();
  }

  // pass B: per-thread 32-pt inverse FFT over kB (radix-2 split into two fft16)
  {
    float2 E[16], O[16];
    #pragma unroll
    for (int k=0;k<16;k++){
      E[k] = sA[t*33 + 2*k];
      O[k] = sA[t*33 + 2*k + 1];
    }
    fft16<1>(E); fft16<1>(O);
    #pragma unroll
    for (int k=0;k<16;k++){
      float2 w = TW[k*2048];                 // e^{+2pi i k/32}
      float2 wo = cmul(w, O[k]);
      float2 X0 = cadd(E[k], wo);            // bb = k
      float2 X1 = csub(E[k], wo);            // bb = k+16
      int m0 = k*256 + t;
      int m1 = (k+16)*256 + t;
      sU[m0 + (m0>>5)] = cmag(X0);
      sU[m1 + (m1>>5)] = cmag(X1);
    }
  }
  if (t < 193) g8[t] = GF[8*t];
  __syncthreads();

  // decimated lowpass: S(p=t) = 8 * sum_j GF[8j] * u'(32t + j - 96)
  float acc = 0.0f;
  for (int j=0;j<193;j++){
    int m = (32*t + j - 96) & 8191;
    acc += g8[j] * sU[m + (m>>5)];
  }
  float* o = sp2 + (size_t)(b*NSEC + s0)*4096;
  o[t] = 8.0f*acc;
  #pragma unroll
  for (int k=1;k<16;k++) o[k*256 + t] = 0.0f;
}

// ---------------- S0 conv ----------------
#define CONV_OUT 32
#define CONV_WIN ((CONV_OUT-1)*256 + GTAPS)
__global__ void __launch_bounds__(256) k_conv_x(const float* __restrict__ x,
                                                float* __restrict__ out)
{
  const int grp = blockIdx.x, b = blockIdx.y;
  const float* src = x + (size_t)b*NF;
  __shared__ float win[CONV_WIN + 3];
  __shared__ float gs[GTAPS];
  const int tid = threadIdx.x;
  const int w0 = grp*(CONV_OUT*256) - LG;
  for (int i=tid; i<CONV_WIN; i+=256) win[i] = src[(w0 + i) & 65535];
  for (int i=tid; i<GTAPS; i+=256) gs[i] = GF[i];
  __syncthreads();
  const int warp = tid >> 5, lane = tid & 31;
  #pragma unroll
  for (int oo=0; oo<CONV_OUT/8; oo++){
    const int o = warp*(CONV_OUT/8) + oo;
    const int off = o * 256;
    float acc = 0.0f;
    for (int i=lane; i<GTAPS; i+=32) acc += gs[i] * win[off + i];
    #pragma unroll
    for (int d=16; d; d>>=1) acc += __shfl_down_sync(0xffffffffu, acc, d);
    if (lane == 0){
      int n = grp*CONV_OUT + o;
      float mag = sqrtf(acc*acc + 1e-8f);
      out[(size_t)b*NCHAN*256 + n] = logf(mag + 1e-8f);
    }
  }
}

// ---------------- epilogue ----------------
__global__ void __launch_bounds__(256) k_log(const float* __restrict__ sp1,
                                             const float* __restrict__ sp2,
                                             float* __restrict__ out)
{
  const int row = blockIdx.x;
  const int b = row / 288, cm1 = row - b*288;
  const int m = threadIdx.x;
  const float* base = (cm1 < 64)
    ? sp1 + (size_t)(b*JQ   + cm1     )*4096
    : sp2 + (size_t)(b*NSEC + cm1 - 64)*4096;
  float S = 0.0f;
  #pragma unroll
  for (int k=0;k<16;k++) S += base[k*256 + m];
  float mag = sqrtf(S*S + 1e-8f);
  out[((size_t)b*NCHAN + 1 + cm1)*256 + m] = logf(mag + 1e-8f);
}

__global__ void k_zero(float* p, int n){
  int i = blockIdx.x*blockDim.x + threadIdx.x;
  if (i < n) p[i] = 0.0f;
}

// ---------------- launch ----------------
extern "C" void kernel_launch(void* const* d_in, const int* in_sizes, int n_in,
                              void* d_out, int out_size)
{
  (void)in_sizes; (void)n_in;
  const float* x = (const float*)d_in[0];
  float* out = (float*)d_out;

  float2 *xtmp, *xf, *p1a, *p1b;
  __half2 *p2, *u1f;
  float *sp1, *sp2;
  cudaGetSymbolAddress((void**)&xtmp, d_xtmp);
  cudaGetSymbolAddress((void**)&xf,   d_xf);
  cudaGetSymbolAddress((void**)&p1a,  d_p1a);
  cudaGetSymbolAddress((void**)&p1b,  d_p1b);
  cudaGetSymbolAddress((void**)&p2,   d_p2);
  cudaGetSymbolAddress((void**)&u1f,  d_u1f);
  cudaGetSymbolAddress((void**)&sp1,  d_sp1);
  cudaGetSymbolAddress((void**)&sp2,  d_sp2);

  static int smem_set = 0;
  if (!smem_set){
    cudaFuncSetAttribute(k_so4096, cudaFuncAttributeMaxDynamicSharedMemorySize, 69632);
    cudaFuncSetAttribute(k_so8192, cudaFuncAttributeMaxDynamicSharedMemorySize, 102400);
    smem_set = 1;
  }

  k_tw<<<256, 256>>>();
  k_g <<<7,   256>>>();

  // forward FFT of x
  k_fwd_col_x<<<dim3(16,8), 256>>>(x, xtmp);
  k_fwd_row  <<<dim3(16,8), 256>>>(xtmp, xf);

  // first order
  k_invA1     <<<dim3(16,512), 256>>>(xf, p1a);
  k_fo_b      <<<dim3(16,512), 256>>>(p1a, p1b, sp1);
  k_fwd_row_u1<<<dim3(16,512), 256>>>(p1b, u1f);

  // second order, full-res sections (j2 <= 4): 80 per batch
  k_invA2   <<<dim3(16, 8*TS2), 256>>>(u1f, p2);
  k_invB_abs<<<dim3(16, 8*TS2), 256>>>(p2, sp2);

  // second order, decimated: j2=5 at N'=8192, j2 in {6,7} at N'=4096
  k_so8192<<<dim3(40,  NB), 256, 102400>>>(u1f, sp2);
  k_so4096<<<dim3(104, NB), 256, 69632>>>(u1f, sp2);

  // S0 + epilogue
  k_conv_x<<<dim3(8, NB), 256>>>(x, out);
  k_log   <<<2304, 256>>>(sp1, sp2, out);

  int half = out_size / 2;
  k_zero<<<(half + 255)/256, 256>>>(out + half, half);
}

// round 11
// speedup vs baseline: 1.6119x; 1.6119x over previous
#include <cuda_runtime.h>
#include <cuda_fp16.h>
#include <math.h>
#include <stdint.h>

#define NF 65536
#define NB 8
#define JQ 64
#define NSEC 224
#define NCHAN 289
#define LG 768
#define GTAPS 1537
#define KPHI 1024
#define INV_N (1.0f/65536.0f)
#define ZCUT 7.4395f       // e^{-0.5*z^2} ~ 1e-12
#define TS2 80             // full-res SO sections per batch (j2<=4)

// ---------------- static device storage ----------------
static __device__ float2  TW[NF];
static __device__ float   GF[GTAPS];
static __device__ float2  d_xtmp[  8u*65536u];
static __device__ float2  d_xf  [  8u*65536u];
static __device__ float2  d_p1a [ 512u*65536u];
static __device__ float2  d_p1b [ 512u*65536u];
static __device__ __half2 d_p2  [(size_t)640u*65536u];  // SO passA->passB (fp16, 4x true)
static __device__ __half2 d_u1f [ 512u*65536u];         // FFT(|U1|) fp16, scaled 1/4
static __device__ float   d_sp1 [  512u*4096u];
static __device__ float   d_sp2 [ 1792u*4096u];

static __device__ const float2 W16T[16] = {
  { 1.0f, 0.0f},
  { 0.9238795325112867f, 0.3826834323650898f},
  { 0.7071067811865476f, 0.7071067811865476f},
  { 0.3826834323650898f, 0.9238795325112867f},
  { 0.0f, 1.0f},
  {-0.3826834323650898f, 0.9238795325112867f},
  {-0.7071067811865476f, 0.7071067811865476f},
  {-0.9238795325112867f, 0.3826834323650898f},
  {-1.0f, 0.0f},
  {-0.9238795325112867f,-0.3826834323650898f},
  {-0.7071067811865476f,-0.7071067811865476f},
  {-0.3826834323650898f,-0.9238795325112867f},
  { 0.0f,-1.0f},
  { 0.3826834323650898f,-0.9238795325112867f},
  { 0.7071067811865476f,-0.7071067811865476f},
  { 0.9238795325112867f,-0.3826834323650898f}
};

// ---------------- helpers ----------------
__device__ __forceinline__ float2 cadd(float2 a, float2 b){ return make_float2(a.x+b.x, a.y+b.y); }
__device__ __forceinline__ float2 csub(float2 a, float2 b){ return make_float2(a.x-b.x, a.y-b.y); }
__device__ __forceinline__ float2 cmul(float2 a, float2 b){ return make_float2(a.x*b.x-a.y*b.y, a.x*b.y+a.y*b.x); }
__device__ __forceinline__ float2 h2f(__half2 h){ return __half22float2(h); }
__device__ __forceinline__ __half2 f2h(float2 v){ return __float22half2_rn(v); }
__device__ __forceinline__ float cmag(float2 z){
  float x2 = z.x*z.x + z.y*z.y + 1e-36f;
  return x2 * rsqrtf(x2);
}
template<int S> __device__ __forceinline__ float2 mul_i(float2 a){
  return (S>0) ? make_float2(-a.y, a.x) : make_float2(a.y, -a.x);
}
template<int S> __device__ __forceinline__ void dft4(float2&a, float2&b, float2&c, float2&d){
  float2 t0=cadd(a,c), t1=csub(a,c), t2=cadd(b,d), t3=mul_i<S>(csub(b,d));
  a=cadd(t0,t2); c=csub(t0,t2); b=cadd(t1,t3); d=csub(t1,t3);
}
template<int S> __device__ __forceinline__ float2 w16(int m){
  float2 w = W16T[m];
  if (S < 0) w.y = -w.y;
  return w;
}
template<int S> __device__ __forceinline__ void fft16(float2 v[16]){
  #pragma unroll
  for (int n0=0; n0<4; n0++) dft4<S>(v[n0], v[n0+4], v[n0+8], v[n0+12]);
  #pragma unroll
  for (int n0=1; n0<4; n0++)
    #pragma unroll
    for (int k1=1; k1<4; k1++)
      v[n0+4*k1] = cmul(v[n0+4*k1], w16<S>(n0*k1));
  float2 o[16];
  #pragma unroll
  for (int k1=0; k1<4; k1++){
    float2 a=v[4*k1+0], b=v[4*k1+1], c=v[4*k1+2], d=v[4*k1+3];
    dft4<S>(a,b,c,d);
    o[k1]=a; o[k1+4]=b; o[k1+8]=c; o[k1+12]=d;
  }
  #pragma unroll
  for (int i=0;i<16;i++) v[i]=o[i];
}

template<int S> __device__ __forceinline__ void fft256_pad(float2 v[16], int i, float2* sm){
  fft16<S>(v);
  #pragma unroll
  for (int k1=1;k1<16;k1++){
    float2 w = TW[(i*k1*256)&65535];
    if (S<0) w.y = -w.y;
    v[k1] = cmul(v[k1], w);
  }
  #pragma unroll
  for (int k1=0;k1<16;k1++) sm[k1*16+i] = v[k1];
  __syncthreads();
  #pragma unroll
  for (int n0=0;n0<16;n0++) v[n0] = sm[i*16+n0];
  fft16<S>(v);
}

template<int S> __device__ __forceinline__ void fft256_swz(float2 v[16], int i, float2* sm){
  fft16<S>(v);
  #pragma unroll
  for (int k1=1;k1<16;k1++){
    float2 w = TW[(i*k1*256)&65535];
    if (S<0) w.y = -w.y;
    v[k1] = cmul(v[k1], w);
  }
  #pragma unroll
  for (int k1=0;k1<16;k1++) sm[k1*16 + ((i+k1)&15)] = v[k1];
  __syncwarp();
  #pragma unroll
  for (int n0=0;n0<16;n0++) v[n0] = sm[i*16 + ((n0+i)&15)];
  fft16<S>(v);
}

__device__ __forceinline__ void conv_partial(const float* u_s, const float* gf_s,
                                             int bx, int m, float* sp)
{
  float acc = 0.0f;
  #pragma unroll
  for (int f2=0; f2<16; f2++){
    const int q = bx*16 + f2 + 768;
    #pragma unroll
    for (int d=-3; d<=3; d++){
      int tap = d*256 + q;
      if (tap >= 0 && tap <= 1536)
        acc += gf_s[tap] * u_s[f2*257 + ((m + d) & 255)];
    }
  }
  sp[bx*256 + m] = acc;
}

// ---------------- setup kernels ----------------
__global__ void k_tw(){
  int k = blockIdx.x*blockDim.x + threadIdx.x;
  double a = 6.283185307179586476925286766559 * (double)k / 65536.0;
  TW[k] = make_float2((float)cos(a), (float)sin(a));
}
__global__ void k_g(){
  __shared__ float ps[KPHI+1];
  const int tid = threadIdx.x;
  const float invden = 1.0f/(65536.0f*(0.35f/256.0f));
  for (int k=tid; k<=KPHI; k+=256){
    float z = (float)k * invden;
    ps[k] = 2.0f*expf(-0.5f*z*z);
  }
  __syncthreads();
  int i = blockIdx.x*256 + tid;
  if (i >= GTAPS) return;
  int tt = i - LG; if (tt < 0) tt = -tt;
  float acc = 1.0f;
  for (int k=1; k<=KPHI; k++)
    acc += ps[k] * TW[(k*tt) & 65535].x;
  GF[i] = acc * INV_N;
}

// ---------------- FFT pass kernels ----------------
__global__ void __launch_bounds__(256) k_fwd_col_x(const float* __restrict__ x,
                                                   float2* __restrict__ out)
{
  __shared__ float2 sm[16*257];
  const int f = threadIdx.x & 15, i = threadIdx.x >> 4;
  const int col = blockIdx.x*16 + f;
  const size_t base = (size_t)blockIdx.y * NF;
  float2 v[16];
  #pragma unroll
  for (int r=0;r<16;r++) v[r] = make_float2(x[base + (r*16+i)*256 + col], 0.0f);
  fft256_pad<-1>(v, i, sm + f*257);
  #pragma unroll
  for (int k2=0;k2<16;k2++){
    int K1 = k2*16 + i;
    float2 w = TW[(col*K1)&65535]; w.y = -w.y;
    out[base + K1*256 + col] = cmul(v[k2], w);
  }
}

__global__ void __launch_bounds__(256) k_fwd_row(const float2* __restrict__ in,
                                                 float2* __restrict__ out)
{
  __shared__ float2 sm[16*256];
  const int i = threadIdx.x & 15, f = threadIdx.x >> 4;
  const int row = blockIdx.x*16 + f;
  const size_t base = (size_t)blockIdx.y * NF;
  float2 v[16];
  #pragma unroll
  for (int r=0;r<16;r++) v[r] = in[base + row*256 + r*16 + i];
  fft256_swz<-1>(v, i, sm + f*256);
  #pragma unroll
  for (int k2=0;k2<16;k2++) out[base + row*256 + k2*16 + i] = v[k2];
}

__global__ void __launch_bounds__(256) k_fwd_row_u1(const float2* __restrict__ in,
                                                    __half2* __restrict__ out)
{
  __shared__ float2 sm[16*256];
  const int i = threadIdx.x & 15, f = threadIdx.x >> 4;
  const int row = blockIdx.x*16 + f;
  const size_t base = (size_t)blockIdx.y * NF;
  float2 v[16];
  #pragma unroll
  for (int r=0;r<16;r++) v[r] = in[base + row*256 + r*16 + i];
  fft256_swz<-1>(v, i, sm + f*256);
  #pragma unroll
  for (int k2=0;k2<16;k2++){
    float2 o = v[k2];
    out[base + row*256 + k2*16 + i] = f2h(make_float2(o.x*0.25f, o.y*0.25f));
  }
}

__global__ void __launch_bounds__(256) k_invA1(const float2* __restrict__ in,
                                               float2* __restrict__ out)
{
  __shared__ float2 sm[16*256];
  const int i = threadIdx.x & 15, f = threadIdx.x >> 4;
  const int K1 = blockIdx.x*16 + f;
  const int ti = blockIdx.y;
  const int b = ti >> 6, ch = ti & 63;
  const float xi   = 0.35f * exp2f(-(float)ch * 0.125f);
  const float invs = 8.0f / xi;
  const float2* src = in + (size_t)b*NF;

  float2 v[16];
  #pragma unroll
  for (int r=0;r<16;r++){
    int k = (r*16 + i)*256 + K1;
    float fn = (k < 32768) ? (float)k * INV_N : ((float)k - 65536.0f) * INV_N;
    float z = (fn - xi) * invs;
    if (fabsf(z) < ZCUT){
      float g = expf(-0.5f*z*z);
      float2 X = src[K1*256 + (r*16+i)];
      float s = g * INV_N;
      v[r] = make_float2(X.x*s, X.y*s);
    } else v[r] = make_float2(0.0f, 0.0f);
  }
  fft256_swz<1>(v, i, sm + f*256);
  #pragma unroll
  for (int k2=0;k2<16;k2++){
    int n2 = k2*16 + i;
    out[(size_t)ti*NF + K1*256 + n2] = cmul(v[k2], TW[(n2*K1)&65535]);
  }
}

// SO inverse pass A (full-res sections only, j2<=4). s = g*16/N.
__global__ void __launch_bounds__(256) k_invA2(const __half2* __restrict__ in,
                                               __half2* __restrict__ out)
{
  __shared__ float2 sm[16*256];
  const int i = threadIdx.x & 15, f = threadIdx.x >> 4;
  const int K1 = blockIdx.x*16 + f;
  const int ti = blockIdx.y;
  const int b = ti / TS2;
  const int s0 = ti - b*TS2;
  int j2 = 1;
  #pragma unroll
  for (int q=1; q<4; q++) if (s0 >= 4*q*(q+1)) j2 = q+1;
  const int ch = s0 - 4*j2*(j2-1);
  const float xi   = 0.35f * exp2f(-(float)j2);
  const float invs = 1.0f / (0.6f * xi);
  const __half2* src = in + ((size_t)b*JQ + ch)*NF;

  float2 v[16];
  #pragma unroll
  for (int r=0;r<16;r++){
    int k = (r*16 + i)*256 + K1;
    float fn = (k < 32768) ? (float)k * INV_N : ((float)k - 65536.0f) * INV_N;
    float z = (fn - xi) * invs;
    if (fabsf(z) < ZCUT){
      float g = expf(-0.5f*z*z);
      float2 X = h2f(src[K1*256 + (r*16+i)]);
      float s = g * (16.0f*INV_N);
      v[r] = make_float2(X.x*s, X.y*s);
    } else v[r] = make_float2(0.0f, 0.0f);
  }
  fft256_swz<1>(v, i, sm + f*256);
  #pragma unroll
  for (int k2=0;k2<16;k2++){
    int n2 = k2*16 + i;
    out[(size_t)ti*NF + K1*256 + n2] = f2h(cmul(v[k2], TW[(n2*K1)&65535]));
  }
}

__global__ void __launch_bounds__(256) k_fo_b(const float2* __restrict__ T,
                                              float2* __restrict__ out,
                                              float* __restrict__ sp1)
{
  __shared__ __align__(16) char smraw[16*257*sizeof(float2)];
  float2* sm   = (float2*)smraw;
  float*  u_s  = (float*)smraw;
  float*  gf_s = (float*)smraw + 16*257;

  const int f = threadIdx.x & 15, i = threadIdx.x >> 4;
  const int tid = threadIdx.x;
  const int n2 = blockIdx.x*16 + f;
  const size_t base = (size_t)blockIdx.y * NF;
  float2 v[16];
  #pragma unroll
  for (int r=0;r<16;r++) v[r] = T[base + (r*16+i)*256 + n2];
  fft256_pad<1>(v, i, sm + f*257);
  __syncthreads();
  #pragma unroll
  for (int k2=0;k2<16;k2++)
    u_s[f*257 + k2*16 + i] = cmag(v[k2]);
  for (int t=tid; t<GTAPS; t+=256) gf_s[t] = GF[t];
  __syncthreads();
  conv_partial(u_s, gf_s, blockIdx.x, tid, sp1 + (size_t)blockIdx.y*4096);
  __syncthreads();
  #pragma unroll
  for (int r=0;r<16;r++) v[r] = make_float2(u_s[f*257 + r*16 + i], 0.0f);
  __syncthreads();
  fft256_pad<-1>(v, i, sm + f*257);
  #pragma unroll
  for (int k2=0;k2<16;k2++){
    int K1 = k2*16 + i;
    float2 w = TW[(n2*K1)&65535]; w.y = -w.y;
    out[base + K1*256 + n2] = cmul(v[k2], w);
  }
}

__global__ void __launch_bounds__(256) k_invB_abs(const __half2* __restrict__ T,
                                                  float* __restrict__ sp2)
{
  __shared__ __align__(16) char smraw[16*257*sizeof(float2)];
  float2* sm   = (float2*)smraw;
  float*  u_s  = (float*)smraw;
  float*  gf_s = (float*)smraw + 16*257;

  const int f = threadIdx.x & 15, i = threadIdx.x >> 4;
  const int tid = threadIdx.x;
  const int n2 = blockIdx.x*16 + f;
  const int ti = blockIdx.y;
  const int b = ti / TS2, s0 = ti - b*TS2;
  const size_t base = (size_t)ti * NF;
  float2 v[16];
  #pragma unroll
  for (int r=0;r<16;r++) v[r] = h2f(T[base + (r*16+i)*256 + n2]);
  fft256_pad<1>(v, i, sm + f*257);
  __syncthreads();
  #pragma unroll
  for (int k2=0;k2<16;k2++)
    u_s[f*257 + k2*16 + i] = 0.25f*cmag(v[k2]);
  for (int t=tid; t<GTAPS; t+=256) gf_s[t] = GF[t];
  __syncthreads();
  conv_partial(u_s, gf_s, blockIdx.x, tid, sp2 + (size_t)(b*NSEC + s0)*4096);
}

// Fused decimated SO, N'=4096, M=16 (j2 in {5,6,7}).
// Spectral folding with ALIAS SUMMATION: for each folded bin kp we sum all
// aliases k = kp + 4096*d inside the filter band (<= 2 for j2=5, 1 for j2>=6).
__global__ void __launch_bounds__(256) k_so4096(const __half2* __restrict__ u1f,
                                                float* __restrict__ sp2)
{
  extern __shared__ char dyn[];
  float2* sm  = (float2*)dyn;               // 16*257 f2
  float2* sA  = (float2*)dyn + 4112;        // 256*17 f2
  float*  sU  = (float*)dyn;                // 4096+128 floats (overlay sm)
  float*  g16 = (float*)dyn + 4300;         // 97 floats

  const int t = threadIdx.x;
  const int f = t & 15, i = t >> 4;
  const int s0 = TS2 + blockIdx.x;          // 80..223
  const int b  = blockIdx.y;
  const int j2 = (s0 >= 168) ? 7 : ((s0 >= 120) ? 6 : 5);
  const int ch = s0 - 4*j2*(j2-1);
  const float xi   = 0.35f * exp2f(-(float)j2);
  const float invs = 1.0f/(0.6f*xi);
  const float kcf  = xi * 65536.0f;
  const __half2* src = u1f + ((size_t)b*JQ + ch)*NF;

  // pass A: 16 x 256-pt inverse FFTs over kA (k' = kA*16 + kB, kB = f)
  float2 v[16];
  #pragma unroll
  for (int r=0;r<16;r++){
    int kp = r*256 + i*16 + f;
    int d0 = (int)floorf((kcf - (float)kp) * (1.0f/4096.0f) + 0.5f);
    float2 a = make_float2(0.0f, 0.0f);
    #pragma unroll
    for (int dd=-1; dd<=1; dd++){
      int k  = (kp + ((d0+dd) << 12)) & 65535;
      float fn = (k < 32768) ? (float)k*INV_N : ((float)k - 65536.0f)*INV_N;
      float z = (fn - xi)*invs;
      if (fabsf(z) < ZCUT){
        float g = expf(-0.5f*z*z);
        float2 X = h2f(src[(k & 255)*256 + (k >> 8)]);
        float s = g * (4.0f*INV_N);        // 4x undoes u1f's 0.25
        a.x += X.x*s; a.y += X.y*s;
      }
    }
    v[r] = a;
  }
  fft256_pad<1>(v, i, sm + f*257);
  #pragma unroll
  for (int k2=0;k2<16;k2++){
    int a = k2*16 + i;
    sA[a*17 + f] = cmul(v[k2], TW[(a*f*16)&65535]);   // e^{+2pi i a kB/4096}
  }
  __syncthreads();

  // pass B: per-thread 16-pt inverse FFT over kB; y[t + 256*bb]
  {
    float2 w[16];
    #pragma unroll
    for (int kB=0;kB<16;kB++) w[kB] = sA[t*17 + kB];
    fft16<1>(w);
    #pragma unroll
    for (int bb=0;bb<16;bb++){
      int m = t + 256*bb;
      sU[m + (m>>5)] = cmag(w[bb]);
    }
  }
  if (t < 97) g16[t] = GF[16*t];
  __syncthreads();

  // decimated lowpass: S(p=t) = 16 * sum_j GF[16j] * u'(16t + j - 48)
  float acc = 0.0f;
  for (int j=0;j<97;j++){
    int m = (16*t + j - 48) & 4095;
    acc += g16[j] * sU[m + (m>>5)];
  }
  float* o = sp2 + (size_t)(b*NSEC + s0)*4096;
  o[t] = 16.0f*acc;
  #pragma unroll
  for (int k=1;k<16;k++) o[k*256 + t] = 0.0f;
}

// ---------------- S0 conv ----------------
#define CONV_OUT 32
#define CONV_WIN ((CONV_OUT-1)*256 + GTAPS)
__global__ void __launch_bounds__(256) k_conv_x(const float* __restrict__ x,
                                                float* __restrict__ out)
{
  const int grp = blockIdx.x, b = blockIdx.y;
  const float* src = x + (size_t)b*NF;
  __shared__ float win[CONV_WIN + 3];
  __shared__ float gs[GTAPS];
  const int tid = threadIdx.x;
  const int w0 = grp*(CONV_OUT*256) - LG;
  for (int i=tid; i<CONV_WIN; i+=256) win[i] = src[(w0 + i) & 65535];
  for (int i=tid; i<GTAPS; i+=256) gs[i] = GF[i];
  __syncthreads();
  const int warp = tid >> 5, lane = tid & 31;
  #pragma unroll
  for (int oo=0; oo<CONV_OUT/8; oo++){
    const int o = warp*(CONV_OUT/8) + oo;
    const int off = o * 256;
    float acc = 0.0f;
    for (int i=lane; i<GTAPS; i+=32) acc += gs[i] * win[off + i];
    #pragma unroll
    for (int d=16; d; d>>=1) acc += __shfl_down_sync(0xffffffffu, acc, d);
    if (lane == 0){
      int n = grp*CONV_OUT + o;
      float mag = sqrtf(acc*acc + 1e-8f);
      out[(size_t)b*NCHAN*256 + n] = logf(mag + 1e-8f);
    }
  }
}

// ---------------- epilogue ----------------
__global__ void __launch_bounds__(256) k_log(const float* __restrict__ sp1,
                                             const float* __restrict__ sp2,
                                             float* __restrict__ out)
{
  const int row = blockIdx.x;
  const int b = row / 288, cm1 = row - b*288;
  const int m = threadIdx.x;
  const float* base = (cm1 < 64)
    ? sp1 + (size_t)(b*JQ   + cm1     )*4096
    : sp2 + (size_t)(b*NSEC + cm1 - 64)*4096;
  float S = 0.0f;
  #pragma unroll
  for (int k=0;k<16;k++) S += base[k*256 + m];
  float mag = sqrtf(S*S + 1e-8f);
  out[((size_t)b*NCHAN + 1 + cm1)*256 + m] = logf(mag + 1e-8f);
}

__global__ void k_zero(float* p, int n){
  int i = blockIdx.x*blockDim.x + threadIdx.x;
  if (i < n) p[i] = 0.0f;
}

// ---------------- launch ----------------
extern "C" void kernel_launch(void* const* d_in, const int* in_sizes, int n_in,
                              void* d_out, int out_size)
{
  (void)in_sizes; (void)n_in;
  const float* x = (const float*)d_in[0];
  float* out = (float*)d_out;

  float2 *xtmp, *xf, *p1a, *p1b;
  __half2 *p2, *u1f;
  float *sp1, *sp2;
  cudaGetSymbolAddress((void**)&xtmp, d_xtmp);
  cudaGetSymbolAddress((void**)&xf,   d_xf);
  cudaGetSymbolAddress((void**)&p1a,  d_p1a);
  cudaGetSymbolAddress((void**)&p1b,  d_p1b);
  cudaGetSymbolAddress((void**)&p2,   d_p2);
  cudaGetSymbolAddress((void**)&u1f,  d_u1f);
  cudaGetSymbolAddress((void**)&sp1,  d_sp1);
  cudaGetSymbolAddress((void**)&sp2,  d_sp2);

  static int smem_set = 0;
  if (!smem_set){
    cudaFuncSetAttribute(k_so4096, cudaFuncAttributeMaxDynamicSharedMemorySize, 69632);
    smem_set = 1;
  }

  k_tw<<<256, 256>>>();
  k_g <<<7,   256>>>();

  // forward FFT of x
  k_fwd_col_x<<<dim3(16,8), 256>>>(x, xtmp);
  k_fwd_row  <<<dim3(16,8), 256>>>(xtmp, xf);

  // first order
  k_invA1     <<<dim3(16,512), 256>>>(xf, p1a);
  k_fo_b      <<<dim3(16,512), 256>>>(p1a, p1b, sp1);
  k_fwd_row_u1<<<dim3(16,512), 256>>>(p1b, u1f);

  // second order, full-res sections (j2 <= 4): 80 per batch
  k_invA2   <<<dim3(16, 8*TS2), 256>>>(u1f, p2);
  k_invB_abs<<<dim3(16, 8*TS2), 256>>>(p2, sp2);

  // second order, decimated (j2 in {5,6,7}): N'=4096 with alias-summed folding
  k_so4096<<<dim3(NSEC-TS2, NB), 256, 69632>>>(u1f, sp2);

  // S0 + epilogue
  k_conv_x<<<dim3(8, NB), 256>>>(x, out);
  k_log   <<<2304, 256>>>(sp1, sp2, out);

  int half = out_size / 2;
  k_zero<<<(half + 255)/256, 256>>>(out + half, half);
}

// round 12
// speedup vs baseline: 2.0707x; 1.2847x over previous
#include <cuda_runtime.h>
#include <cuda_fp16.h>
#include <math.h>
#include <stdint.h>

#define NF 65536
#define NB 8
#define JQ 64
#define NSEC 224
#define NCHAN 289
#define LG 768
#define GTAPS 1537
#define KPHI 1024
#define INV_N (1.0f/65536.0f)
#define ZCUT 7.4395f       // e^{-0.5*z^2} ~ 1e-12
#define TS2 80             // full-res SO sections per batch (j2<=4)

// ---------------- static device storage ----------------
static __device__ float2  TW[NF];
static __device__ float   GF[GTAPS];
static __device__ float2  d_xtmp[  8u*65536u];
static __device__ float2  d_xf  [  8u*65536u];
static __device__ float2  d_p1a [ 256u*65536u];         // FO full-res only (ch<32)
static __device__ float2  d_p1b [ 256u*65536u];
static __device__ __half2 d_p2  [(size_t)640u*65536u];  // SO passA->passB (fp16, 4x true)
static __device__ __half2 d_u1f [ 512u*65536u];         // FFT(|U1|) fp16 x0.25 (ch<32 slots used)
static __device__ float2  d_u1f4[ 256u*4096u];          // decimated FFT(|U1|) fp32 (ch>=32)
static __device__ float   d_sp1 [  512u*4096u];
static __device__ float   d_sp2 [ 1792u*4096u];

static __device__ const float2 W16T[16] = {
  { 1.0f, 0.0f},
  { 0.9238795325112867f, 0.3826834323650898f},
  { 0.7071067811865476f, 0.7071067811865476f},
  { 0.3826834323650898f, 0.9238795325112867f},
  { 0.0f, 1.0f},
  {-0.3826834323650898f, 0.9238795325112867f},
  {-0.7071067811865476f, 0.7071067811865476f},
  {-0.9238795325112867f, 0.3826834323650898f},
  {-1.0f, 0.0f},
  {-0.9238795325112867f,-0.3826834323650898f},
  {-0.7071067811865476f,-0.7071067811865476f},
  {-0.3826834323650898f,-0.9238795325112867f},
  { 0.0f,-1.0f},
  { 0.3826834323650898f,-0.9238795325112867f},
  { 0.7071067811865476f,-0.7071067811865476f},
  { 0.9238795325112867f,-0.3826834323650898f}
};

// ---------------- helpers ----------------
__device__ __forceinline__ float2 cadd(float2 a, float2 b){ return make_float2(a.x+b.x, a.y+b.y); }
__device__ __forceinline__ float2 csub(float2 a, float2 b){ return make_float2(a.x-b.x, a.y-b.y); }
__device__ __forceinline__ float2 cmul(float2 a, float2 b){ return make_float2(a.x*b.x-a.y*b.y, a.x*b.y+a.y*b.x); }
__device__ __forceinline__ float2 h2f(__half2 h){ return __half22float2(h); }
__device__ __forceinline__ __half2 f2h(float2 v){ return __float22half2_rn(v); }
__device__ __forceinline__ float cmag(float2 z){
  float x2 = z.x*z.x + z.y*z.y + 1e-36f;
  return x2 * rsqrtf(x2);
}
template<int S> __device__ __forceinline__ float2 mul_i(float2 a){
  return (S>0) ? make_float2(-a.y, a.x) : make_float2(a.y, -a.x);
}
template<int S> __device__ __forceinline__ void dft4(float2&a, float2&b, float2&c, float2&d){
  float2 t0=cadd(a,c), t1=csub(a,c), t2=cadd(b,d), t3=mul_i<S>(csub(b,d));
  a=cadd(t0,t2); c=csub(t0,t2); b=cadd(t1,t3); d=csub(t1,t3);
}
template<int S> __device__ __forceinline__ float2 w16(int m){
  float2 w = W16T[m];
  if (S < 0) w.y = -w.y;
  return w;
}
template<int S> __device__ __forceinline__ void fft16(float2 v[16]){
  #pragma unroll
  for (int n0=0; n0<4; n0++) dft4<S>(v[n0], v[n0+4], v[n0+8], v[n0+12]);
  #pragma unroll
  for (int n0=1; n0<4; n0++)
    #pragma unroll
    for (int k1=1; k1<4; k1++)
      v[n0+4*k1] = cmul(v[n0+4*k1], w16<S>(n0*k1));
  float2 o[16];
  #pragma unroll
  for (int k1=0; k1<4; k1++){
    float2 a=v[4*k1+0], b=v[4*k1+1], c=v[4*k1+2], d=v[4*k1+3];
    dft4<S>(a,b,c,d);
    o[k1]=a; o[k1+4]=b; o[k1+8]=c; o[k1+12]=d;
  }
  #pragma unroll
  for (int i=0;i<16;i++) v[i]=o[i];
}

template<int S> __device__ __forceinline__ void fft256_pad(float2 v[16], int i, float2* sm){
  fft16<S>(v);
  #pragma unroll
  for (int k1=1;k1<16;k1++){
    float2 w = TW[(i*k1*256)&65535];
    if (S<0) w.y = -w.y;
    v[k1] = cmul(v[k1], w);
  }
  #pragma unroll
  for (int k1=0;k1<16;k1++) sm[k1*16+i] = v[k1];
  __syncthreads();
  #pragma unroll
  for (int n0=0;n0<16;n0++) v[n0] = sm[i*16+n0];
  fft16<S>(v);
}

template<int S> __device__ __forceinline__ void fft256_swz(float2 v[16], int i, float2* sm){
  fft16<S>(v);
  #pragma unroll
  for (int k1=1;k1<16;k1++){
    float2 w = TW[(i*k1*256)&65535];
    if (S<0) w.y = -w.y;
    v[k1] = cmul(v[k1], w);
  }
  #pragma unroll
  for (int k1=0;k1<16;k1++) sm[k1*16 + ((i+k1)&15)] = v[k1];
  __syncwarp();
  #pragma unroll
  for (int n0=0;n0<16;n0++) v[n0] = sm[i*16 + ((n0+i)&15)];
  fft16<S>(v);
}

__device__ __forceinline__ void conv_partial(const float* u_s, const float* gf_s,
                                             int bx, int m, float* sp)
{
  float acc = 0.0f;
  #pragma unroll
  for (int f2=0; f2<16; f2++){
    const int q = bx*16 + f2 + 768;
    #pragma unroll
    for (int d=-3; d<=3; d++){
      int tap = d*256 + q;
      if (tap >= 0 && tap <= 1536)
        acc += gf_s[tap] * u_s[f2*257 + ((m + d) & 255)];
    }
  }
  sp[bx*256 + m] = acc;
}

// ---------------- setup kernels ----------------
__global__ void k_tw(){
  int k = blockIdx.x*blockDim.x + threadIdx.x;
  double a = 6.283185307179586476925286766559 * (double)k / 65536.0;
  TW[k] = make_float2((float)cos(a), (float)sin(a));
}
__global__ void k_g(){
  __shared__ float ps[KPHI+1];
  const int tid = threadIdx.x;
  const float invden = 1.0f/(65536.0f*(0.35f/256.0f));
  for (int k=tid; k<=KPHI; k+=256){
    float z = (float)k * invden;
    ps[k] = 2.0f*expf(-0.5f*z*z);
  }
  __syncthreads();
  int i = blockIdx.x*256 + tid;
  if (i >= GTAPS) return;
  int tt = i - LG; if (tt < 0) tt = -tt;
  float acc = 1.0f;
  for (int k=1; k<=KPHI; k++)
    acc += ps[k] * TW[(k*tt) & 65535].x;
  GF[i] = acc * INV_N;
}

// ---------------- FFT pass kernels ----------------
__global__ void __launch_bounds__(256) k_fwd_col_x(const float* __restrict__ x,
                                                   float2* __restrict__ out)
{
  __shared__ float2 sm[16*257];
  const int f = threadIdx.x & 15, i = threadIdx.x >> 4;
  const int col = blockIdx.x*16 + f;
  const size_t base = (size_t)blockIdx.y * NF;
  float2 v[16];
  #pragma unroll
  for (int r=0;r<16;r++) v[r] = make_float2(x[base + (r*16+i)*256 + col], 0.0f);
  fft256_pad<-1>(v, i, sm + f*257);
  #pragma unroll
  for (int k2=0;k2<16;k2++){
    int K1 = k2*16 + i;
    float2 w = TW[(col*K1)&65535]; w.y = -w.y;
    out[base + K1*256 + col] = cmul(v[k2], w);
  }
}

__global__ void __launch_bounds__(256) k_fwd_row(const float2* __restrict__ in,
                                                 float2* __restrict__ out)
{
  __shared__ float2 sm[16*256];
  const int i = threadIdx.x & 15, f = threadIdx.x >> 4;
  const int row = blockIdx.x*16 + f;
  const size_t base = (size_t)blockIdx.y * NF;
  float2 v[16];
  #pragma unroll
  for (int r=0;r<16;r++) v[r] = in[base + row*256 + r*16 + i];
  fft256_swz<-1>(v, i, sm + f*256);
  #pragma unroll
  for (int k2=0;k2<16;k2++) out[base + row*256 + k2*16 + i] = v[k2];
}

// row pass: fp32 in (compact index) -> fp16 u1f at (b*JQ+ch) (x 0.25)
__global__ void __launch_bounds__(256) k_fwd_row_u1(const float2* __restrict__ in,
                                                    __half2* __restrict__ out)
{
  __shared__ float2 sm[16*256];
  const int i = threadIdx.x & 15, f = threadIdx.x >> 4;
  const int row = blockIdx.x*16 + f;
  const int ti = blockIdx.y;               // 0..255, b=ti>>5, ch=ti&31
  const size_t obase = ((size_t)(ti>>5)*JQ + (ti&31)) * NF;
  float2 v[16];
  #pragma unroll
  for (int r=0;r<16;r++) v[r] = in[(size_t)ti*NF + row*256 + r*16 + i];
  fft256_swz<-1>(v, i, sm + f*256);
  #pragma unroll
  for (int k2=0;k2<16;k2++){
    float2 o = v[k2];
    out[obase + row*256 + k2*16 + i] = f2h(make_float2(o.x*0.25f, o.y*0.25f));
  }
}

// FO inverse pass A, full-res channels ch<32 only.
__global__ void __launch_bounds__(256) k_invA1(const float2* __restrict__ in,
                                               float2* __restrict__ out)
{
  __shared__ float2 sm[16*256];
  const int i = threadIdx.x & 15, f = threadIdx.x >> 4;
  const int K1 = blockIdx.x*16 + f;
  const int ti = blockIdx.y;               // 0..255
  const int b = ti >> 5, ch = ti & 31;
  const float xi   = 0.35f * exp2f(-(float)ch * 0.125f);
  const float invs = 8.0f / xi;
  const float2* src = in + (size_t)b*NF;

  float2 v[16];
  #pragma unroll
  for (int r=0;r<16;r++){
    int k = (r*16 + i)*256 + K1;
    float fn = (k < 32768) ? (float)k * INV_N : ((float)k - 65536.0f) * INV_N;
    float z = (fn - xi) * invs;
    if (fabsf(z) < ZCUT){
      float g = expf(-0.5f*z*z);
      float2 X = src[K1*256 + (r*16+i)];
      float s = g * INV_N;
      v[r] = make_float2(X.x*s, X.y*s);
    } else v[r] = make_float2(0.0f, 0.0f);
  }
  fft256_swz<1>(v, i, sm + f*256);
  #pragma unroll
  for (int k2=0;k2<16;k2++){
    int n2 = k2*16 + i;
    out[(size_t)ti*NF + K1*256 + n2] = cmul(v[k2], TW[(n2*K1)&65535]);
  }
}

// SO inverse pass A (full-res sections only, j2<=4). s = g*16/N.
__global__ void __launch_bounds__(256) k_invA2(const __half2* __restrict__ in,
                                               __half2* __restrict__ out)
{
  __shared__ float2 sm[16*256];
  const int i = threadIdx.x & 15, f = threadIdx.x >> 4;
  const int K1 = blockIdx.x*16 + f;
  const int ti = blockIdx.y;
  const int b = ti / TS2;
  const int s0 = ti - b*TS2;
  int j2 = 1;
  #pragma unroll
  for (int q=1; q<4; q++) if (s0 >= 4*q*(q+1)) j2 = q+1;
  const int ch = s0 - 4*j2*(j2-1);
  const float xi   = 0.35f * exp2f(-(float)j2);
  const float invs = 1.0f / (0.6f * xi);
  const __half2* src = in + ((size_t)b*JQ + ch)*NF;

  float2 v[16];
  #pragma unroll
  for (int r=0;r<16;r++){
    int k = (r*16 + i)*256 + K1;
    float fn = (k < 32768) ? (float)k * INV_N : ((float)k - 65536.0f) * INV_N;
    float z = (fn - xi) * invs;
    if (fabsf(z) < ZCUT){
      float g = expf(-0.5f*z*z);
      float2 X = h2f(src[K1*256 + (r*16+i)]);
      float s = g * (16.0f*INV_N);
      v[r] = make_float2(X.x*s, X.y*s);
    } else v[r] = make_float2(0.0f, 0.0f);
  }
  fft256_swz<1>(v, i, sm + f*256);
  #pragma unroll
  for (int k2=0;k2<16;k2++){
    int n2 = k2*16 + i;
    out[(size_t)ti*NF + K1*256 + n2] = f2h(cmul(v[k2], TW[(n2*K1)&65535]));
  }
}

// FO pass B (ch<32): col IFFT -> |.| -> lowpass partial -> col FFT -> twiddle
__global__ void __launch_bounds__(256) k_fo_b(const float2* __restrict__ T,
                                              float2* __restrict__ out,
                                              float* __restrict__ sp1)
{
  __shared__ __align__(16) char smraw[16*257*sizeof(float2)];
  float2* sm   = (float2*)smraw;
  float*  u_s  = (float*)smraw;
  float*  gf_s = (float*)smraw + 16*257;

  const int f = threadIdx.x & 15, i = threadIdx.x >> 4;
  const int tid = threadIdx.x;
  const int n2 = blockIdx.x*16 + f;
  const int ti = blockIdx.y;               // 0..255
  const size_t base = (size_t)ti * NF;
  const size_t spo  = ((size_t)(ti>>5)*JQ + (ti&31)) * 4096;
  float2 v[16];
  #pragma unroll
  for (int r=0;r<16;r++) v[r] = T[base + (r*16+i)*256 + n2];
  fft256_pad<1>(v, i, sm + f*257);
  __syncthreads();
  #pragma unroll
  for (int k2=0;k2<16;k2++)
    u_s[f*257 + k2*16 + i] = cmag(v[k2]);
  for (int t=tid; t<GTAPS; t+=256) gf_s[t] = GF[t];
  __syncthreads();
  conv_partial(u_s, gf_s, blockIdx.x, tid, sp1 + spo);
  __syncthreads();
  #pragma unroll
  for (int r=0;r<16;r++) v[r] = make_float2(u_s[f*257 + r*16 + i], 0.0f);
  __syncthreads();
  fft256_pad<-1>(v, i, sm + f*257);
  #pragma unroll
  for (int k2=0;k2<16;k2++){
    int K1 = k2*16 + i;
    float2 w = TW[(n2*K1)&65535]; w.y = -w.y;
    out[base + K1*256 + n2] = cmul(v[k2], w);
  }
}

__global__ void __launch_bounds__(256) k_invB_abs(const __half2* __restrict__ T,
                                                  float* __restrict__ sp2)
{
  __shared__ __align__(16) char smraw[16*257*sizeof(float2)];
  float2* sm   = (float2*)smraw;
  float*  u_s  = (float*)smraw;
  float*  gf_s = (float*)smraw + 16*257;

  const int f = threadIdx.x & 15, i = threadIdx.x >> 4;
  const int tid = threadIdx.x;
  const int n2 = blockIdx.x*16 + f;
  const int ti = blockIdx.y;
  const int b = ti / TS2, s0 = ti - b*TS2;
  const size_t base = (size_t)ti * NF;
  float2 v[16];
  #pragma unroll
  for (int r=0;r<16;r++) v[r] = h2f(T[base + (r*16+i)*256 + n2]);
  fft256_pad<1>(v, i, sm + f*257);
  __syncthreads();
  #pragma unroll
  for (int k2=0;k2<16;k2++)
    u_s[f*257 + k2*16 + i] = 0.25f*cmag(v[k2]);
  for (int t=tid; t<GTAPS; t+=256) gf_s[t] = GF[t];
  __syncthreads();
  conv_partial(u_s, gf_s, blockIdx.x, tid, sp2 + (size_t)(b*NSEC + s0)*4096);
}

// Fused decimated FIRST ORDER for ch>=32 (one block per (b,ch)):
// fold psi1*xf to N'=4096 -> IFFT -> |.| -> decimated S1 lowpass ->
// forward FFT_4096(|U1| decimated) -> u1f4 (fp32, true scale).
__global__ void __launch_bounds__(256) k_fo4096(const float2* __restrict__ xf,
                                                float* __restrict__ sp1,
                                                float2* __restrict__ u1f4)
{
  extern __shared__ char dyn[];
  float2* sm  = (float2*)dyn;               // 16*257 f2 (transpose; overlays sU)
  float2* sA  = (float2*)dyn + 4112;        // 256*17 f2
  float*  sU  = (float*)dyn;                // 4096+128 floats
  float*  g16 = (float*)dyn + 4300;         // 97 floats

  const int t = threadIdx.x;
  const int f = t & 15, i = t >> 4;
  const int ch = 32 + blockIdx.x;
  const int b  = blockIdx.y;
  const float xi   = 0.35f * exp2f(-(float)ch * 0.125f);
  const float invs = 8.0f / xi;
  const float kcf  = xi * 65536.0f;
  const float2* src = xf + (size_t)b*NF;

  // IFFT pass A: 16 x 256-pt inverse FFTs over kA (kp = kA*16 + kB, kB=f)
  float2 v[16];
  #pragma unroll
  for (int r=0;r<16;r++){
    int kp = r*256 + i*16 + f;
    int d0 = (int)floorf((kcf - (float)kp) * (1.0f/4096.0f) + 0.5f);
    int k  = (kp + (d0 << 12)) & 65535;
    float fn = (k < 32768) ? (float)k*INV_N : ((float)k - 65536.0f)*INV_N;
    float z = (fn - xi)*invs;
    if (fabsf(z) < ZCUT){
      float g = expf(-0.5f*z*z) * INV_N;
      float2 X = src[(k & 255)*256 + (k >> 8)];
      v[r] = make_float2(X.x*g, X.y*g);
    } else v[r] = make_float2(0.0f, 0.0f);
  }
  fft256_pad<1>(v, i, sm + f*257);
  #pragma unroll
  for (int k2=0;k2<16;k2++){
    int a = k2*16 + i;
    sA[a*17 + f] = cmul(v[k2], TW[(a*f*16)&65535]);
  }
  __syncthreads();

  // IFFT pass B + modulus -> sU (sm region now dead)
  {
    float2 w[16];
    #pragma unroll
    for (int kB=0;kB<16;kB++) w[kB] = sA[t*17 + kB];
    fft16<1>(w);
    #pragma unroll
    for (int bb=0;bb<16;bb++){
      int m = t + 256*bb;
      sU[m + (m>>5)] = cmag(w[bb]);
    }
  }
  if (t < 97) g16[t] = GF[16*t];
  __syncthreads();

  // decimated S1 lowpass
  {
    float acc = 0.0f;
    for (int j=0;j<97;j++){
      int m = (16*t + j - 48) & 4095;
      acc += g16[j] * sU[m + (m>>5)];
    }
    float* o = sp1 + ((size_t)b*JQ + ch)*4096;
    o[t] = 16.0f*acc;
    #pragma unroll
    for (int k=1;k<16;k++) o[k*256 + t] = 0.0f;
  }

  // forward FFT_4096 of sU. step1: per-thread (mA=t) 16-pt fwd FFT over mB.
  float2 c[16];
  #pragma unroll
  for (int mB=0;mB<16;mB++){
    int m = t + 256*mB;
    c[mB] = make_float2(sU[m + (m>>5)], 0.0f);
  }
  fft16<-1>(c);
  #pragma unroll
  for (int q=0;q<16;q++){
    float2 w = TW[(q*t*16)&65535]; w.y = -w.y;   // e^{-2pi i q mA/4096}
    sA[t*17 + q] = cmul(c[q], w);
  }
  __syncthreads();

  // step3: 256-pt fwd FFT over mA per q=f. Output k = f + 16*(k2*16+i).
  float2 u[16];
  #pragma unroll
  for (int r=0;r<16;r++) u[r] = sA[(r*16+i)*17 + f];
  fft256_pad<-1>(u, i, sm + f*257);
  float2* dst = u1f4 + ((size_t)b*32 + (ch-32))*4096;
  #pragma unroll
  for (int k2=0;k2<16;k2++)
    dst[f + 16*(k2*16 + i)] = u[k2];
}

// Fused decimated SO, N'=4096, M=16 (j2 in {5,6,7}).
// ch<32: alias-summed fold of full-res u1f (fp16, x0.25).
// ch>=32: direct read of folded spectrum u1f4 (fp32, Uhat; true U1f ~ 16*Uhat).
__global__ void __launch_bounds__(256) k_so4096(const __half2* __restrict__ u1f,
                                                const float2* __restrict__ u1f4,
                                                float* __restrict__ sp2)
{
  extern __shared__ char dyn[];
  float2* sm  = (float2*)dyn;
  float2* sA  = (float2*)dyn + 4112;
  float*  sU  = (float*)dyn;
  float*  g16 = (float*)dyn + 4300;

  const int t = threadIdx.x;
  const int f = t & 15, i = t >> 4;
  const int s0 = TS2 + blockIdx.x;          // 80..223
  const int b  = blockIdx.y;
  const int j2 = (s0 >= 168) ? 7 : ((s0 >= 120) ? 6 : 5);
  const int ch = s0 - 4*j2*(j2-1);
  const float xi   = 0.35f * exp2f(-(float)j2);
  const float invs = 1.0f/(0.6f*xi);
  const float kcf  = xi * 65536.0f;
  const bool dec = (ch >= 32);
  const __half2* src  = u1f  + ((size_t)b*JQ + ch)*NF;
  const float2*  src4 = u1f4 + ((size_t)b*32 + (ch-32))*4096;

  float2 v[16];
  #pragma unroll
  for (int r=0;r<16;r++){
    int kp = r*256 + i*16 + f;
    int d0 = (int)floorf((kcf - (float)kp) * (1.0f/4096.0f) + 0.5f);
    if (!dec){
      float2 a = make_float2(0.0f, 0.0f);
      #pragma unroll
      for (int dd=-1; dd<=1; dd++){
        int k  = (kp + ((d0+dd) << 12)) & 65535;
        float fn = (k < 32768) ? (float)k*INV_N : ((float)k - 65536.0f)*INV_N;
        float z = (fn - xi)*invs;
        if (fabsf(z) < ZCUT){
          float g = expf(-0.5f*z*z);
          float2 X = h2f(src[(k & 255)*256 + (k >> 8)]);
          float s = g * (4.0f*INV_N);
          a.x += X.x*s; a.y += X.y*s;
        }
      }
      v[r] = a;
    } else {
      float gsum = 0.0f;
      #pragma unroll
      for (int dd=-1; dd<=1; dd++){
        int k  = (kp + ((d0+dd) << 12)) & 65535;
        float fn = (k < 32768) ? (float)k*INV_N : ((float)k - 65536.0f)*INV_N;
        float z = (fn - xi)*invs;
        if (fabsf(z) < ZCUT) gsum += expf(-0.5f*z*z);
      }
      if (gsum != 0.0f){
        float2 X = src4[kp];
        float s = gsum * (16.0f*INV_N);
        v[r] = make_float2(X.x*s, X.y*s);
      } else v[r] = make_float2(0.0f, 0.0f);
    }
  }
  fft256_pad<1>(v, i, sm + f*257);
  #pragma unroll
  for (int k2=0;k2<16;k2++){
    int a = k2*16 + i;
    sA[a*17 + f] = cmul(v[k2], TW[(a*f*16)&65535]);
  }
  __syncthreads();

  {
    float2 w[16];
    #pragma unroll
    for (int kB=0;kB<16;kB++) w[kB] = sA[t*17 + kB];
    fft16<1>(w);
    #pragma unroll
    for (int bb=0;bb<16;bb++){
      int m = t + 256*bb;
      sU[m + (m>>5)] = cmag(w[bb]);
    }
  }
  if (t < 97) g16[t] = GF[16*t];
  __syncthreads();

  float acc = 0.0f;
  for (int j=0;j<97;j++){
    int m = (16*t + j - 48) & 4095;
    acc += g16[j] * sU[m + (m>>5)];
  }
  float* o = sp2 + (size_t)(b*NSEC + s0)*4096;
  o[t] = 16.0f*acc;
  #pragma unroll
  for (int k=1;k<16;k++) o[k*256 + t] = 0.0f;
}

// ---------------- S0 conv ----------------
#define CONV_OUT 32
#define CONV_WIN ((CONV_OUT-1)*256 + GTAPS)
__global__ void __launch_bounds__(256) k_conv_x(const float* __restrict__ x,
                                                float* __restrict__ out)
{
  const int grp = blockIdx.x, b = blockIdx.y;
  const float* src = x + (size_t)b*NF;
  __shared__ float win[CONV_WIN + 3];
  __shared__ float gs[GTAPS];
  const int tid = threadIdx.x;
  const int w0 = grp*(CONV_OUT*256) - LG;
  for (int i=tid; i<CONV_WIN; i+=256) win[i] = src[(w0 + i) & 65535];
  for (int i=tid; i<GTAPS; i+=256) gs[i] = GF[i];
  __syncthreads();
  const int warp = tid >> 5, lane = tid & 31;
  #pragma unroll
  for (int oo=0; oo<CONV_OUT/8; oo++){
    const int o = warp*(CONV_OUT/8) + oo;
    const int off = o * 256;
    float acc = 0.0f;
    for (int i=lane; i<GTAPS; i+=32) acc += gs[i] * win[off + i];
    #pragma unroll
    for (int d=16; d; d>>=1) acc += __shfl_down_sync(0xffffffffu, acc, d);
    if (lane == 0){
      int n = grp*CONV_OUT + o;
      float mag = sqrtf(acc*acc + 1e-8f);
      out[(size_t)b*NCHAN*256 + n] = logf(mag + 1e-8f);
    }
  }
}

// ---------------- epilogue ----------------
__global__ void __launch_bounds__(256) k_log(const float* __restrict__ sp1,
                                             const float* __restrict__ sp2,
                                             float* __restrict__ out)
{
  const int row = blockIdx.x;
  const int b = row / 288, cm1 = row - b*288;
  const int m = threadIdx.x;
  const float* base = (cm1 < 64)
    ? sp1 + (size_t)(b*JQ   + cm1     )*4096
    : sp2 + (size_t)(b*NSEC + cm1 - 64)*4096;
  float S = 0.0f;
  #pragma unroll
  for (int k=0;k<16;k++) S += base[k*256 + m];
  float mag = sqrtf(S*S + 1e-8f);
  out[((size_t)b*NCHAN + 1 + cm1)*256 + m] = logf(mag + 1e-8f);
}

__global__ void k_zero(float* p, int n){
  int i = blockIdx.x*blockDim.x + threadIdx.x;
  if (i < n) p[i] = 0.0f;
}

// ---------------- launch ----------------
extern "C" void kernel_launch(void* const* d_in, const int* in_sizes, int n_in,
                              void* d_out, int out_size)
{
  (void)in_sizes; (void)n_in;
  const float* x = (const float*)d_in[0];
  float* out = (float*)d_out;

  float2 *xtmp, *xf, *p1a, *p1b, *u1f4;
  __half2 *p2, *u1f;
  float *sp1, *sp2;
  cudaGetSymbolAddress((void**)&xtmp, d_xtmp);
  cudaGetSymbolAddress((void**)&xf,   d_xf);
  cudaGetSymbolAddress((void**)&p1a,  d_p1a);
  cudaGetSymbolAddress((void**)&p1b,  d_p1b);
  cudaGetSymbolAddress((void**)&p2,   d_p2);
  cudaGetSymbolAddress((void**)&u1f,  d_u1f);
  cudaGetSymbolAddress((void**)&u1f4, d_u1f4);
  cudaGetSymbolAddress((void**)&sp1,  d_sp1);
  cudaGetSymbolAddress((void**)&sp2,  d_sp2);

  static int smem_set = 0;
  if (!smem_set){
    cudaFuncSetAttribute(k_so4096, cudaFuncAttributeMaxDynamicSharedMemorySize, 69632);
    cudaFuncSetAttribute(k_fo4096, cudaFuncAttributeMaxDynamicSharedMemorySize, 69632);
    smem_set = 1;
  }

  k_tw<<<256, 256>>>();
  k_g <<<7,   256>>>();

  // forward FFT of x
  k_fwd_col_x<<<dim3(16,8), 256>>>(x, xtmp);
  k_fwd_row  <<<dim3(16,8), 256>>>(xtmp, xf);

  // first order, full-res channels ch<32 (256 transforms)
  k_invA1     <<<dim3(16,256), 256>>>(xf, p1a);
  k_fo_b      <<<dim3(16,256), 256>>>(p1a, p1b, sp1);
  k_fwd_row_u1<<<dim3(16,256), 256>>>(p1b, u1f);

  // first order, decimated channels ch>=32 (fused, 256 blocks)
  k_fo4096<<<dim3(32, NB), 256, 69632>>>(xf, sp1, u1f4);

  // second order, full-res sections (j2 <= 4)
  k_invA2   <<<dim3(16, 8*TS2), 256>>>(u1f, p2);
  k_invB_abs<<<dim3(16, 8*TS2), 256>>>(p2, sp2);

  // second order, decimated (j2 in {5,6,7})
  k_so4096<<<dim3(NSEC-TS2, NB), 256, 69632>>>(u1f, u1f4, sp2);

  // S0 + epilogue
  k_conv_x<<<dim3(8, NB), 256>>>(x, out);
  k_log   <<<2304, 256>>>(sp1, sp2, out);

  int half = out_size / 2;
  k_zero<<<(half + 255)/256, 256>>>(out + half, half);
}

// round 13
// speedup vs baseline: 2.3215x; 1.1211x over previous
#include <cuda_runtime.h>
#include <cuda_fp16.h>
#include <math.h>
#include <stdint.h>

#define NF 65536
#define NB 8
#define JQ 64
#define NSEC 224
#define NCHAN 289
#define LG 768
#define GTAPS 1537
#define KPHI 1024
#define INV_N (1.0f/65536.0f)
#define ZCUT 7.4395f       // e^{-0.5*z^2} ~ 1e-12
#define TS2 48             // full-res SO sections per batch (j2<=3)
#define NS8 72             // N'=8192 sections per batch (j2 in {4,5})

// ---------------- static device storage ----------------
static __device__ float2  TW[NF];
static __device__ float   GF[GTAPS];
static __device__ float2  d_xtmp[  8u*65536u];
static __device__ float2  d_xf  [  8u*65536u];
static __device__ float2  d_p1a [ 256u*65536u];         // FO full-res; later 8192-scratch
static __device__ float2  d_p1b [ 256u*65536u];
static __device__ __half2 d_p2  [(size_t)640u*65536u];  // SO passA->passB (fp16, 4x true)
static __device__ __half2 d_u1f [ 512u*65536u];         // FFT(|U1|) fp16 x0.25 (ch<32)
static __device__ float2  d_u1f4[ 256u*4096u];          // decimated FFT(|U1|) fp32 (ch>=32)
static __device__ float   d_sp1 [  512u*4096u];
static __device__ float   d_sp2 [ 1792u*4096u];

static __device__ const float2 W16T[16] = {
  { 1.0f, 0.0f},
  { 0.9238795325112867f, 0.3826834323650898f},
  { 0.7071067811865476f, 0.7071067811865476f},
  { 0.3826834323650898f, 0.9238795325112867f},
  { 0.0f, 1.0f},
  {-0.3826834323650898f, 0.9238795325112867f},
  {-0.7071067811865476f, 0.7071067811865476f},
  {-0.9238795325112867f, 0.3826834323650898f},
  {-1.0f, 0.0f},
  {-0.9238795325112867f,-0.3826834323650898f},
  {-0.7071067811865476f,-0.7071067811865476f},
  {-0.3826834323650898f,-0.9238795325112867f},
  { 0.0f,-1.0f},
  { 0.3826834323650898f,-0.9238795325112867f},
  { 0.7071067811865476f,-0.7071067811865476f},
  { 0.9238795325112867f,-0.3826834323650898f}
};

// ---------------- helpers ----------------
__device__ __forceinline__ float2 cadd(float2 a, float2 b){ return make_float2(a.x+b.x, a.y+b.y); }
__device__ __forceinline__ float2 csub(float2 a, float2 b){ return make_float2(a.x-b.x, a.y-b.y); }
__device__ __forceinline__ float2 cmul(float2 a, float2 b){ return make_float2(a.x*b.x-a.y*b.y, a.x*b.y+a.y*b.x); }
__device__ __forceinline__ float2 h2f(__half2 h){ return __half22float2(h); }
__device__ __forceinline__ __half2 f2h(float2 v){ return __float22half2_rn(v); }
__device__ __forceinline__ float cmag(float2 z){
  float x2 = z.x*z.x + z.y*z.y + 1e-36f;
  return x2 * rsqrtf(x2);
}
template<int S> __device__ __forceinline__ float2 mul_i(float2 a){
  return (S>0) ? make_float2(-a.y, a.x) : make_float2(a.y, -a.x);
}
template<int S> __device__ __forceinline__ void dft4(float2&a, float2&b, float2&c, float2&d){
  float2 t0=cadd(a,c), t1=csub(a,c), t2=cadd(b,d), t3=mul_i<S>(csub(b,d));
  a=cadd(t0,t2); c=csub(t0,t2); b=cadd(t1,t3); d=csub(t1,t3);
}
template<int S> __device__ __forceinline__ float2 w16(int m){
  float2 w = W16T[m];
  if (S < 0) w.y = -w.y;
  return w;
}
template<int S> __device__ __forceinline__ void fft16(float2 v[16]){
  #pragma unroll
  for (int n0=0; n0<4; n0++) dft4<S>(v[n0], v[n0+4], v[n0+8], v[n0+12]);
  #pragma unroll
  for (int n0=1; n0<4; n0++)
    #pragma unroll
    for (int k1=1; k1<4; k1++)
      v[n0+4*k1] = cmul(v[n0+4*k1], w16<S>(n0*k1));
  float2 o[16];
  #pragma unroll
  for (int k1=0; k1<4; k1++){
    float2 a=v[4*k1+0], b=v[4*k1+1], c=v[4*k1+2], d=v[4*k1+3];
    dft4<S>(a,b,c,d);
    o[k1]=a; o[k1+4]=b; o[k1+8]=c; o[k1+12]=d;
  }
  #pragma unroll
  for (int i=0;i<16;i++) v[i]=o[i];
}

template<int S> __device__ __forceinline__ void fft256_pad(float2 v[16], int i, float2* sm){
  fft16<S>(v);
  #pragma unroll
  for (int k1=1;k1<16;k1++){
    float2 w = TW[(i*k1*256)&65535];
    if (S<0) w.y = -w.y;
    v[k1] = cmul(v[k1], w);
  }
  #pragma unroll
  for (int k1=0;k1<16;k1++) sm[k1*16+i] = v[k1];
  __syncthreads();
  #pragma unroll
  for (int n0=0;n0<16;n0++) v[n0] = sm[i*16+n0];
  fft16<S>(v);
}

template<int S> __device__ __forceinline__ void fft256_swz(float2 v[16], int i, float2* sm){
  fft16<S>(v);
  #pragma unroll
  for (int k1=1;k1<16;k1++){
    float2 w = TW[(i*k1*256)&65535];
    if (S<0) w.y = -w.y;
    v[k1] = cmul(v[k1], w);
  }
  #pragma unroll
  for (int k1=0;k1<16;k1++) sm[k1*16 + ((i+k1)&15)] = v[k1];
  __syncwarp();
  #pragma unroll
  for (int n0=0;n0<16;n0++) v[n0] = sm[i*16 + ((n0+i)&15)];
  fft16<S>(v);
}

__device__ __forceinline__ void conv_partial(const float* u_s, const float* gf_s,
                                             int bx, int m, float* sp)
{
  float acc = 0.0f;
  #pragma unroll
  for (int f2=0; f2<16; f2++){
    const int q = bx*16 + f2 + 768;
    #pragma unroll
    for (int d=-3; d<=3; d++){
      int tap = d*256 + q;
      if (tap >= 0 && tap <= 1536)
        acc += gf_s[tap] * u_s[f2*257 + ((m + d) & 255)];
    }
  }
  sp[bx*256 + m] = acc;
}

// ---------------- setup kernels ----------------
__global__ void k_tw(){
  int k = blockIdx.x*blockDim.x + threadIdx.x;
  double a = 6.283185307179586476925286766559 * (double)k / 65536.0;
  TW[k] = make_float2((float)cos(a), (float)sin(a));
}
__global__ void k_g(){
  __shared__ float ps[KPHI+1];
  const int tid = threadIdx.x;
  const float invden = 1.0f/(65536.0f*(0.35f/256.0f));
  for (int k=tid; k<=KPHI; k+=256){
    float z = (float)k * invden;
    ps[k] = 2.0f*expf(-0.5f*z*z);
  }
  __syncthreads();
  int i = blockIdx.x*256 + tid;
  if (i >= GTAPS) return;
  int tt = i - LG; if (tt < 0) tt = -tt;
  float acc = 1.0f;
  for (int k=1; k<=KPHI; k++)
    acc += ps[k] * TW[(k*tt) & 65535].x;
  GF[i] = acc * INV_N;
}

// ---------------- FFT pass kernels ----------------
__global__ void __launch_bounds__(256) k_fwd_col_x(const float* __restrict__ x,
                                                   float2* __restrict__ out)
{
  __shared__ float2 sm[16*257];
  const int f = threadIdx.x & 15, i = threadIdx.x >> 4;
  const int col = blockIdx.x*16 + f;
  const size_t base = (size_t)blockIdx.y * NF;
  float2 v[16];
  #pragma unroll
  for (int r=0;r<16;r++) v[r] = make_float2(x[base + (r*16+i)*256 + col], 0.0f);
  fft256_pad<-1>(v, i, sm + f*257);
  #pragma unroll
  for (int k2=0;k2<16;k2++){
    int K1 = k2*16 + i;
    float2 w = TW[(col*K1)&65535]; w.y = -w.y;
    out[base + K1*256 + col] = cmul(v[k2], w);
  }
}

__global__ void __launch_bounds__(256) k_fwd_row(const float2* __restrict__ in,
                                                 float2* __restrict__ out)
{
  __shared__ float2 sm[16*256];
  const int i = threadIdx.x & 15, f = threadIdx.x >> 4;
  const int row = blockIdx.x*16 + f;
  const size_t base = (size_t)blockIdx.y * NF;
  float2 v[16];
  #pragma unroll
  for (int r=0;r<16;r++) v[r] = in[base + row*256 + r*16 + i];
  fft256_swz<-1>(v, i, sm + f*256);
  #pragma unroll
  for (int k2=0;k2<16;k2++) out[base + row*256 + k2*16 + i] = v[k2];
}

// row pass: fp32 in (compact) -> fp16 u1f at (b*JQ+ch) (x 0.25)
__global__ void __launch_bounds__(256) k_fwd_row_u1(const float2* __restrict__ in,
                                                    __half2* __restrict__ out)
{
  __shared__ float2 sm[16*256];
  const int i = threadIdx.x & 15, f = threadIdx.x >> 4;
  const int row = blockIdx.x*16 + f;
  const int ti = blockIdx.y;               // b=ti>>5, ch=ti&31
  const size_t obase = ((size_t)(ti>>5)*JQ + (ti&31)) * NF;
  float2 v[16];
  #pragma unroll
  for (int r=0;r<16;r++) v[r] = in[(size_t)ti*NF + row*256 + r*16 + i];
  fft256_swz<-1>(v, i, sm + f*256);
  #pragma unroll
  for (int k2=0;k2<16;k2++){
    float2 o = v[k2];
    out[obase + row*256 + k2*16 + i] = f2h(make_float2(o.x*0.25f, o.y*0.25f));
  }
}

// FO inverse pass A, full-res channels ch<32.
__global__ void __launch_bounds__(256) k_invA1(const float2* __restrict__ in,
                                               float2* __restrict__ out)
{
  __shared__ float2 sm[16*256];
  const int i = threadIdx.x & 15, f = threadIdx.x >> 4;
  const int K1 = blockIdx.x*16 + f;
  const int ti = blockIdx.y;
  const int b = ti >> 5, ch = ti & 31;
  const float xi   = 0.35f * exp2f(-(float)ch * 0.125f);
  const float invs = 8.0f / xi;
  const float2* src = in + (size_t)b*NF;

  float2 v[16];
  #pragma unroll
  for (int r=0;r<16;r++){
    int k = (r*16 + i)*256 + K1;
    float fn = (k < 32768) ? (float)k * INV_N : ((float)k - 65536.0f) * INV_N;
    float z = (fn - xi) * invs;
    if (fabsf(z) < ZCUT){
      float g = expf(-0.5f*z*z);
      float2 X = src[K1*256 + (r*16+i)];
      float s = g * INV_N;
      v[r] = make_float2(X.x*s, X.y*s);
    } else v[r] = make_float2(0.0f, 0.0f);
  }
  fft256_swz<1>(v, i, sm + f*256);
  #pragma unroll
  for (int k2=0;k2<16;k2++){
    int n2 = k2*16 + i;
    out[(size_t)ti*NF + K1*256 + n2] = cmul(v[k2], TW[(n2*K1)&65535]);
  }
}

// SO inverse pass A (full-res, j2<=3). s = g*16/N.
__global__ void __launch_bounds__(256) k_invA2(const __half2* __restrict__ in,
                                               __half2* __restrict__ out)
{
  __shared__ float2 sm[16*256];
  const int i = threadIdx.x & 15, f = threadIdx.x >> 4;
  const int K1 = blockIdx.x*16 + f;
  const int ti = blockIdx.y;
  const int b = ti / TS2;
  const int s0 = ti - b*TS2;
  int j2 = 1;
  #pragma unroll
  for (int q=1; q<3; q++) if (s0 >= 4*q*(q+1)) j2 = q+1;
  const int ch = s0 - 4*j2*(j2-1);
  const float xi   = 0.35f * exp2f(-(float)j2);
  const float invs = 1.0f / (0.6f * xi);
  const __half2* src = in + ((size_t)b*JQ + ch)*NF;

  float2 v[16];
  #pragma unroll
  for (int r=0;r<16;r++){
    int k = (r*16 + i)*256 + K1;
    float fn = (k < 32768) ? (float)k * INV_N : ((float)k - 65536.0f) * INV_N;
    float z = (fn - xi) * invs;
    if (fabsf(z) < ZCUT){
      float g = expf(-0.5f*z*z);
      float2 X = h2f(src[K1*256 + (r*16+i)]);
      float s = g * (16.0f*INV_N);
      v[r] = make_float2(X.x*s, X.y*s);
    } else v[r] = make_float2(0.0f, 0.0f);
  }
  fft256_swz<1>(v, i, sm + f*256);
  #pragma unroll
  for (int k2=0;k2<16;k2++){
    int n2 = k2*16 + i;
    out[(size_t)ti*NF + K1*256 + n2] = f2h(cmul(v[k2], TW[(n2*K1)&65535]));
  }
}

// FO pass B (ch<32)
__global__ void __launch_bounds__(256) k_fo_b(const float2* __restrict__ T,
                                              float2* __restrict__ out,
                                              float* __restrict__ sp1)
{
  __shared__ __align__(16) char smraw[16*257*sizeof(float2)];
  float2* sm   = (float2*)smraw;
  float*  u_s  = (float*)smraw;
  float*  gf_s = (float*)smraw + 16*257;

  const int f = threadIdx.x & 15, i = threadIdx.x >> 4;
  const int tid = threadIdx.x;
  const int n2 = blockIdx.x*16 + f;
  const int ti = blockIdx.y;
  const size_t base = (size_t)ti * NF;
  const size_t spo  = ((size_t)(ti>>5)*JQ + (ti&31)) * 4096;
  float2 v[16];
  #pragma unroll
  for (int r=0;r<16;r++) v[r] = T[base + (r*16+i)*256 + n2];
  fft256_pad<1>(v, i, sm + f*257);
  __syncthreads();
  #pragma unroll
  for (int k2=0;k2<16;k2++)
    u_s[f*257 + k2*16 + i] = cmag(v[k2]);
  for (int t=tid; t<GTAPS; t+=256) gf_s[t] = GF[t];
  __syncthreads();
  conv_partial(u_s, gf_s, blockIdx.x, tid, sp1 + spo);
  __syncthreads();
  #pragma unroll
  for (int r=0;r<16;r++) v[r] = make_float2(u_s[f*257 + r*16 + i], 0.0f);
  __syncthreads();
  fft256_pad<-1>(v, i, sm + f*257);
  #pragma unroll
  for (int k2=0;k2<16;k2++){
    int K1 = k2*16 + i;
    float2 w = TW[(n2*K1)&65535]; w.y = -w.y;
    out[base + K1*256 + n2] = cmul(v[k2], w);
  }
}

__global__ void __launch_bounds__(256) k_invB_abs(const __half2* __restrict__ T,
                                                  float* __restrict__ sp2)
{
  __shared__ __align__(16) char smraw[16*257*sizeof(float2)];
  float2* sm   = (float2*)smraw;
  float*  u_s  = (float*)smraw;
  float*  gf_s = (float*)smraw + 16*257;

  const int f = threadIdx.x & 15, i = threadIdx.x >> 4;
  const int tid = threadIdx.x;
  const int n2 = blockIdx.x*16 + f;
  const int ti = blockIdx.y;
  const int b = ti / TS2, s0 = ti - b*TS2;
  const size_t base = (size_t)ti * NF;
  float2 v[16];
  #pragma unroll
  for (int r=0;r<16;r++) v[r] = h2f(T[base + (r*16+i)*256 + n2]);
  fft256_pad<1>(v, i, sm + f*257);
  __syncthreads();
  #pragma unroll
  for (int k2=0;k2<16;k2++)
    u_s[f*257 + k2*16 + i] = 0.25f*cmag(v[k2]);
  for (int t=tid; t<GTAPS; t+=256) gf_s[t] = GF[t];
  __syncthreads();
  conv_partial(u_s, gf_s, blockIdx.x, tid, sp2 + (size_t)(b*NSEC + s0)*4096);
}

// Fused decimated FIRST ORDER for ch>=32.
__global__ void __launch_bounds__(256) k_fo4096(const float2* __restrict__ xf,
                                                float* __restrict__ sp1,
                                                float2* __restrict__ u1f4)
{
  extern __shared__ char dyn[];
  float2* sm  = (float2*)dyn;
  float2* sA  = (float2*)dyn + 4112;
  float*  sU  = (float*)dyn;
  float*  g16 = (float*)dyn + 4300;

  const int t = threadIdx.x;
  const int f = t & 15, i = t >> 4;
  const int ch = 32 + blockIdx.x;
  const int b  = blockIdx.y;
  const float xi   = 0.35f * exp2f(-(float)ch * 0.125f);
  const float invs = 8.0f / xi;
  const float kcf  = xi * 65536.0f;
  const float2* src = xf + (size_t)b*NF;

  float2 v[16];
  #pragma unroll
  for (int r=0;r<16;r++){
    int kp = r*256 + i*16 + f;
    int d0 = (int)floorf((kcf - (float)kp) * (1.0f/4096.0f) + 0.5f);
    int k  = (kp + (d0 << 12)) & 65535;
    float fn = (k < 32768) ? (float)k*INV_N : ((float)k - 65536.0f)*INV_N;
    float z = (fn - xi)*invs;
    if (fabsf(z) < ZCUT){
      float g = expf(-0.5f*z*z) * INV_N;
      float2 X = src[(k & 255)*256 + (k >> 8)];
      v[r] = make_float2(X.x*g, X.y*g);
    } else v[r] = make_float2(0.0f, 0.0f);
  }
  fft256_pad<1>(v, i, sm + f*257);
  #pragma unroll
  for (int k2=0;k2<16;k2++){
    int a = k2*16 + i;
    sA[a*17 + f] = cmul(v[k2], TW[(a*f*16)&65535]);
  }
  __syncthreads();

  {
    float2 w[16];
    #pragma unroll
    for (int kB=0;kB<16;kB++) w[kB] = sA[t*17 + kB];
    fft16<1>(w);
    #pragma unroll
    for (int bb=0;bb<16;bb++){
      int m = t + 256*bb;
      sU[m + (m>>5)] = cmag(w[bb]);
    }
  }
  if (t < 97) g16[t] = GF[16*t];
  __syncthreads();

  {
    float acc = 0.0f;
    for (int j=0;j<97;j++){
      int m = (16*t + j - 48) & 4095;
      acc += g16[j] * sU[m + (m>>5)];
    }
    float* o = sp1 + ((size_t)b*JQ + ch)*4096;
    o[t] = 16.0f*acc;
    #pragma unroll
    for (int k=1;k<16;k++) o[k*256 + t] = 0.0f;
  }

  float2 c[16];
  #pragma unroll
  for (int mB=0;mB<16;mB++){
    int m = t + 256*mB;
    c[mB] = make_float2(sU[m + (m>>5)], 0.0f);
  }
  fft16<-1>(c);
  #pragma unroll
  for (int q=0;q<16;q++){
    float2 w = TW[(q*t*16)&65535]; w.y = -w.y;
    sA[t*17 + q] = cmul(c[q], w);
  }
  __syncthreads();

  float2 u[16];
  #pragma unroll
  for (int r=0;r<16;r++) u[r] = sA[(r*16+i)*17 + f];
  fft256_pad<-1>(u, i, sm + f*257);
  float2* dst = u1f4 + ((size_t)b*32 + (ch-32))*4096;
  #pragma unroll
  for (int k2=0;k2<16;k2++)
    dst[f + 16*(k2*16 + i)] = u[k2];
}

// Fused decimated SO, N'=4096, M=16 (j2 in {6,7}).
__global__ void __launch_bounds__(256) k_so4096(const __half2* __restrict__ u1f,
                                                const float2* __restrict__ u1f4,
                                                float* __restrict__ sp2)
{
  extern __shared__ char dyn[];
  float2* sm  = (float2*)dyn;
  float2* sA  = (float2*)dyn + 4112;
  float*  sU  = (float*)dyn;
  float*  g16 = (float*)dyn + 4300;

  const int t = threadIdx.x;
  const int f = t & 15, i = t >> 4;
  const int s0 = 120 + blockIdx.x;          // 120..223
  const int b  = blockIdx.y;
  const int j2 = (s0 >= 168) ? 7 : 6;
  const int ch = s0 - 4*j2*(j2-1);
  const float xi   = 0.35f * exp2f(-(float)j2);
  const float invs = 1.0f/(0.6f*xi);
  const float kcf  = xi * 65536.0f;
  const bool dec = (ch >= 32);
  const __half2* src  = u1f  + ((size_t)b*JQ + ch)*NF;
  const float2*  src4 = u1f4 + ((size_t)b*32 + (ch-32))*4096;

  float2 v[16];
  #pragma unroll
  for (int r=0;r<16;r++){
    int kp = r*256 + i*16 + f;
    int d0 = (int)floorf((kcf - (float)kp) * (1.0f/4096.0f) + 0.5f);
    if (!dec){
      float2 a = make_float2(0.0f, 0.0f);
      #pragma unroll
      for (int dd=-1; dd<=1; dd++){
        int k  = (kp + ((d0+dd) << 12)) & 65535;
        float fn = (k < 32768) ? (float)k*INV_N : ((float)k - 65536.0f)*INV_N;
        float z = (fn - xi)*invs;
        if (fabsf(z) < ZCUT){
          float g = expf(-0.5f*z*z);
          float2 X = h2f(src[(k & 255)*256 + (k >> 8)]);
          float s = g * (4.0f*INV_N);
          a.x += X.x*s; a.y += X.y*s;
        }
      }
      v[r] = a;
    } else {
      float gsum = 0.0f;
      #pragma unroll
      for (int dd=-1; dd<=1; dd++){
        int k  = (kp + ((d0+dd) << 12)) & 65535;
        float fn = (k < 32768) ? (float)k*INV_N : ((float)k - 65536.0f)*INV_N;
        float z = (fn - xi)*invs;
        if (fabsf(z) < ZCUT) gsum += expf(-0.5f*z*z);
      }
      if (gsum != 0.0f){
        float2 X = src4[kp];
        float s = gsum * (16.0f*INV_N);
        v[r] = make_float2(X.x*s, X.y*s);
      } else v[r] = make_float2(0.0f, 0.0f);
    }
  }
  fft256_pad<1>(v, i, sm + f*257);
  #pragma unroll
  for (int k2=0;k2<16;k2++){
    int a = k2*16 + i;
    sA[a*17 + f] = cmul(v[k2], TW[(a*f*16)&65535]);
  }
  __syncthreads();

  {
    float2 w[16];
    #pragma unroll
    for (int kB=0;kB<16;kB++) w[kB] = sA[t*17 + kB];
    fft16<1>(w);
    #pragma unroll
    for (int bb=0;bb<16;bb++){
      int m = t + 256*bb;
      sU[m + (m>>5)] = cmag(w[bb]);
    }
  }
  if (t < 97) g16[t] = GF[16*t];
  __syncthreads();

  float acc = 0.0f;
  for (int j=0;j<97;j++){
    int m = (16*t + j - 48) & 4095;
    acc += g16[j] * sU[m + (m>>5)];
  }
  float* o = sp2 + (size_t)(b*NSEC + s0)*4096;
  o[t] = 16.0f*acc;
  #pragma unroll
  for (int k=1;k<16;k++) o[k*256 + t] = 0.0f;
}

// Decimated SO at N'=8192, M=8 (j2 in {4,5}), pass A.
// grid (2, NS8, NB): blockIdx.x = kB half, y = section idx, z = batch.
// idx<32: j2=4, ch=idx (full-res u1f). idx>=32: j2=5, ch=idx-32 (ch>=32 -> u1f4).
__global__ void __launch_bounds__(256) k_so8kA(const __half2* __restrict__ u1f,
                                               const float2* __restrict__ u1f4,
                                               float2* __restrict__ scr)
{
  __shared__ float2 sm[16*257];
  const int f = threadIdx.x & 15, i = threadIdx.x >> 4;
  const int h = blockIdx.x, idx = blockIdx.y, b = blockIdx.z;
  const int j2 = (idx < 32) ? 4 : 5;
  const int ch = (idx < 32) ? idx : (idx - 32);
  const float xi   = 0.35f * exp2f(-(float)j2);
  const float invs = 1.0f/(0.6f*xi);
  const float kcf  = xi * 65536.0f;
  const bool dec = (ch >= 32);
  const __half2* src  = u1f  + ((size_t)b*JQ + ch)*NF;
  const float2*  src4 = u1f4 + ((size_t)b*32 + (ch-32))*4096;
  const int kB = h*16 + f;

  float2 v[16];
  #pragma unroll
  for (int r=0;r<16;r++){
    int kA = r*16 + i;
    int kp = kA*32 + kB;                   // [0,8192)
    int d0 = (int)floorf((kcf - (float)kp) * (1.0f/8192.0f) + 0.5f);
    if (!dec){
      float2 a = make_float2(0.0f, 0.0f);
      #pragma unroll
      for (int dd=-1; dd<=1; dd++){
        int k  = (kp + ((d0+dd) << 13)) & 65535;
        float fn = (k < 32768) ? (float)k*INV_N : ((float)k - 65536.0f)*INV_N;
        float z = (fn - xi)*invs;
        if (fabsf(z) < ZCUT){
          float g = expf(-0.5f*z*z);
          float2 X = h2f(src[(k & 255)*256 + (k >> 8)]);
          float s = g * (4.0f*INV_N);
          a.x += X.x*s; a.y += X.y*s;
        }
      }
      v[r] = a;
    } else {
      float gsum = 0.0f;
      #pragma unroll
      for (int dd=-1; dd<=1; dd++){
        int k  = (kp + ((d0+dd) << 13)) & 65535;
        float fn = (k < 32768) ? (float)k*INV_N : ((float)k - 65536.0f)*INV_N;
        float z = (fn - xi)*invs;
        if (fabsf(z) < ZCUT) gsum += expf(-0.5f*z*z);
      }
      if (gsum != 0.0f){
        float2 X = src4[kp & 4095];
        float s = gsum * (16.0f*INV_N);
        v[r] = make_float2(X.x*s, X.y*s);
      } else v[r] = make_float2(0.0f, 0.0f);
    }
  }
  fft256_pad<1>(v, i, sm + f*257);
  float2* dst = scr + ((size_t)(b*NS8 + idx))*8192;
  #pragma unroll
  for (int k2=0;k2<16;k2++){
    int a = k2*16 + i;
    dst[a*32 + kB] = cmul(v[k2], TW[(a*kB*8)&65535]);  // e^{+2pi i a kB/8192}
  }
}

// Pass B: per-thread 32-pt inverse FFT over kB -> |.| -> M=8 decimated lowpass.
__global__ void __launch_bounds__(256) k_so8kB(const float2* __restrict__ scr,
                                               float* __restrict__ sp2)
{
  __shared__ float sU[8448];                // 8192 + pad
  __shared__ float g8[193];
  const int t = threadIdx.x;
  const int idx = blockIdx.x, b = blockIdx.y;
  const float2* s = scr + ((size_t)(b*NS8 + idx))*8192 + (size_t)t*32;

  float2 E[16], O[16];
  #pragma unroll
  for (int k=0;k<16;k++){ E[k] = s[2*k]; O[k] = s[2*k+1]; }
  fft16<1>(E); fft16<1>(O);
  #pragma unroll
  for (int k=0;k<16;k++){
    float2 w = TW[k*2048];                  // e^{+2pi i k/32}
    float2 wo = cmul(w, O[k]);
    int m0 = k*256 + t;
    int m1 = (k+16)*256 + t;
    sU[m0 + (m0>>5)] = cmag(cadd(E[k], wo));
    sU[m1 + (m1>>5)] = cmag(csub(E[k], wo));
  }
  if (t < 193) g8[t] = GF[8*t];
  __syncthreads();

  float acc = 0.0f;
  for (int j=0;j<193;j++){
    int m = (32*t + j - 96) & 8191;
    acc += g8[j] * sU[m + (m>>5)];
  }
  const int s0 = TS2 + idx;                 // 48..119
  float* o = sp2 + (size_t)(b*NSEC + s0)*4096;
  o[t] = 8.0f*acc;
  #pragma unroll
  for (int k=1;k<16;k++) o[k*256 + t] = 0.0f;
}

// ---------------- S0 conv ----------------
#define CONV_OUT 32
#define CONV_WIN ((CONV_OUT-1)*256 + GTAPS)
__global__ void __launch_bounds__(256) k_conv_x(const float* __restrict__ x,
                                                float* __restrict__ out)
{
  const int grp = blockIdx.x, b = blockIdx.y;
  const float* src = x + (size_t)b*NF;
  __shared__ float win[CONV_WIN + 3];
  __shared__ float gs[GTAPS];
  const int tid = threadIdx.x;
  const int w0 = grp*(CONV_OUT*256) - LG;
  for (int i=tid; i<CONV_WIN; i+=256) win[i] = src[(w0 + i) & 65535];
  for (int i=tid; i<GTAPS; i+=256) gs[i] = GF[i];
  __syncthreads();
  const int warp = tid >> 5, lane = tid & 31;
  #pragma unroll
  for (int oo=0; oo<CONV_OUT/8; oo++){
    const int o = warp*(CONV_OUT/8) + oo;
    const int off = o * 256;
    float acc = 0.0f;
    for (int i=lane; i<GTAPS; i+=32) acc += gs[i] * win[off + i];
    #pragma unroll
    for (int d=16; d; d>>=1) acc += __shfl_down_sync(0xffffffffu, acc, d);
    if (lane == 0){
      int n = grp*CONV_OUT + o;
      float mag = sqrtf(acc*acc + 1e-8f);
      out[(size_t)b*NCHAN*256 + n] = logf(mag + 1e-8f);
    }
  }
}

// ---------------- epilogue ----------------
__global__ void __launch_bounds__(256) k_log(const float* __restrict__ sp1,
                                             const float* __restrict__ sp2,
                                             float* __restrict__ out)
{
  const int row = blockIdx.x;
  const int b = row / 288, cm1 = row - b*288;
  const int m = threadIdx.x;
  const float* base = (cm1 < 64)
    ? sp1 + (size_t)(b*JQ   + cm1     )*4096
    : sp2 + (size_t)(b*NSEC + cm1 - 64)*4096;
  float S = 0.0f;
  #pragma unroll
  for (int k=0;k<16;k++) S += base[k*256 + m];
  float mag = sqrtf(S*S + 1e-8f);
  out[((size_t)b*NCHAN + 1 + cm1)*256 + m] = logf(mag + 1e-8f);
}

__global__ void k_zero(float* p, int n){
  int i = blockIdx.x*blockDim.x + threadIdx.x;
  if (i < n) p[i] = 0.0f;
}

// ---------------- launch ----------------
extern "C" void kernel_launch(void* const* d_in, const int* in_sizes, int n_in,
                              void* d_out, int out_size)
{
  (void)in_sizes; (void)n_in;
  const float* x = (const float*)d_in[0];
  float* out = (float*)d_out;

  float2 *xtmp, *xf, *p1a, *p1b, *u1f4;
  __half2 *p2, *u1f;
  float *sp1, *sp2;
  cudaGetSymbolAddress((void**)&xtmp, d_xtmp);
  cudaGetSymbolAddress((void**)&xf,   d_xf);
  cudaGetSymbolAddress((void**)&p1a,  d_p1a);
  cudaGetSymbolAddress((void**)&p1b,  d_p1b);
  cudaGetSymbolAddress((void**)&p2,   d_p2);
  cudaGetSymbolAddress((void**)&u1f,  d_u1f);
  cudaGetSymbolAddress((void**)&u1f4, d_u1f4);
  cudaGetSymbolAddress((void**)&sp1,  d_sp1);
  cudaGetSymbolAddress((void**)&sp2,  d_sp2);
  float2* scr8 = p1a;   // p1a free after k_fo_b

  static int smem_set = 0;
  if (!smem_set){
    cudaFuncSetAttribute(k_so4096, cudaFuncAttributeMaxDynamicSharedMemorySize, 69632);
    cudaFuncSetAttribute(k_fo4096, cudaFuncAttributeMaxDynamicSharedMemorySize, 69632);
    smem_set = 1;
  }

  k_tw<<<256, 256>>>();
  k_g <<<7,   256>>>();

  // forward FFT of x
  k_fwd_col_x<<<dim3(16,8), 256>>>(x, xtmp);
  k_fwd_row  <<<dim3(16,8), 256>>>(xtmp, xf);

  // first order, full-res channels ch<32
  k_invA1     <<<dim3(16,256), 256>>>(xf, p1a);
  k_fo_b      <<<dim3(16,256), 256>>>(p1a, p1b, sp1);
  k_fwd_row_u1<<<dim3(16,256), 256>>>(p1b, u1f);

  // first order, decimated channels ch>=32
  k_fo4096<<<dim3(32, NB), 256, 69632>>>(xf, sp1, u1f4);

  // second order, full-res sections (j2 <= 3)
  k_invA2   <<<dim3(16, 8*TS2), 256>>>(u1f, p2);
  k_invB_abs<<<dim3(16, 8*TS2), 256>>>(p2, sp2);

  // second order, decimated: j2 in {4,5} at N'=8192 (two-pass via L2 scratch)
  k_so8kA<<<dim3(2, NS8, NB), 256>>>(u1f, u1f4, scr8);
  k_so8kB<<<dim3(NS8, NB),    256>>>(scr8, sp2);

  // second order, decimated: j2 in {6,7} at N'=4096 (fused)
  k_so4096<<<dim3(104, NB), 256, 69632>>>(u1f, u1f4, sp2);

  // S0 + epilogue
  k_conv_x<<<dim3(8, NB), 256>>>(x, out);
  k_log   <<<2304, 256>>>(sp1, sp2, out);

  int half = out_size / 2;
  k_zero<<<(half + 255)/256, 256>>>(out + half, half);
}

// round 14
// speedup vs baseline: 2.4395x; 1.0508x over previous
#include <cuda_runtime.h>
#include <cuda_fp16.h>
#include <math.h>
#include <stdint.h>

#define NF 65536
#define NB 8
#define JQ 64
#define NSEC 224
#define NCHAN 289
#define LG 768
#define GTAPS 1537
#define KPHI 1024
#define INV_N (1.0f/65536.0f)
#define ZCUT 7.4395f       // e^{-0.5*z^2} ~ 1e-12
#define TS2 48             // full-res SO sections per batch (j2<=3)
#define NS8 72             // N'=8192 SO sections per batch (j2 in {4,5})
#define FCH 24             // full-res FO channels (ch<24)

// ---------------- static device storage ----------------
static __device__ float2  TW[NF];
static __device__ float   GF[GTAPS];
static __device__ float2  d_xtmp[  8u*65536u];
static __device__ float2  d_xf  [  8u*65536u];
static __device__ float2  d_p1a [ 256u*65536u];         // FO full-res A->B; fo8k + so8k scratch
static __device__ float2  d_p1b [ 256u*65536u];
static __device__ __half2 d_p2  [(size_t)640u*65536u];  // SO passA->passB (fp16, 4x true)
static __device__ __half2 d_u1f [ 512u*65536u];         // FFT(|U1|) fp16 x0.25 (ch<24)
static __device__ float2  d_u1f4[ 256u*4096u];          // FFT(|U1|dec16) fp32 (ch>=32)
static __device__ float2  d_u1f8[  64u*8192u];          // FFT(|U1|dec8)  fp32 (ch in [24,32))
static __device__ float   d_sp1 [  512u*4096u];
static __device__ float   d_sp2 [ 1792u*4096u];

static __device__ const float2 W16T[16] = {
  { 1.0f, 0.0f},
  { 0.9238795325112867f, 0.3826834323650898f},
  { 0.7071067811865476f, 0.7071067811865476f},
  { 0.3826834323650898f, 0.9238795325112867f},
  { 0.0f, 1.0f},
  {-0.3826834323650898f, 0.9238795325112867f},
  {-0.7071067811865476f, 0.7071067811865476f},
  {-0.9238795325112867f, 0.3826834323650898f},
  {-1.0f, 0.0f},
  {-0.9238795325112867f,-0.3826834323650898f},
  {-0.7071067811865476f,-0.7071067811865476f},
  {-0.3826834323650898f,-0.9238795325112867f},
  { 0.0f,-1.0f},
  { 0.3826834323650898f,-0.9238795325112867f},
  { 0.7071067811865476f,-0.7071067811865476f},
  { 0.9238795325112867f,-0.3826834323650898f}
};

// ---------------- helpers ----------------
__device__ __forceinline__ float2 cadd(float2 a, float2 b){ return make_float2(a.x+b.x, a.y+b.y); }
__device__ __forceinline__ float2 csub(float2 a, float2 b){ return make_float2(a.x-b.x, a.y-b.y); }
__device__ __forceinline__ float2 cmul(float2 a, float2 b){ return make_float2(a.x*b.x-a.y*b.y, a.x*b.y+a.y*b.x); }
__device__ __forceinline__ float2 h2f(__half2 h){ return __half22float2(h); }
__device__ __forceinline__ __half2 f2h(float2 v){ return __float22half2_rn(v); }
__device__ __forceinline__ float cmag(float2 z){
  float x2 = z.x*z.x + z.y*z.y + 1e-36f;
  return x2 * rsqrtf(x2);
}
template<int S> __device__ __forceinline__ float2 mul_i(float2 a){
  return (S>0) ? make_float2(-a.y, a.x) : make_float2(a.y, -a.x);
}
template<int S> __device__ __forceinline__ void dft4(float2&a, float2&b, float2&c, float2&d){
  float2 t0=cadd(a,c), t1=csub(a,c), t2=cadd(b,d), t3=mul_i<S>(csub(b,d));
  a=cadd(t0,t2); c=csub(t0,t2); b=cadd(t1,t3); d=csub(t1,t3);
}
template<int S> __device__ __forceinline__ float2 w16(int m){
  float2 w = W16T[m];
  if (S < 0) w.y = -w.y;
  return w;
}
template<int S> __device__ __forceinline__ void fft16(float2 v[16]){
  #pragma unroll
  for (int n0=0; n0<4; n0++) dft4<S>(v[n0], v[n0+4], v[n0+8], v[n0+12]);
  #pragma unroll
  for (int n0=1; n0<4; n0++)
    #pragma unroll
    for (int k1=1; k1<4; k1++)
      v[n0+4*k1] = cmul(v[n0+4*k1], w16<S>(n0*k1));
  float2 o[16];
  #pragma unroll
  for (int k1=0; k1<4; k1++){
    float2 a=v[4*k1+0], b=v[4*k1+1], c=v[4*k1+2], d=v[4*k1+3];
    dft4<S>(a,b,c,d);
    o[k1]=a; o[k1+4]=b; o[k1+8]=c; o[k1+12]=d;
  }
  #pragma unroll
  for (int i=0;i<16;i++) v[i]=o[i];
}

template<int S> __device__ __forceinline__ void fft256_pad(float2 v[16], int i, float2* sm){
  fft16<S>(v);
  #pragma unroll
  for (int k1=1;k1<16;k1++){
    float2 w = TW[(i*k1*256)&65535];
    if (S<0) w.y = -w.y;
    v[k1] = cmul(v[k1], w);
  }
  #pragma unroll
  for (int k1=0;k1<16;k1++) sm[k1*16+i] = v[k1];
  __syncthreads();
  #pragma unroll
  for (int n0=0;n0<16;n0++) v[n0] = sm[i*16+n0];
  fft16<S>(v);
}

template<int S> __device__ __forceinline__ void fft256_swz(float2 v[16], int i, float2* sm){
  fft16<S>(v);
  #pragma unroll
  for (int k1=1;k1<16;k1++){
    float2 w = TW[(i*k1*256)&65535];
    if (S<0) w.y = -w.y;
    v[k1] = cmul(v[k1], w);
  }
  #pragma unroll
  for (int k1=0;k1<16;k1++) sm[k1*16 + ((i+k1)&15)] = v[k1];
  __syncwarp();
  #pragma unroll
  for (int n0=0;n0<16;n0++) v[n0] = sm[i*16 + ((n0+i)&15)];
  fft16<S>(v);
}

__device__ __forceinline__ void conv_partial(const float* u_s, const float* gf_s,
                                             int bx, int m, float* sp)
{
  float acc = 0.0f;
  #pragma unroll
  for (int f2=0; f2<16; f2++){
    const int q = bx*16 + f2 + 768;
    #pragma unroll
    for (int d=-3; d<=3; d++){
      int tap = d*256 + q;
      if (tap >= 0 && tap <= 1536)
        acc += gf_s[tap] * u_s[f2*257 + ((m + d) & 255)];
    }
  }
  sp[bx*256 + m] = acc;
}

// ---------------- setup kernels ----------------
__global__ void k_tw(){
  int k = blockIdx.x*blockDim.x + threadIdx.x;
  double a = 6.283185307179586476925286766559 * (double)k / 65536.0;
  TW[k] = make_float2((float)cos(a), (float)sin(a));
}
__global__ void k_g(){
  __shared__ float ps[KPHI+1];
  const int tid = threadIdx.x;
  const float invden = 1.0f/(65536.0f*(0.35f/256.0f));
  for (int k=tid; k<=KPHI; k+=256){
    float z = (float)k * invden;
    ps[k] = 2.0f*expf(-0.5f*z*z);
  }
  __syncthreads();
  int i = blockIdx.x*256 + tid;
  if (i >= GTAPS) return;
  int tt = i - LG; if (tt < 0) tt = -tt;
  float acc = 1.0f;
  for (int k=1; k<=KPHI; k++)
    acc += ps[k] * TW[(k*tt) & 65535].x;
  GF[i] = acc * INV_N;
}

// ---------------- FFT pass kernels ----------------
__global__ void __launch_bounds__(256) k_fwd_col_x(const float* __restrict__ x,
                                                   float2* __restrict__ out)
{
  __shared__ float2 sm[16*257];
  const int f = threadIdx.x & 15, i = threadIdx.x >> 4;
  const int col = blockIdx.x*16 + f;
  const size_t base = (size_t)blockIdx.y * NF;
  float2 v[16];
  #pragma unroll
  for (int r=0;r<16;r++) v[r] = make_float2(x[base + (r*16+i)*256 + col], 0.0f);
  fft256_pad<-1>(v, i, sm + f*257);
  #pragma unroll
  for (int k2=0;k2<16;k2++){
    int K1 = k2*16 + i;
    float2 w = TW[(col*K1)&65535]; w.y = -w.y;
    out[base + K1*256 + col] = cmul(v[k2], w);
  }
}

__global__ void __launch_bounds__(256) k_fwd_row(const float2* __restrict__ in,
                                                 float2* __restrict__ out)
{
  __shared__ float2 sm[16*256];
  const int i = threadIdx.x & 15, f = threadIdx.x >> 4;
  const int row = blockIdx.x*16 + f;
  const size_t base = (size_t)blockIdx.y * NF;
  float2 v[16];
  #pragma unroll
  for (int r=0;r<16;r++) v[r] = in[base + row*256 + r*16 + i];
  fft256_swz<-1>(v, i, sm + f*256);
  #pragma unroll
  for (int k2=0;k2<16;k2++) out[base + row*256 + k2*16 + i] = v[k2];
}

// row pass: fp32 in (compact, 192 transforms) -> fp16 u1f at (b*JQ+ch) (x 0.25)
__global__ void __launch_bounds__(256) k_fwd_row_u1(const float2* __restrict__ in,
                                                    __half2* __restrict__ out)
{
  __shared__ float2 sm[16*256];
  const int i = threadIdx.x & 15, f = threadIdx.x >> 4;
  const int row = blockIdx.x*16 + f;
  const int ti = blockIdx.y;               // b=ti/FCH, ch=ti%FCH
  const int b = ti / FCH, ch = ti - b*FCH;
  const size_t obase = ((size_t)b*JQ + ch) * NF;
  float2 v[16];
  #pragma unroll
  for (int r=0;r<16;r++) v[r] = in[(size_t)ti*NF + row*256 + r*16 + i];
  fft256_swz<-1>(v, i, sm + f*256);
  #pragma unroll
  for (int k2=0;k2<16;k2++){
    float2 o = v[k2];
    out[obase + row*256 + k2*16 + i] = f2h(make_float2(o.x*0.25f, o.y*0.25f));
  }
}

// FO inverse pass A, full-res channels ch<24.
__global__ void __launch_bounds__(256) k_invA1(const float2* __restrict__ in,
                                               float2* __restrict__ out)
{
  __shared__ float2 sm[16*256];
  const int i = threadIdx.x & 15, f = threadIdx.x >> 4;
  const int K1 = blockIdx.x*16 + f;
  const int ti = blockIdx.y;               // 0..191
  const int b = ti / FCH, ch = ti - b*FCH;
  const float xi   = 0.35f * exp2f(-(float)ch * 0.125f);
  const float invs = 8.0f / xi;
  const float2* src = in + (size_t)b*NF;

  float2 v[16];
  #pragma unroll
  for (int r=0;r<16;r++){
    int k = (r*16 + i)*256 + K1;
    float fn = (k < 32768) ? (float)k * INV_N : ((float)k - 65536.0f) * INV_N;
    float z = (fn - xi) * invs;
    if (fabsf(z) < ZCUT){
      float g = expf(-0.5f*z*z);
      float2 X = src[K1*256 + (r*16+i)];
      float s = g * INV_N;
      v[r] = make_float2(X.x*s, X.y*s);
    } else v[r] = make_float2(0.0f, 0.0f);
  }
  fft256_swz<1>(v, i, sm + f*256);
  #pragma unroll
  for (int k2=0;k2<16;k2++){
    int n2 = k2*16 + i;
    out[(size_t)ti*NF + K1*256 + n2] = cmul(v[k2], TW[(n2*K1)&65535]);
  }
}

// SO inverse pass A (full-res, j2<=3; all ch<24). s = g*16/N.
__global__ void __launch_bounds__(256) k_invA2(const __half2* __restrict__ in,
                                               __half2* __restrict__ out)
{
  __shared__ float2 sm[16*256];
  const int i = threadIdx.x & 15, f = threadIdx.x >> 4;
  const int K1 = blockIdx.x*16 + f;
  const int ti = blockIdx.y;
  const int b = ti / TS2;
  const int s0 = ti - b*TS2;
  int j2 = 1;
  #pragma unroll
  for (int q=1; q<3; q++) if (s0 >= 4*q*(q+1)) j2 = q+1;
  const int ch = s0 - 4*j2*(j2-1);
  const float xi   = 0.35f * exp2f(-(float)j2);
  const float invs = 1.0f / (0.6f * xi);
  const __half2* src = in + ((size_t)b*JQ + ch)*NF;

  float2 v[16];
  #pragma unroll
  for (int r=0;r<16;r++){
    int k = (r*16 + i)*256 + K1;
    float fn = (k < 32768) ? (float)k * INV_N : ((float)k - 65536.0f) * INV_N;
    float z = (fn - xi) * invs;
    if (fabsf(z) < ZCUT){
      float g = expf(-0.5f*z*z);
      float2 X = h2f(src[K1*256 + (r*16+i)]);
      float s = g * (16.0f*INV_N);
      v[r] = make_float2(X.x*s, X.y*s);
    } else v[r] = make_float2(0.0f, 0.0f);
  }
  fft256_swz<1>(v, i, sm + f*256);
  #pragma unroll
  for (int k2=0;k2<16;k2++){
    int n2 = k2*16 + i;
    out[(size_t)ti*NF + K1*256 + n2] = f2h(cmul(v[k2], TW[(n2*K1)&65535]));
  }
}

// FO pass B (ch<24)
__global__ void __launch_bounds__(256) k_fo_b(const float2* __restrict__ T,
                                              float2* __restrict__ out,
                                              float* __restrict__ sp1)
{
  __shared__ __align__(16) char smraw[16*257*sizeof(float2)];
  float2* sm   = (float2*)smraw;
  float*  u_s  = (float*)smraw;
  float*  gf_s = (float*)smraw + 16*257;

  const int f = threadIdx.x & 15, i = threadIdx.x >> 4;
  const int tid = threadIdx.x;
  const int n2 = blockIdx.x*16 + f;
  const int ti = blockIdx.y;
  const int b = ti / FCH, ch = ti - b*FCH;
  const size_t base = (size_t)ti * NF;
  const size_t spo  = ((size_t)b*JQ + ch) * 4096;
  float2 v[16];
  #pragma unroll
  for (int r=0;r<16;r++) v[r] = T[base + (r*16+i)*256 + n2];
  fft256_pad<1>(v, i, sm + f*257);
  __syncthreads();
  #pragma unroll
  for (int k2=0;k2<16;k2++)
    u_s[f*257 + k2*16 + i] = cmag(v[k2]);
  for (int t=tid; t<GTAPS; t+=256) gf_s[t] = GF[t];
  __syncthreads();
  conv_partial(u_s, gf_s, blockIdx.x, tid, sp1 + spo);
  __syncthreads();
  #pragma unroll
  for (int r=0;r<16;r++) v[r] = make_float2(u_s[f*257 + r*16 + i], 0.0f);
  __syncthreads();
  fft256_pad<-1>(v, i, sm + f*257);
  #pragma unroll
  for (int k2=0;k2<16;k2++){
    int K1 = k2*16 + i;
    float2 w = TW[(n2*K1)&65535]; w.y = -w.y;
    out[base + K1*256 + n2] = cmul(v[k2], w);
  }
}

__global__ void __launch_bounds__(256) k_invB_abs(const __half2* __restrict__ T,
                                                  float* __restrict__ sp2)
{
  __shared__ __align__(16) char smraw[16*257*sizeof(float2)];
  float2* sm   = (float2*)smraw;
  float*  u_s  = (float*)smraw;
  float*  gf_s = (float*)smraw + 16*257;

  const int f = threadIdx.x & 15, i = threadIdx.x >> 4;
  const int tid = threadIdx.x;
  const int n2 = blockIdx.x*16 + f;
  const int ti = blockIdx.y;
  const int b = ti / TS2, s0 = ti - b*TS2;
  const size_t base = (size_t)ti * NF;
  float2 v[16];
  #pragma unroll
  for (int r=0;r<16;r++) v[r] = h2f(T[base + (r*16+i)*256 + n2]);
  fft256_pad<1>(v, i, sm + f*257);
  __syncthreads();
  #pragma unroll
  for (int k2=0;k2<16;k2++)
    u_s[f*257 + k2*16 + i] = 0.25f*cmag(v[k2]);
  for (int t=tid; t<GTAPS; t+=256) gf_s[t] = GF[t];
  __syncthreads();
  conv_partial(u_s, gf_s, blockIdx.x, tid, sp2 + (size_t)(b*NSEC + s0)*4096);
}

// Fused decimated FIRST ORDER for ch>=32 (N'=4096). Writes S1 slot0 + u1f4.
__global__ void __launch_bounds__(256) k_fo4096(const float2* __restrict__ xf,
                                                float* __restrict__ sp1,
                                                float2* __restrict__ u1f4)
{
  extern __shared__ char dyn[];
  float2* sm  = (float2*)dyn;
  float2* sA  = (float2*)dyn + 4112;
  float*  sU  = (float*)dyn;
  float*  g16 = (float*)dyn + 4300;

  const int t = threadIdx.x;
  const int f = t & 15, i = t >> 4;
  const int ch = 32 + blockIdx.x;
  const int b  = blockIdx.y;
  const float xi   = 0.35f * exp2f(-(float)ch * 0.125f);
  const float invs = 8.0f / xi;
  const float kcf  = xi * 65536.0f;
  const float2* src = xf + (size_t)b*NF;

  float2 v[16];
  #pragma unroll
  for (int r=0;r<16;r++){
    int kp = r*256 + i*16 + f;
    int d0 = (int)floorf((kcf - (float)kp) * (1.0f/4096.0f) + 0.5f);
    int k  = (kp + (d0 << 12)) & 65535;
    float fn = (k < 32768) ? (float)k*INV_N : ((float)k - 65536.0f)*INV_N;
    float z = (fn - xi)*invs;
    if (fabsf(z) < ZCUT){
      float g = expf(-0.5f*z*z) * INV_N;
      float2 X = src[(k & 255)*256 + (k >> 8)];
      v[r] = make_float2(X.x*g, X.y*g);
    } else v[r] = make_float2(0.0f, 0.0f);
  }
  fft256_pad<1>(v, i, sm + f*257);
  #pragma unroll
  for (int k2=0;k2<16;k2++){
    int a = k2*16 + i;
    sA[a*17 + f] = cmul(v[k2], TW[(a*f*16)&65535]);
  }
  __syncthreads();

  {
    float2 w[16];
    #pragma unroll
    for (int kB=0;kB<16;kB++) w[kB] = sA[t*17 + kB];
    fft16<1>(w);
    #pragma unroll
    for (int bb=0;bb<16;bb++){
      int m = t + 256*bb;
      sU[m + (m>>5)] = cmag(w[bb]);
    }
  }
  if (t < 97) g16[t] = GF[16*t];
  __syncthreads();

  {
    float acc = 0.0f;
    for (int j=0;j<97;j++){
      int m = (16*t + j - 48) & 4095;
      acc += g16[j] * sU[m + (m>>5)];
    }
    sp1[((size_t)b*JQ + ch)*4096 + t] = 16.0f*acc;
  }

  float2 c[16];
  #pragma unroll
  for (int mB=0;mB<16;mB++){
    int m = t + 256*mB;
    c[mB] = make_float2(sU[m + (m>>5)], 0.0f);
  }
  fft16<-1>(c);
  #pragma unroll
  for (int q=0;q<16;q++){
    float2 w = TW[(q*t*16)&65535]; w.y = -w.y;
    sA[t*17 + q] = cmul(c[q], w);
  }
  __syncthreads();

  float2 u[16];
  #pragma unroll
  for (int r=0;r<16;r++) u[r] = sA[(r*16+i)*17 + f];
  fft256_pad<-1>(u, i, sm + f*257);
  float2* dst = u1f4 + ((size_t)b*32 + (ch-32))*4096;
  #pragma unroll
  for (int k2=0;k2<16;k2++)
    dst[f + 16*(k2*16 + i)] = u[k2];
}

// Decimated FO for ch in [24,32), N'=8192, pass A: fold psi1*xf, 256-IFFT over kA.
__global__ void __launch_bounds__(256) k_fo8kA(const float2* __restrict__ xf,
                                               float2* __restrict__ scrA)
{
  __shared__ float2 sm[16*257];
  const int f = threadIdx.x & 15, i = threadIdx.x >> 4;
  const int h = blockIdx.x, idx8 = blockIdx.y, b = blockIdx.z;
  const int ch = 24 + idx8;
  const float xi   = 0.35f * exp2f(-(float)ch * 0.125f);
  const float invs = 8.0f / xi;
  const float kcf  = xi * 65536.0f;
  const float2* src = xf + (size_t)b*NF;
  const int kB = h*16 + f;

  float2 v[16];
  #pragma unroll
  for (int r=0;r<16;r++){
    int kA = r*16 + i;
    int kp = kA*32 + kB;
    int d0 = (int)floorf((kcf - (float)kp) * (1.0f/8192.0f) + 0.5f);
    int k  = (kp + (d0 << 13)) & 65535;
    float fn = (k < 32768) ? (float)k*INV_N : ((float)k - 65536.0f)*INV_N;
    float z = (fn - xi)*invs;
    if (fabsf(z) < ZCUT){
      float g = expf(-0.5f*z*z) * INV_N;
      float2 X = src[(k & 255)*256 + (k >> 8)];
      v[r] = make_float2(X.x*g, X.y*g);
    } else v[r] = make_float2(0.0f, 0.0f);
  }
  fft256_pad<1>(v, i, sm + f*257);
  float2* dst = scrA + ((size_t)(b*8 + idx8))*8192;
  #pragma unroll
  for (int k2=0;k2<16;k2++){
    int a = k2*16 + i;
    dst[a*32 + kB] = cmul(v[k2], TW[(a*kB*8)&65535]);
  }
}

// FO 8192 pass B+C1: radix-32 IFFT -> |.| -> M=8 S1 lowpass -> fwd radix-32 over mB.
__global__ void __launch_bounds__(256) k_fo8kBC(const float2* __restrict__ scrA,
                                                float* __restrict__ sp1,
                                                float2* __restrict__ scrW)
{
  __shared__ float sU[8448];
  __shared__ float g8[193];
  const int t = threadIdx.x;
  const int idx8 = blockIdx.x, b = blockIdx.y;
  const float2* s = scrA + ((size_t)(b*8 + idx8))*8192 + (size_t)t*32;

  {
    float2 E[16], O[16];
    #pragma unroll
    for (int k=0;k<16;k++){ E[k] = s[2*k]; O[k] = s[2*k+1]; }
    fft16<1>(E); fft16<1>(O);
    #pragma unroll
    for (int k=0;k<16;k++){
      float2 w = TW[k*2048];
      float2 wo = cmul(w, O[k]);
      int m0 = k*256 + t;
      int m1 = (k+16)*256 + t;
      sU[m0 + (m0>>5)] = cmag(cadd(E[k], wo));
      sU[m1 + (m1>>5)] = cmag(csub(E[k], wo));
    }
  }
  if (t < 193) g8[t] = GF[8*t];
  __syncthreads();

  {
    float acc = 0.0f;
    for (int j=0;j<193;j++){
      int m = (32*t + j - 96) & 8191;
      acc += g8[j] * sU[m + (m>>5)];
    }
    sp1[((size_t)b*JQ + 24 + idx8)*4096 + t] = 8.0f*acc;
  }

  // C1: forward radix-32 over mB (values sU[mB*256 + t]), then inter-pass twiddle.
  {
    float2 E[16], O[16];
    #pragma unroll
    for (int k=0;k<16;k++){
      int me = (2*k)*256 + t, mo = (2*k+1)*256 + t;
      E[k] = make_float2(sU[me + (me>>5)], 0.0f);
      O[k] = make_float2(sU[mo + (mo>>5)], 0.0f);
    }
    fft16<-1>(E); fft16<-1>(O);
    float2* dst = scrW + ((size_t)(b*8 + idx8))*8192;
    #pragma unroll
    for (int k=0;k<16;k++){
      float2 w = TW[k*2048]; w.y = -w.y;
      float2 wo = cmul(w, O[k]);
      float2 X0 = cadd(E[k], wo);           // kB = k
      float2 X1 = csub(E[k], wo);           // kB = k+16
      float2 w0 = TW[(t*k*8)&65535];        w0.y = -w0.y;
      float2 w1 = TW[(t*(k+16)*8)&65535];   w1.y = -w1.y;
      dst[k*256 + t]      = cmul(X0, w0);
      dst[(k+16)*256 + t] = cmul(X1, w1);
    }
  }
}

// FO 8192 pass C2: 256-pt fwd FFT over mA per kB row -> u1f8[kA*32 + kB].
__global__ void __launch_bounds__(256) k_fo8kC2(const float2* __restrict__ scrW,
                                                float2* __restrict__ u1f8)
{
  __shared__ float2 sm[16*256];
  const int i = threadIdx.x & 15, f = threadIdx.x >> 4;
  const int h = blockIdx.x, idx8 = blockIdx.y, b = blockIdx.z;
  const int kB = h*16 + f;
  const size_t base = (size_t)(b*8 + idx8)*8192;
  float2 v[16];
  #pragma unroll
  for (int r=0;r<16;r++) v[r] = scrW[base + kB*256 + r*16 + i];
  fft256_swz<-1>(v, i, sm + f*256);
  float2* dst = u1f8 + base;
  #pragma unroll
  for (int k2=0;k2<16;k2++)
    dst[(k2*16 + i)*32 + kB] = v[k2];
}

// Fused decimated SO, N'=4096, M=16 (j2 in {6,7}). 3-way source.
__global__ void __launch_bounds__(256) k_so4096(const __half2* __restrict__ u1f,
                                                const float2* __restrict__ u1f4,
                                                const float2* __restrict__ u1f8,
                                                float* __restrict__ sp2)
{
  extern __shared__ char dyn[];
  float2* sm  = (float2*)dyn;
  float2* sA  = (float2*)dyn + 4112;
  float*  sU  = (float*)dyn;
  float*  g16 = (float*)dyn + 4300;

  const int t = threadIdx.x;
  const int f = t & 15, i = t >> 4;
  const int s0 = 120 + blockIdx.x;          // 120..223
  const int b  = blockIdx.y;
  const int j2 = (s0 >= 168) ? 7 : 6;
  const int ch = s0 - 4*j2*(j2-1);
  const float xi   = 0.35f * exp2f(-(float)j2);
  const float invs = 1.0f/(0.6f*xi);
  const float kcf  = xi * 65536.0f;
  const __half2* src  = u1f  + ((size_t)b*JQ + ch)*NF;
  const float2*  src4 = u1f4 + ((size_t)b*32 + (ch-32))*4096;
  const float2*  src8 = u1f8 + ((size_t)(b*8 + (ch-24)))*8192;

  float2 v[16];
  #pragma unroll
  for (int r=0;r<16;r++){
    int kp = r*256 + i*16 + f;
    int d0 = (int)floorf((kcf - (float)kp) * (1.0f/4096.0f) + 0.5f);
    if (ch < 24){
      float2 a = make_float2(0.0f, 0.0f);
      #pragma unroll
      for (int dd=-1; dd<=1; dd++){
        int k  = (kp + ((d0+dd) << 12)) & 65535;
        float fn = (k < 32768) ? (float)k*INV_N : ((float)k - 65536.0f)*INV_N;
        float z = (fn - xi)*invs;
        if (fabsf(z) < ZCUT){
          float g = expf(-0.5f*z*z);
          float2 X = h2f(src[(k & 255)*256 + (k >> 8)]);
          float s = g * (4.0f*INV_N);
          a.x += X.x*s; a.y += X.y*s;
        }
      }
      v[r] = a;
    } else if (ch < 32){
      float2 a = make_float2(0.0f, 0.0f);
      #pragma unroll
      for (int dd=-1; dd<=1; dd++){
        int k  = (kp + ((d0+dd) << 12)) & 65535;
        float fn = (k < 32768) ? (float)k*INV_N : ((float)k - 65536.0f)*INV_N;
        float z = (fn - xi)*invs;
        if (fabsf(z) < ZCUT){
          float g = expf(-0.5f*z*z);
          float2 X = src8[k & 8191];
          float s = g * (8.0f*INV_N);
          a.x += X.x*s; a.y += X.y*s;
        }
      }
      v[r] = a;
    } else {
      float gsum = 0.0f;
      #pragma unroll
      for (int dd=-1; dd<=1; dd++){
        int k  = (kp + ((d0+dd) << 12)) & 65535;
        float fn = (k < 32768) ? (float)k*INV_N : ((float)k - 65536.0f)*INV_N;
        float z = (fn - xi)*invs;
        if (fabsf(z) < ZCUT) gsum += expf(-0.5f*z*z);
      }
      if (gsum != 0.0f){
        float2 X = src4[kp];
        float s = gsum * (16.0f*INV_N);
        v[r] = make_float2(X.x*s, X.y*s);
      } else v[r] = make_float2(0.0f, 0.0f);
    }
  }
  fft256_pad<1>(v, i, sm + f*257);
  #pragma unroll
  for (int k2=0;k2<16;k2++){
    int a = k2*16 + i;
    sA[a*17 + f] = cmul(v[k2], TW[(a*f*16)&65535]);
  }
  __syncthreads();

  {
    float2 w[16];
    #pragma unroll
    for (int kB=0;kB<16;kB++) w[kB] = sA[t*17 + kB];
    fft16<1>(w);
    #pragma unroll
    for (int bb=0;bb<16;bb++){
      int m = t + 256*bb;
      sU[m + (m>>5)] = cmag(w[bb]);
    }
  }
  if (t < 97) g16[t] = GF[16*t];
  __syncthreads();

  float acc = 0.0f;
  for (int j=0;j<97;j++){
    int m = (16*t + j - 48) & 4095;
    acc += g16[j] * sU[m + (m>>5)];
  }
  sp2[(size_t)(b*NSEC + s0)*4096 + t] = 16.0f*acc;
}

// Decimated SO at N'=8192, M=8 (j2 in {4,5}), pass A. 3-way source.
__global__ void __launch_bounds__(256) k_so8kA(const __half2* __restrict__ u1f,
                                               const float2* __restrict__ u1f4,
                                               const float2* __restrict__ u1f8,
                                               float2* __restrict__ scr)
{
  __shared__ float2 sm[16*257];
  const int f = threadIdx.x & 15, i = threadIdx.x >> 4;
  const int h = blockIdx.x, idx = blockIdx.y, b = blockIdx.z;
  const int j2 = (idx < 32) ? 4 : 5;
  const int ch = (idx < 32) ? idx : (idx - 32);
  const float xi   = 0.35f * exp2f(-(float)j2);
  const float invs = 1.0f/(0.6f*xi);
  const float kcf  = xi * 65536.0f;
  const __half2* src  = u1f  + ((size_t)b*JQ + ch)*NF;
  const float2*  src4 = u1f4 + ((size_t)b*32 + (ch-32))*4096;
  const float2*  src8 = u1f8 + ((size_t)(b*8 + (ch-24)))*8192;
  const int kB = h*16 + f;

  float2 v[16];
  #pragma unroll
  for (int r=0;r<16;r++){
    int kA = r*16 + i;
    int kp = kA*32 + kB;
    int d0 = (int)floorf((kcf - (float)kp) * (1.0f/8192.0f) + 0.5f);
    if (ch < 24){
      float2 a = make_float2(0.0f, 0.0f);
      #pragma unroll
      for (int dd=-1; dd<=1; dd++){
        int k  = (kp + ((d0+dd) << 13)) & 65535;
        float fn = (k < 32768) ? (float)k*INV_N : ((float)k - 65536.0f)*INV_N;
        float z = (fn - xi)*invs;
        if (fabsf(z) < ZCUT){
          float g = expf(-0.5f*z*z);
          float2 X = h2f(src[(k & 255)*256 + (k >> 8)]);
          float s = g * (4.0f*INV_N);
          a.x += X.x*s; a.y += X.y*s;
        }
      }
      v[r] = a;
    } else {
      float gsum = 0.0f;
      #pragma unroll
      for (int dd=-1; dd<=1; dd++){
        int k  = (kp + ((d0+dd) << 13)) & 65535;
        float fn = (k < 32768) ? (float)k*INV_N : ((float)k - 65536.0f)*INV_N;
        float z = (fn - xi)*invs;
        if (fabsf(z) < ZCUT) gsum += expf(-0.5f*z*z);
      }
      if (gsum != 0.0f){
        if (ch < 32){
          float2 X = src8[kp];
          float s = gsum * (8.0f*INV_N);
          v[r] = make_float2(X.x*s, X.y*s);
        } else {
          float2 X = src4[kp & 4095];
          float s = gsum * (16.0f*INV_N);
          v[r] = make_float2(X.x*s, X.y*s);
        }
      } else v[r] = make_float2(0.0f, 0.0f);
    }
  }
  fft256_pad<1>(v, i, sm + f*257);
  float2* dst = scr + ((size_t)(b*NS8 + idx))*8192;
  #pragma unroll
  for (int k2=0;k2<16;k2++){
    int a = k2*16 + i;
    dst[a*32 + kB] = cmul(v[k2], TW[(a*kB*8)&65535]);
  }
}

// Pass B: per-thread 32-pt inverse FFT over kB -> |.| -> M=8 decimated lowpass.
__global__ void __launch_bounds__(256) k_so8kB(const float2* __restrict__ scr,
                                               float* __restrict__ sp2)
{
  __shared__ float sU[8448];
  __shared__ float g8[193];
  const int t = threadIdx.x;
  const int idx = blockIdx.x, b = blockIdx.y;
  const float2* s = scr + ((size_t)(b*NS8 + idx))*8192 + (size_t)t*32;

  float2 E[16], O[16];
  #pragma unroll
  for (int k=0;k<16;k++){ E[k] = s[2*k]; O[k] = s[2*k+1]; }
  fft16<1>(E); fft16<1>(O);
  #pragma unroll
  for (int k=0;k<16;k++){
    float2 w = TW[k*2048];
    float2 wo = cmul(w, O[k]);
    int m0 = k*256 + t;
    int m1 = (k+16)*256 + t;
    sU[m0 + (m0>>5)] = cmag(cadd(E[k], wo));
    sU[m1 + (m1>>5)] = cmag(csub(E[k], wo));
  }
  if (t < 193) g8[t] = GF[8*t];
  __syncthreads();

  float acc = 0.0f;
  for (int j=0;j<193;j++){
    int m = (32*t + j - 96) & 8191;
    acc += g8[j] * sU[m + (m>>5)];
  }
  const int s0 = TS2 + idx;
  sp2[(size_t)(b*NSEC + s0)*4096 + t] = 8.0f*acc;
}

// ---------------- S0 conv ----------------
#define CONV_OUT 32
#define CONV_WIN ((CONV_OUT-1)*256 + GTAPS)
__global__ void __launch_bounds__(256) k_conv_x(const float* __restrict__ x,
                                                float* __restrict__ out)
{
  const int grp = blockIdx.x, b = blockIdx.y;
  const float* src = x + (size_t)b*NF;
  __shared__ float win[CONV_WIN + 3];
  __shared__ float gs[GTAPS];
  const int tid = threadIdx.x;
  const int w0 = grp*(CONV_OUT*256) - LG;
  for (int i=tid; i<CONV_WIN; i+=256) win[i] = src[(w0 + i) & 65535];
  for (int i=tid; i<GTAPS; i+=256) gs[i] = GF[i];
  __syncthreads();
  const int warp = tid >> 5, lane = tid & 31;
  #pragma unroll
  for (int oo=0; oo<CONV_OUT/8; oo++){
    const int o = warp*(CONV_OUT/8) + oo;
    const int off = o * 256;
    float acc = 0.0f;
    for (int i=lane; i<GTAPS; i+=32) acc += gs[i] * win[off + i];
    #pragma unroll
    for (int d=16; d; d>>=1) acc += __shfl_down_sync(0xffffffffu, acc, d);
    if (lane == 0){
      int n = grp*CONV_OUT + o;
      float mag = sqrtf(acc*acc + 1e-8f);
      out[(size_t)b*NCHAN*256 + n] = logf(mag + 1e-8f);
    }
  }
}

// ---------------- epilogue (slot-aware) ----------------
__global__ void __launch_bounds__(256) k_log(const float* __restrict__ sp1,
                                             const float* __restrict__ sp2,
                                             float* __restrict__ out)
{
  const int row = blockIdx.x;
  const int b = row / 288, cm1 = row - b*288;
  const int m = threadIdx.x;
  const float* base;
  bool full;
  if (cm1 < 64){
    base = sp1 + (size_t)(b*JQ + cm1)*4096;
    full = (cm1 < FCH);
  } else {
    int s0 = cm1 - 64;
    base = sp2 + (size_t)(b*NSEC + s0)*4096;
    full = (s0 < TS2);
  }
  float S = base[m];
  if (full){
    #pragma unroll
    for (int k=1;k<16;k++) S += base[k*256 + m];
  }
  float mag = sqrtf(S*S + 1e-8f);
  out[((size_t)b*NCHAN + 1 + cm1)*256 + m] = logf(mag + 1e-8f);
}

__global__ void k_zero(float* p, int n){
  int i = blockIdx.x*blockDim.x + threadIdx.x;
  if (i < n) p[i] = 0.0f;
}

// ---------------- launch ----------------
extern "C" void kernel_launch(void* const* d_in, const int* in_sizes, int n_in,
                              void* d_out, int out_size)
{
  (void)in_sizes; (void)n_in;
  const float* x = (const float*)d_in[0];
  float* out = (float*)d_out;

  float2 *xtmp, *xf, *p1a, *p1b, *u1f4, *u1f8;
  __half2 *p2, *u1f;
  float *sp1, *sp2;
  cudaGetSymbolAddress((void**)&xtmp, d_xtmp);
  cudaGetSymbolAddress((void**)&xf,   d_xf);
  cudaGetSymbolAddress((void**)&p1a,  d_p1a);
  cudaGetSymbolAddress((void**)&p1b,  d_p1b);
  cudaGetSymbolAddress((void**)&p2,   d_p2);
  cudaGetSymbolAddress((void**)&u1f,  d_u1f);
  cudaGetSymbolAddress((void**)&u1f4, d_u1f4);
  cudaGetSymbolAddress((void**)&u1f8, d_u1f8);
  cudaGetSymbolAddress((void**)&sp1,  d_sp1);
  cudaGetSymbolAddress((void**)&sp2,  d_sp2);
  float2* scrA = p1a;                       // fo8k pass-A scratch (free after k_fo_b)
  float2* scrW = p1a + (size_t)64*8192;     // fo8k C1 scratch
  float2* scr8 = p1a;                       // so8k scratch (after fo8k done)

  static int smem_set = 0;
  if (!smem_set){
    cudaFuncSetAttribute(k_so4096, cudaFuncAttributeMaxDynamicSharedMemorySize, 69632);
    cudaFuncSetAttribute(k_fo4096, cudaFuncAttributeMaxDynamicSharedMemorySize, 69632);
    smem_set = 1;
  }

  k_tw<<<256, 256>>>();
  k_g <<<7,   256>>>();

  // forward FFT of x
  k_fwd_col_x<<<dim3(16,8), 256>>>(x, xtmp);
  k_fwd_row  <<<dim3(16,8), 256>>>(xtmp, xf);

  // first order, full-res channels ch<24 (192 transforms)
  k_invA1     <<<dim3(16,192), 256>>>(xf, p1a);
  k_fo_b      <<<dim3(16,192), 256>>>(p1a, p1b, sp1);
  k_fwd_row_u1<<<dim3(16,192), 256>>>(p1b, u1f);

  // first order, decimated: ch in [24,32) at N'=8192
  k_fo8kA <<<dim3(2, 8, NB), 256>>>(xf, scrA);
  k_fo8kBC<<<dim3(8, NB),    256>>>(scrA, sp1, scrW);
  k_fo8kC2<<<dim3(2, 8, NB), 256>>>(scrW, u1f8);

  // first order, decimated: ch>=32 at N'=4096 (fused)
  k_fo4096<<<dim3(32, NB), 256, 69632>>>(xf, sp1, u1f4);

  // second order, full-res sections (j2 <= 3, ch<24)
  k_invA2   <<<dim3(16, 8*TS2), 256>>>(u1f, p2);
  k_invB_abs<<<dim3(16, 8*TS2), 256>>>(p2, sp2);

  // second order, decimated: j2 in {4,5} at N'=8192
  k_so8kA<<<dim3(2, NS8, NB), 256>>>(u1f, u1f4, u1f8, scr8);
  k_so8kB<<<dim3(NS8, NB),    256>>>(scr8, sp2);

  // second order, decimated: j2 in {6,7} at N'=4096 (fused)
  k_so4096<<<dim3(104, NB), 256, 69632>>>(u1f, u1f4, u1f8, sp2);

  // S0 + epilogue
  k_conv_x<<<dim3(8, NB), 256>>>(x, out);
  k_log   <<<2304, 256>>>(sp1, sp2, out);

  int half = out_size / 2;
  k_zero<<<(half + 255)/256, 256>>>(out + half, half);
}

// round 15
// speedup vs baseline: 2.4947x; 1.0226x over previous
#include <cuda_runtime.h>
#include <cuda_fp16.h>
#include <math.h>
#include <stdint.h>

#define NF 65536
#define NB 8
#define JQ 64
#define NSEC 224
#define NCHAN 289
#define LG 768
#define GTAPS 1537
#define KPHI 1024
#define INV_N (1.0f/65536.0f)
#define ZCUT 7.4395f       // e^{-0.5*z^2} ~ 1e-12
#define TS2 24             // full-res SO sections per batch (j2<=2)
#define NS8 96             // N'=8192 SO sections per batch (j2 in {3,4,5})
#define FCH 24             // full-res FO channels (ch<24)

// ---------------- static device storage ----------------
static __device__ float2  TW[NF];
static __device__ float   GF[GTAPS];
static __device__ float2  d_xtmp[  8u*65536u];
static __device__ float2  d_xf  [  8u*65536u];
static __device__ float2  d_p1a [ 256u*65536u];         // FO A->B; fo8k/so8k scratch
static __device__ float2  d_p1b [ 256u*65536u];
static __device__ __half2 d_p2  [(size_t)320u*65536u];  // SO passA->passB (fp16, 4x true)
static __device__ __half2 d_u1f [ 512u*65536u];         // FFT(|U1|) fp16 x0.25 (ch<24)
static __device__ float2  d_u1f4[ 256u*4096u];          // FFT(|U1|dec16) fp32 (ch>=32)
static __device__ float2  d_u1f8[  64u*8192u];          // FFT(|U1|dec8)  fp32 (ch in [24,32))
static __device__ float   d_sp1 [  512u*4096u];
static __device__ float   d_sp2 [ 1792u*4096u];

static __device__ const float2 W16T[16] = {
  { 1.0f, 0.0f},
  { 0.9238795325112867f, 0.3826834323650898f},
  { 0.7071067811865476f, 0.7071067811865476f},
  { 0.3826834323650898f, 0.9238795325112867f},
  { 0.0f, 1.0f},
  {-0.3826834323650898f, 0.9238795325112867f},
  {-0.7071067811865476f, 0.7071067811865476f},
  {-0.9238795325112867f, 0.3826834323650898f},
  {-1.0f, 0.0f},
  {-0.9238795325112867f,-0.3826834323650898f},
  {-0.7071067811865476f,-0.7071067811865476f},
  {-0.3826834323650898f,-0.9238795325112867f},
  { 0.0f,-1.0f},
  { 0.3826834323650898f,-0.9238795325112867f},
  { 0.7071067811865476f,-0.7071067811865476f},
  { 0.9238795325112867f,-0.3826834323650898f}
};

// ---------------- helpers ----------------
__device__ __forceinline__ float2 cadd(float2 a, float2 b){ return make_float2(a.x+b.x, a.y+b.y); }
__device__ __forceinline__ float2 csub(float2 a, float2 b){ return make_float2(a.x-b.x, a.y-b.y); }
__device__ __forceinline__ float2 cmul(float2 a, float2 b){ return make_float2(a.x*b.x-a.y*b.y, a.x*b.y+a.y*b.x); }
__device__ __forceinline__ float2 h2f(__half2 h){ return __half22float2(h); }
__device__ __forceinline__ __half2 f2h(float2 v){ return __float22half2_rn(v); }
__device__ __forceinline__ float cmag(float2 z){
  float x2 = z.x*z.x + z.y*z.y + 1e-36f;
  return x2 * rsqrtf(x2);
}
template<int S> __device__ __forceinline__ float2 mul_i(float2 a){
  return (S>0) ? make_float2(-a.y, a.x) : make_float2(a.y, -a.x);
}
template<int S> __device__ __forceinline__ void dft4(float2&a, float2&b, float2&c, float2&d){
  float2 t0=cadd(a,c), t1=csub(a,c), t2=cadd(b,d), t3=mul_i<S>(csub(b,d));
  a=cadd(t0,t2); c=csub(t0,t2); b=cadd(t1,t3); d=csub(t1,t3);
}
template<int S> __device__ __forceinline__ float2 w16(int m){
  float2 w = W16T[m];
  if (S < 0) w.y = -w.y;
  return w;
}
template<int S> __device__ __forceinline__ void fft16(float2 v[16]){
  #pragma unroll
  for (int n0=0; n0<4; n0++) dft4<S>(v[n0], v[n0+4], v[n0+8], v[n0+12]);
  #pragma unroll
  for (int n0=1; n0<4; n0++)
    #pragma unroll
    for (int k1=1; k1<4; k1++)
      v[n0+4*k1] = cmul(v[n0+4*k1], w16<S>(n0*k1));
  float2 o[16];
  #pragma unroll
  for (int k1=0; k1<4; k1++){
    float2 a=v[4*k1+0], b=v[4*k1+1], c=v[4*k1+2], d=v[4*k1+3];
    dft4<S>(a,b,c,d);
    o[k1]=a; o[k1+4]=b; o[k1+8]=c; o[k1+12]=d;
  }
  #pragma unroll
  for (int i=0;i<16;i++) v[i]=o[i];
}

template<int S> __device__ __forceinline__ void fft256_pad(float2 v[16], int i, float2* sm){
  fft16<S>(v);
  #pragma unroll
  for (int k1=1;k1<16;k1++){
    float2 w = TW[(i*k1*256)&65535];
    if (S<0) w.y = -w.y;
    v[k1] = cmul(v[k1], w);
  }
  #pragma unroll
  for (int k1=0;k1<16;k1++) sm[k1*16+i] = v[k1];
  __syncthreads();
  #pragma unroll
  for (int n0=0;n0<16;n0++) v[n0] = sm[i*16+n0];
  fft16<S>(v);
}

template<int S> __device__ __forceinline__ void fft256_swz(float2 v[16], int i, float2* sm){
  fft16<S>(v);
  #pragma unroll
  for (int k1=1;k1<16;k1++){
    float2 w = TW[(i*k1*256)&65535];
    if (S<0) w.y = -w.y;
    v[k1] = cmul(v[k1], w);
  }
  #pragma unroll
  for (int k1=0;k1<16;k1++) sm[k1*16 + ((i+k1)&15)] = v[k1];
  __syncwarp();
  #pragma unroll
  for (int n0=0;n0<16;n0++) v[n0] = sm[i*16 + ((n0+i)&15)];
  fft16<S>(v);
}

__device__ __forceinline__ void conv_partial(const float* u_s, const float* gf_s,
                                             int bx, int m, float* sp)
{
  float acc = 0.0f;
  #pragma unroll
  for (int f2=0; f2<16; f2++){
    const int q = bx*16 + f2 + 768;
    #pragma unroll
    for (int d=-3; d<=3; d++){
      int tap = d*256 + q;
      if (tap >= 0 && tap <= 1536)
        acc += gf_s[tap] * u_s[f2*257 + ((m + d) & 255)];
    }
  }
  sp[bx*256 + m] = acc;
}

// ---------------- setup kernels ----------------
__global__ void k_tw(){
  int k = blockIdx.x*blockDim.x + threadIdx.x;
  double a = 6.283185307179586476925286766559 * (double)k / 65536.0;
  TW[k] = make_float2((float)cos(a), (float)sin(a));
}
__global__ void k_g(){
  __shared__ float ps[KPHI+1];
  const int tid = threadIdx.x;
  const float invden = 1.0f/(65536.0f*(0.35f/256.0f));
  for (int k=tid; k<=KPHI; k+=256){
    float z = (float)k * invden;
    ps[k] = 2.0f*expf(-0.5f*z*z);
  }
  __syncthreads();
  int i = blockIdx.x*256 + tid;
  if (i >= GTAPS) return;
  int tt = i - LG; if (tt < 0) tt = -tt;
  float acc = 1.0f;
  for (int k=1; k<=KPHI; k++)
    acc += ps[k] * TW[(k*tt) & 65535].x;
  GF[i] = acc * INV_N;
}

// ---------------- FFT pass kernels ----------------
__global__ void __launch_bounds__(256) k_fwd_col_x(const float* __restrict__ x,
                                                   float2* __restrict__ out)
{
  __shared__ float2 sm[16*257];
  const int f = threadIdx.x & 15, i = threadIdx.x >> 4;
  const int col = blockIdx.x*16 + f;
  const size_t base = (size_t)blockIdx.y * NF;
  float2 v[16];
  #pragma unroll
  for (int r=0;r<16;r++) v[r] = make_float2(x[base + (r*16+i)*256 + col], 0.0f);
  fft256_pad<-1>(v, i, sm + f*257);
  #pragma unroll
  for (int k2=0;k2<16;k2++){
    int K1 = k2*16 + i;
    float2 w = TW[(col*K1)&65535]; w.y = -w.y;
    out[base + K1*256 + col] = cmul(v[k2], w);
  }
}

__global__ void __launch_bounds__(256) k_fwd_row(const float2* __restrict__ in,
                                                 float2* __restrict__ out)
{
  __shared__ float2 sm[16*256];
  const int i = threadIdx.x & 15, f = threadIdx.x >> 4;
  const int row = blockIdx.x*16 + f;
  const size_t base = (size_t)blockIdx.y * NF;
  float2 v[16];
  #pragma unroll
  for (int r=0;r<16;r++) v[r] = in[base + row*256 + r*16 + i];
  fft256_swz<-1>(v, i, sm + f*256);
  #pragma unroll
  for (int k2=0;k2<16;k2++) out[base + row*256 + k2*16 + i] = v[k2];
}

__global__ void __launch_bounds__(256) k_fwd_row_u1(const float2* __restrict__ in,
                                                    __half2* __restrict__ out)
{
  __shared__ float2 sm[16*256];
  const int i = threadIdx.x & 15, f = threadIdx.x >> 4;
  const int row = blockIdx.x*16 + f;
  const int ti = blockIdx.y;
  const int b = ti / FCH, ch = ti - b*FCH;
  const size_t obase = ((size_t)b*JQ + ch) * NF;
  float2 v[16];
  #pragma unroll
  for (int r=0;r<16;r++) v[r] = in[(size_t)ti*NF + row*256 + r*16 + i];
  fft256_swz<-1>(v, i, sm + f*256);
  #pragma unroll
  for (int k2=0;k2<16;k2++){
    float2 o = v[k2];
    out[obase + row*256 + k2*16 + i] = f2h(make_float2(o.x*0.25f, o.y*0.25f));
  }
}

__global__ void __launch_bounds__(256) k_invA1(const float2* __restrict__ in,
                                               float2* __restrict__ out)
{
  __shared__ float2 sm[16*256];
  const int i = threadIdx.x & 15, f = threadIdx.x >> 4;
  const int K1 = blockIdx.x*16 + f;
  const int ti = blockIdx.y;
  const int b = ti / FCH, ch = ti - b*FCH;
  const float xi   = 0.35f * exp2f(-(float)ch * 0.125f);
  const float invs = 8.0f / xi;
  const float2* src = in + (size_t)b*NF;

  float2 v[16];
  #pragma unroll
  for (int r=0;r<16;r++){
    int k = (r*16 + i)*256 + K1;
    float fn = (k < 32768) ? (float)k * INV_N : ((float)k - 65536.0f) * INV_N;
    float z = (fn - xi) * invs;
    if (fabsf(z) < ZCUT){
      float g = expf(-0.5f*z*z);
      float2 X = src[K1*256 + (r*16+i)];
      float s = g * INV_N;
      v[r] = make_float2(X.x*s, X.y*s);
    } else v[r] = make_float2(0.0f, 0.0f);
  }
  fft256_swz<1>(v, i, sm + f*256);
  #pragma unroll
  for (int k2=0;k2<16;k2++){
    int n2 = k2*16 + i;
    out[(size_t)ti*NF + K1*256 + n2] = cmul(v[k2], TW[(n2*K1)&65535]);
  }
}

// SO inverse pass A (full-res, j2<=2; ch<16). s = g*16/N.
__global__ void __launch_bounds__(256) k_invA2(const __half2* __restrict__ in,
                                               __half2* __restrict__ out)
{
  __shared__ float2 sm[16*256];
  const int i = threadIdx.x & 15, f = threadIdx.x >> 4;
  const int K1 = blockIdx.x*16 + f;
  const int ti = blockIdx.y;
  const int b = ti / TS2;
  const int s0 = ti - b*TS2;
  const int j2 = (s0 >= 8) ? 2 : 1;
  const int ch = s0 - 4*j2*(j2-1);
  const float xi   = 0.35f * exp2f(-(float)j2);
  const float invs = 1.0f / (0.6f * xi);
  const __half2* src = in + ((size_t)b*JQ + ch)*NF;

  float2 v[16];
  #pragma unroll
  for (int r=0;r<16;r++){
    int k = (r*16 + i)*256 + K1;
    float fn = (k < 32768) ? (float)k * INV_N : ((float)k - 65536.0f) * INV_N;
    float z = (fn - xi) * invs;
    if (fabsf(z) < ZCUT){
      float g = expf(-0.5f*z*z);
      float2 X = h2f(src[K1*256 + (r*16+i)]);
      float s = g * (16.0f*INV_N);
      v[r] = make_float2(X.x*s, X.y*s);
    } else v[r] = make_float2(0.0f, 0.0f);
  }
  fft256_swz<1>(v, i, sm + f*256);
  #pragma unroll
  for (int k2=0;k2<16;k2++){
    int n2 = k2*16 + i;
    out[(size_t)ti*NF + K1*256 + n2] = f2h(cmul(v[k2], TW[(n2*K1)&65535]));
  }
}

__global__ void __launch_bounds__(256) k_fo_b(const float2* __restrict__ T,
                                              float2* __restrict__ out,
                                              float* __restrict__ sp1)
{
  __shared__ __align__(16) char smraw[16*257*sizeof(float2)];
  float2* sm   = (float2*)smraw;
  float*  u_s  = (float*)smraw;
  float*  gf_s = (float*)smraw + 16*257;

  const int f = threadIdx.x & 15, i = threadIdx.x >> 4;
  const int tid = threadIdx.x;
  const int n2 = blockIdx.x*16 + f;
  const int ti = blockIdx.y;
  const int b = ti / FCH, ch = ti - b*FCH;
  const size_t base = (size_t)ti * NF;
  const size_t spo  = ((size_t)b*JQ + ch) * 4096;
  float2 v[16];
  #pragma unroll
  for (int r=0;r<16;r++) v[r] = T[base + (r*16+i)*256 + n2];
  fft256_pad<1>(v, i, sm + f*257);
  __syncthreads();
  #pragma unroll
  for (int k2=0;k2<16;k2++)
    u_s[f*257 + k2*16 + i] = cmag(v[k2]);
  for (int t=tid; t<GTAPS; t+=256) gf_s[t] = GF[t];
  __syncthreads();
  conv_partial(u_s, gf_s, blockIdx.x, tid, sp1 + spo);
  __syncthreads();
  #pragma unroll
  for (int r=0;r<16;r++) v[r] = make_float2(u_s[f*257 + r*16 + i], 0.0f);
  __syncthreads();
  fft256_pad<-1>(v, i, sm + f*257);
  #pragma unroll
  for (int k2=0;k2<16;k2++){
    int K1 = k2*16 + i;
    float2 w = TW[(n2*K1)&65535]; w.y = -w.y;
    out[base + K1*256 + n2] = cmul(v[k2], w);
  }
}

__global__ void __launch_bounds__(256) k_invB_abs(const __half2* __restrict__ T,
                                                  float* __restrict__ sp2)
{
  __shared__ __align__(16) char smraw[16*257*sizeof(float2)];
  float2* sm   = (float2*)smraw;
  float*  u_s  = (float*)smraw;
  float*  gf_s = (float*)smraw + 16*257;

  const int f = threadIdx.x & 15, i = threadIdx.x >> 4;
  const int tid = threadIdx.x;
  const int n2 = blockIdx.x*16 + f;
  const int ti = blockIdx.y;
  const int b = ti / TS2, s0 = ti - b*TS2;
  const size_t base = (size_t)ti * NF;
  float2 v[16];
  #pragma unroll
  for (int r=0;r<16;r++) v[r] = h2f(T[base + (r*16+i)*256 + n2]);
  fft256_pad<1>(v, i, sm + f*257);
  __syncthreads();
  #pragma unroll
  for (int k2=0;k2<16;k2++)
    u_s[f*257 + k2*16 + i] = 0.25f*cmag(v[k2]);
  for (int t=tid; t<GTAPS; t+=256) gf_s[t] = GF[t];
  __syncthreads();
  conv_partial(u_s, gf_s, blockIdx.x, tid, sp2 + (size_t)(b*NSEC + s0)*4096);
}

// Fused decimated FIRST ORDER for ch>=32 (N'=4096).
__global__ void __launch_bounds__(256) k_fo4096(const float2* __restrict__ xf,
                                                float* __restrict__ sp1,
                                                float2* __restrict__ u1f4)
{
  extern __shared__ char dyn[];
  float2* sm  = (float2*)dyn;
  float2* sA  = (float2*)dyn + 4112;
  float*  sU  = (float*)dyn;
  float*  g16 = (float*)dyn + 4300;

  const int t = threadIdx.x;
  const int f = t & 15, i = t >> 4;
  const int ch = 32 + blockIdx.x;
  const int b  = blockIdx.y;
  const float xi   = 0.35f * exp2f(-(float)ch * 0.125f);
  const float invs = 8.0f / xi;
  const float kcf  = xi * 65536.0f;
  const float2* src = xf + (size_t)b*NF;

  float2 v[16];
  #pragma unroll
  for (int r=0;r<16;r++){
    int kp = r*256 + i*16 + f;
    int d0 = (int)floorf((kcf - (float)kp) * (1.0f/4096.0f) + 0.5f);
    int k  = (kp + (d0 << 12)) & 65535;
    float fn = (k < 32768) ? (float)k*INV_N : ((float)k - 65536.0f)*INV_N;
    float z = (fn - xi)*invs;
    if (fabsf(z) < ZCUT){
      float g = expf(-0.5f*z*z) * INV_N;
      float2 X = src[(k & 255)*256 + (k >> 8)];
      v[r] = make_float2(X.x*g, X.y*g);
    } else v[r] = make_float2(0.0f, 0.0f);
  }
  fft256_pad<1>(v, i, sm + f*257);
  #pragma unroll
  for (int k2=0;k2<16;k2++){
    int a = k2*16 + i;
    sA[a*17 + f] = cmul(v[k2], TW[(a*f*16)&65535]);
  }
  __syncthreads();

  {
    float2 w[16];
    #pragma unroll
    for (int kB=0;kB<16;kB++) w[kB] = sA[t*17 + kB];
    fft16<1>(w);
    #pragma unroll
    for (int bb=0;bb<16;bb++){
      int m = t + 256*bb;
      sU[m + (m>>5)] = cmag(w[bb]);
    }
  }
  if (t < 97) g16[t] = GF[16*t];
  __syncthreads();

  {
    float acc = 0.0f;
    for (int j=0;j<97;j++){
      int m = (16*t + j - 48) & 4095;
      acc += g16[j] * sU[m + (m>>5)];
    }
    sp1[((size_t)b*JQ + ch)*4096 + t] = 16.0f*acc;
  }

  float2 c[16];
  #pragma unroll
  for (int mB=0;mB<16;mB++){
    int m = t + 256*mB;
    c[mB] = make_float2(sU[m + (m>>5)], 0.0f);
  }
  fft16<-1>(c);
  #pragma unroll
  for (int q=0;q<16;q++){
    float2 w = TW[(q*t*16)&65535]; w.y = -w.y;
    sA[t*17 + q] = cmul(c[q], w);
  }
  __syncthreads();

  float2 u[16];
  #pragma unroll
  for (int r=0;r<16;r++) u[r] = sA[(r*16+i)*17 + f];
  fft256_pad<-1>(u, i, sm + f*257);
  float2* dst = u1f4 + ((size_t)b*32 + (ch-32))*4096;
  #pragma unroll
  for (int k2=0;k2<16;k2++)
    dst[f + 16*(k2*16 + i)] = u[k2];
}

// Decimated FO for ch in [24,32), N'=8192, pass A.
__global__ void __launch_bounds__(256) k_fo8kA(const float2* __restrict__ xf,
                                               float2* __restrict__ scrA)
{
  __shared__ float2 sm[16*257];
  const int f = threadIdx.x & 15, i = threadIdx.x >> 4;
  const int h = blockIdx.x, idx8 = blockIdx.y, b = blockIdx.z;
  const int ch = 24 + idx8;
  const float xi   = 0.35f * exp2f(-(float)ch * 0.125f);
  const float invs = 8.0f / xi;
  const float kcf  = xi * 65536.0f;
  const float2* src = xf + (size_t)b*NF;
  const int kB = h*16 + f;

  float2 v[16];
  #pragma unroll
  for (int r=0;r<16;r++){
    int kA = r*16 + i;
    int kp = kA*32 + kB;
    int d0 = (int)floorf((kcf - (float)kp) * (1.0f/8192.0f) + 0.5f);
    int k  = (kp + (d0 << 13)) & 65535;
    float fn = (k < 32768) ? (float)k*INV_N : ((float)k - 65536.0f)*INV_N;
    float z = (fn - xi)*invs;
    if (fabsf(z) < ZCUT){
      float g = expf(-0.5f*z*z) * INV_N;
      float2 X = src[(k & 255)*256 + (k >> 8)];
      v[r] = make_float2(X.x*g, X.y*g);
    } else v[r] = make_float2(0.0f, 0.0f);
  }
  fft256_pad<1>(v, i, sm + f*257);
  float2* dst = scrA + ((size_t)(b*8 + idx8))*8192;
  #pragma unroll
  for (int k2=0;k2<16;k2++){
    int a = k2*16 + i;
    dst[a*32 + kB] = cmul(v[k2], TW[(a*kB*8)&65535]);
  }
}

__global__ void __launch_bounds__(256) k_fo8kBC(const float2* __restrict__ scrA,
                                                float* __restrict__ sp1,
                                                float2* __restrict__ scrW)
{
  __shared__ float sU[8448];
  __shared__ float g8[193];
  const int t = threadIdx.x;
  const int idx8 = blockIdx.x, b = blockIdx.y;
  const float2* s = scrA + ((size_t)(b*8 + idx8))*8192 + (size_t)t*32;

  {
    float2 E[16], O[16];
    #pragma unroll
    for (int k=0;k<16;k++){ E[k] = s[2*k]; O[k] = s[2*k+1]; }
    fft16<1>(E); fft16<1>(O);
    #pragma unroll
    for (int k=0;k<16;k++){
      float2 w = TW[k*2048];
      float2 wo = cmul(w, O[k]);
      int m0 = k*256 + t;
      int m1 = (k+16)*256 + t;
      sU[m0 + (m0>>5)] = cmag(cadd(E[k], wo));
      sU[m1 + (m1>>5)] = cmag(csub(E[k], wo));
    }
  }
  if (t < 193) g8[t] = GF[8*t];
  __syncthreads();

  {
    float acc = 0.0f;
    for (int j=0;j<193;j++){
      int m = (32*t + j - 96) & 8191;
      acc += g8[j] * sU[m + (m>>5)];
    }
    sp1[((size_t)b*JQ + 24 + idx8)*4096 + t] = 8.0f*acc;
  }

  {
    float2 E[16], O[16];
    #pragma unroll
    for (int k=0;k<16;k++){
      int me = (2*k)*256 + t, mo = (2*k+1)*256 + t;
      E[k] = make_float2(sU[me + (me>>5)], 0.0f);
      O[k] = make_float2(sU[mo + (mo>>5)], 0.0f);
    }
    fft16<-1>(E); fft16<-1>(O);
    float2* dst = scrW + ((size_t)(b*8 + idx8))*8192;
    #pragma unroll
    for (int k=0;k<16;k++){
      float2 w = TW[k*2048]; w.y = -w.y;
      float2 wo = cmul(w, O[k]);
      float2 X0 = cadd(E[k], wo);
      float2 X1 = csub(E[k], wo);
      float2 w0 = TW[(t*k*8)&65535];        w0.y = -w0.y;
      float2 w1 = TW[(t*(k+16)*8)&65535];   w1.y = -w1.y;
      dst[k*256 + t]      = cmul(X0, w0);
      dst[(k+16)*256 + t] = cmul(X1, w1);
    }
  }
}

__global__ void __launch_bounds__(256) k_fo8kC2(const float2* __restrict__ scrW,
                                                float2* __restrict__ u1f8)
{
  __shared__ float2 sm[16*256];
  const int i = threadIdx.x & 15, f = threadIdx.x >> 4;
  const int h = blockIdx.x, idx8 = blockIdx.y, b = blockIdx.z;
  const int kB = h*16 + f;
  const size_t base = (size_t)(b*8 + idx8)*8192;
  float2 v[16];
  #pragma unroll
  for (int r=0;r<16;r++) v[r] = scrW[base + kB*256 + r*16 + i];
  fft256_swz<-1>(v, i, sm + f*256);
  float2* dst = u1f8 + base;
  #pragma unroll
  for (int k2=0;k2<16;k2++)
    dst[(k2*16 + i)*32 + kB] = v[k2];
}

// Fused decimated SO, N'=4096, M=16 (j2 in {6,7}). 3-way source.
__global__ void __launch_bounds__(256) k_so4096(const __half2* __restrict__ u1f,
                                                const float2* __restrict__ u1f4,
                                                const float2* __restrict__ u1f8,
                                                float* __restrict__ sp2)
{
  extern __shared__ char dyn[];
  float2* sm  = (float2*)dyn;
  float2* sA  = (float2*)dyn + 4112;
  float*  sU  = (float*)dyn;
  float*  g16 = (float*)dyn + 4300;

  const int t = threadIdx.x;
  const int f = t & 15, i = t >> 4;
  const int s0 = 120 + blockIdx.x;
  const int b  = blockIdx.y;
  const int j2 = (s0 >= 168) ? 7 : 6;
  const int ch = s0 - 4*j2*(j2-1);
  const float xi   = 0.35f * exp2f(-(float)j2);
  const float invs = 1.0f/(0.6f*xi);
  const float kcf  = xi * 65536.0f;
  const __half2* src  = u1f  + ((size_t)b*JQ + ch)*NF;
  const float2*  src4 = u1f4 + ((size_t)b*32 + (ch-32))*4096;
  const float2*  src8 = u1f8 + ((size_t)(b*8 + (ch-24)))*8192;

  float2 v[16];
  #pragma unroll
  for (int r=0;r<16;r++){
    int kp = r*256 + i*16 + f;
    int d0 = (int)floorf((kcf - (float)kp) * (1.0f/4096.0f) + 0.5f);
    if (ch < 24){
      float2 a = make_float2(0.0f, 0.0f);
      #pragma unroll
      for (int dd=-1; dd<=1; dd++){
        int k  = (kp + ((d0+dd) << 12)) & 65535;
        float fn = (k < 32768) ? (float)k*INV_N : ((float)k - 65536.0f)*INV_N;
        float z = (fn - xi)*invs;
        if (fabsf(z) < ZCUT){
          float g = expf(-0.5f*z*z);
          float2 X = h2f(src[(k & 255)*256 + (k >> 8)]);
          float s = g * (4.0f*INV_N);
          a.x += X.x*s; a.y += X.y*s;
        }
      }
      v[r] = a;
    } else if (ch < 32){
      float2 a = make_float2(0.0f, 0.0f);
      #pragma unroll
      for (int dd=-1; dd<=1; dd++){
        int k  = (kp + ((d0+dd) << 12)) & 65535;
        float fn = (k < 32768) ? (float)k*INV_N : ((float)k - 65536.0f)*INV_N;
        float z = (fn - xi)*invs;
        if (fabsf(z) < ZCUT){
          float g = expf(-0.5f*z*z);
          float2 X = src8[k & 8191];
          float s = g * (8.0f*INV_N);
          a.x += X.x*s; a.y += X.y*s;
        }
      }
      v[r] = a;
    } else {
      float gsum = 0.0f;
      #pragma unroll
      for (int dd=-1; dd<=1; dd++){
        int k  = (kp + ((d0+dd) << 12)) & 65535;
        float fn = (k < 32768) ? (float)k*INV_N : ((float)k - 65536.0f)*INV_N;
        float z = (fn - xi)*invs;
        if (fabsf(z) < ZCUT) gsum += expf(-0.5f*z*z);
      }
      if (gsum != 0.0f){
        float2 X = src4[kp];
        float s = gsum * (16.0f*INV_N);
        v[r] = make_float2(X.x*s, X.y*s);
      } else v[r] = make_float2(0.0f, 0.0f);
    }
  }
  fft256_pad<1>(v, i, sm + f*257);
  #pragma unroll
  for (int k2=0;k2<16;k2++){
    int a = k2*16 + i;
    sA[a*17 + f] = cmul(v[k2], TW[(a*f*16)&65535]);
  }
  __syncthreads();

  {
    float2 w[16];
    #pragma unroll
    for (int kB=0;kB<16;kB++) w[kB] = sA[t*17 + kB];
    fft16<1>(w);
    #pragma unroll
    for (int bb=0;bb<16;bb++){
      int m = t + 256*bb;
      sU[m + (m>>5)] = cmag(w[bb]);
    }
  }
  if (t < 97) g16[t] = GF[16*t];
  __syncthreads();

  float acc = 0.0f;
  for (int j=0;j<97;j++){
    int m = (16*t + j - 48) & 4095;
    acc += g16[j] * sU[m + (m>>5)];
  }
  sp2[(size_t)(b*NSEC + s0)*4096 + t] = 16.0f*acc;
}

// Decimated SO at N'=8192 pass A (j2 in {3,4,5}), with phase shift tau.
// idx<24: j2=3 (ch=idx, 5-alias); idx<56: j2=4 (ch=idx-24); else j2=5 (ch=idx-56).
__global__ void __launch_bounds__(256) k_so8kA(const __half2* __restrict__ u1f,
                                               const float2* __restrict__ u1f4,
                                               const float2* __restrict__ u1f8,
                                               float2* __restrict__ scr,
                                               int nstride, int tau)
{
  __shared__ float2 sm[16*257];
  const int f = threadIdx.x & 15, i = threadIdx.x >> 4;
  const int h = blockIdx.x, idx = blockIdx.y, b = blockIdx.z;
  const int j2 = (idx < 24) ? 3 : ((idx < 56) ? 4 : 5);
  const int ch = (idx < 24) ? idx : ((idx < 56) ? idx-24 : idx-56);
  const int ext = (j2 == 3) ? 2 : 1;
  const float xi   = 0.35f * exp2f(-(float)j2);
  const float invs = 1.0f/(0.6f*xi);
  const float kcf  = xi * 65536.0f;
  const __half2* src  = u1f  + ((size_t)b*JQ + ch)*NF;
  const float2*  src4 = u1f4 + ((size_t)b*32 + (ch-32))*4096;
  const float2*  src8 = u1f8 + ((size_t)(b*8 + (ch-24)))*8192;
  const int kB = h*16 + f;

  float2 v[16];
  #pragma unroll
  for (int r=0;r<16;r++){
    int kA = r*16 + i;
    int kp = kA*32 + kB;
    int d0 = (int)floorf((kcf - (float)kp) * (1.0f/8192.0f) + 0.5f);
    if (ch < 24){
      float2 a = make_float2(0.0f, 0.0f);
      for (int dd=-ext; dd<=ext; dd++){
        int k  = (kp + ((d0+dd) << 13)) & 65535;
        float fn = (k < 32768) ? (float)k*INV_N : ((float)k - 65536.0f)*INV_N;
        float z = (fn - xi)*invs;
        if (fabsf(z) < ZCUT){
          float g = expf(-0.5f*z*z);
          float2 X = h2f(src[(k & 255)*256 + (k >> 8)]);
          if (tau){ X = cmul(X, TW[(k*tau)&65535]); }
          float s = g * (4.0f*INV_N);
          a.x += X.x*s; a.y += X.y*s;
        }
      }
      v[r] = a;
    } else {
      float gsum = 0.0f;
      #pragma unroll
      for (int dd=-1; dd<=1; dd++){
        int k  = (kp + ((d0+dd) << 13)) & 65535;
        float fn = (k < 32768) ? (float)k*INV_N : ((float)k - 65536.0f)*INV_N;
        float z = (fn - xi)*invs;
        if (fabsf(z) < ZCUT) gsum += expf(-0.5f*z*z);
      }
      if (gsum != 0.0f){
        if (ch < 32){
          float2 X = src8[kp];
          float s = gsum * (8.0f*INV_N);
          v[r] = make_float2(X.x*s, X.y*s);
        } else {
          float2 X = src4[kp & 4095];
          float s = gsum * (16.0f*INV_N);
          v[r] = make_float2(X.x*s, X.y*s);
        }
      } else v[r] = make_float2(0.0f, 0.0f);
    }
  }
  fft256_pad<1>(v, i, sm + f*257);
  float2* dst = scr + ((size_t)(b*nstride + idx))*8192;
  #pragma unroll
  for (int k2=0;k2<16;k2++){
    int a = k2*16 + i;
    dst[a*32 + kB] = cmul(v[k2], TW[(a*kB*8)&65535]);
  }
}

// Pass B (j2 in {4,5}): 32-pt IFFT -> |.| -> M=8 decimated lowpass.
__global__ void __launch_bounds__(256) k_so8kB(const float2* __restrict__ scr,
                                               float* __restrict__ sp2)
{
  __shared__ float sU[8448];
  __shared__ float g8[193];
  const int t = threadIdx.x;
  const int idx = blockIdx.x + 24, b = blockIdx.y;
  const float2* s = scr + ((size_t)(b*NS8 + idx))*8192 + (size_t)t*32;

  float2 E[16], O[16];
  #pragma unroll
  for (int k=0;k<16;k++){ E[k] = s[2*k]; O[k] = s[2*k+1]; }
  fft16<1>(E); fft16<1>(O);
  #pragma unroll
  for (int k=0;k<16;k++){
    float2 w = TW[k*2048];
    float2 wo = cmul(w, O[k]);
    int m0 = k*256 + t;
    int m1 = (k+16)*256 + t;
    sU[m0 + (m0>>5)] = cmag(cadd(E[k], wo));
    sU[m1 + (m1>>5)] = cmag(csub(E[k], wo));
  }
  if (t < 193) g8[t] = GF[8*t];
  __syncthreads();

  float acc = 0.0f;
  for (int j=0;j<193;j++){
    int m = (32*t + j - 96) & 8191;
    acc += g8[j] * sU[m + (m>>5)];
  }
  const int s0 = TS2 + idx;
  sp2[(size_t)(b*NSEC + s0)*4096 + t] = 8.0f*acc;
}

// Pass B for j2=3: two phase signals (u(8m), u(8m+4)) -> M=4 lowpass.
__global__ void __launch_bounds__(256) k_so8kB_j3(const float2* __restrict__ scr0,
                                                  const float2* __restrict__ scr1,
                                                  float* __restrict__ sp2)
{
  extern __shared__ char dyn[];
  float* sU0 = (float*)dyn;                 // 8448
  float* sU1 = (float*)dyn + 8448;          // 8448
  float* ge  = (float*)dyn + 16896;         // 193 (GF[8j])
  float* go  = (float*)dyn + 17089;         // 192 (GF[8j+4])
  const int t = threadIdx.x;
  const int idx = blockIdx.x, b = blockIdx.y;

  #pragma unroll
  for (int ph=0; ph<2; ph++){
    const float2* s = (ph ? scr1 + ((size_t)(b*24 + idx))*8192
                          : scr0 + ((size_t)(b*NS8 + idx))*8192) + (size_t)t*32;
    float* sU = ph ? sU1 : sU0;
    float2 E[16], O[16];
    #pragma unroll
    for (int k=0;k<16;k++){ E[k] = s[2*k]; O[k] = s[2*k+1]; }
    fft16<1>(E); fft16<1>(O);
    #pragma unroll
    for (int k=0;k<16;k++){
      float2 w = TW[k*2048];
      float2 wo = cmul(w, O[k]);
      int m0 = k*256 + t;
      int m1 = (k+16)*256 + t;
      sU[m0 + (m0>>5)] = cmag(cadd(E[k], wo));
      sU[m1 + (m1>>5)] = cmag(csub(E[k], wo));
    }
  }
  if (t < 193) ge[t] = GF[8*t];
  if (t < 192) go[t] = GF[8*t+4];
  __syncthreads();

  float acc = 0.0f;
  for (int j=0;j<193;j++){
    int m = (32*t + j - 96) & 8191;
    int ms = m + (m>>5);
    acc += ge[j] * sU0[ms];
    if (j < 192) acc += go[j] * sU1[ms];
  }
  const int s0 = TS2 + idx;                 // 24..47
  sp2[(size_t)(b*NSEC + s0)*4096 + t] = 4.0f*acc;
}

// ---------------- S0 conv ----------------
#define CONV_OUT 32
#define CONV_WIN ((CONV_OUT-1)*256 + GTAPS)
__global__ void __launch_bounds__(256) k_conv_x(const float* __restrict__ x,
                                                float* __restrict__ out)
{
  const int grp = blockIdx.x, b = blockIdx.y;
  const float* src = x + (size_t)b*NF;
  __shared__ float win[CONV_WIN + 3];
  __shared__ float gs[GTAPS];
  const int tid = threadIdx.x;
  const int w0 = grp*(CONV_OUT*256) - LG;
  for (int i=tid; i<CONV_WIN; i+=256) win[i] = src[(w0 + i) & 65535];
  for (int i=tid; i<GTAPS; i+=256) gs[i] = GF[i];
  __syncthreads();
  const int warp = tid >> 5, lane = tid & 31;
  #pragma unroll
  for (int oo=0; oo<CONV_OUT/8; oo++){
    const int o = warp*(CONV_OUT/8) + oo;
    const int off = o * 256;
    float acc = 0.0f;
    for (int i=lane; i<GTAPS; i+=32) acc += gs[i] * win[off + i];
    #pragma unroll
    for (int d=16; d; d>>=1) acc += __shfl_down_sync(0xffffffffu, acc, d);
    if (lane == 0){
      int n = grp*CONV_OUT + o;
      float mag = sqrtf(acc*acc + 1e-8f);
      out[(size_t)b*NCHAN*256 + n] = logf(mag + 1e-8f);
    }
  }
}

// ---------------- epilogue (slot-aware) ----------------
__global__ void __launch_bounds__(256) k_log(const float* __restrict__ sp1,
                                             const float* __restrict__ sp2,
                                             float* __restrict__ out)
{
  const int row = blockIdx.x;
  const int b = row / 288, cm1 = row - b*288;
  const int m = threadIdx.x;
  const float* base;
  bool full;
  if (cm1 < 64){
    base = sp1 + (size_t)(b*JQ + cm1)*4096;
    full = (cm1 < FCH);
  } else {
    int s0 = cm1 - 64;
    base = sp2 + (size_t)(b*NSEC + s0)*4096;
    full = (s0 < TS2);
  }
  float S = base[m];
  if (full){
    #pragma unroll
    for (int k=1;k<16;k++) S += base[k*256 + m];
  }
  float mag = sqrtf(S*S + 1e-8f);
  out[((size_t)b*NCHAN + 1 + cm1)*256 + m] = logf(mag + 1e-8f);
}

__global__ void k_zero(float* p, int n){
  int i = blockIdx.x*blockDim.x + threadIdx.x;
  if (i < n) p[i] = 0.0f;
}

// ---------------- launch ----------------
extern "C" void kernel_launch(void* const* d_in, const int* in_sizes, int n_in,
                              void* d_out, int out_size)
{
  (void)in_sizes; (void)n_in;
  const float* x = (const float*)d_in[0];
  float* out = (float*)d_out;

  float2 *xtmp, *xf, *p1a, *p1b, *u1f4, *u1f8;
  __half2 *p2, *u1f;
  float *sp1, *sp2;
  cudaGetSymbolAddress((void**)&xtmp, d_xtmp);
  cudaGetSymbolAddress((void**)&xf,   d_xf);
  cudaGetSymbolAddress((void**)&p1a,  d_p1a);
  cudaGetSymbolAddress((void**)&p1b,  d_p1b);
  cudaGetSymbolAddress((void**)&p2,   d_p2);
  cudaGetSymbolAddress((void**)&u1f,  d_u1f);
  cudaGetSymbolAddress((void**)&u1f4, d_u1f4);
  cudaGetSymbolAddress((void**)&u1f8, d_u1f8);
  cudaGetSymbolAddress((void**)&sp1,  d_sp1);
  cudaGetSymbolAddress((void**)&sp2,  d_sp2);
  float2* scrA = p1a;
  float2* scrW = p1a + (size_t)64*8192;
  float2* scr0 = p1a;                              // so8k phase0 (96 sec/batch)
  float2* scr1 = p1a + (size_t)NS8*NB*8192;        // so8k phase1 (24 sec/batch)

  static int smem_set = 0;
  if (!smem_set){
    cudaFuncSetAttribute(k_so4096,   cudaFuncAttributeMaxDynamicSharedMemorySize, 69632);
    cudaFuncSetAttribute(k_fo4096,   cudaFuncAttributeMaxDynamicSharedMemorySize, 69632);
    cudaFuncSetAttribute(k_so8kB_j3, cudaFuncAttributeMaxDynamicSharedMemorySize, 70656);
    smem_set = 1;
  }

  k_tw<<<256, 256>>>();
  k_g <<<7,   256>>>();

  // forward FFT of x
  k_fwd_col_x<<<dim3(16,8), 256>>>(x, xtmp);
  k_fwd_row  <<<dim3(16,8), 256>>>(xtmp, xf);

  // first order, full-res channels ch<24
  k_invA1     <<<dim3(16,192), 256>>>(xf, p1a);
  k_fo_b      <<<dim3(16,192), 256>>>(p1a, p1b, sp1);
  k_fwd_row_u1<<<dim3(16,192), 256>>>(p1b, u1f);

  // first order, decimated: ch in [24,32) at N'=8192
  k_fo8kA <<<dim3(2, 8, NB), 256>>>(xf, scrA);
  k_fo8kBC<<<dim3(8, NB),    256>>>(scrA, sp1, scrW);
  k_fo8kC2<<<dim3(2, 8, NB), 256>>>(scrW, u1f8);

  // first order, decimated: ch>=32 at N'=4096 (fused)
  k_fo4096<<<dim3(32, NB), 256, 69632>>>(xf, sp1, u1f4);

  // second order, full-res sections (j2 <= 2)
  k_invA2   <<<dim3(16, 8*TS2), 256>>>(u1f, p2);
  k_invB_abs<<<dim3(16, 8*TS2), 256>>>(p2, sp2);

  // second order, decimated: j2 in {3,4,5} at N'=8192 (j2=3 two-phase)
  k_so8kA<<<dim3(2, NS8, NB), 256>>>(u1f, u1f4, u1f8, scr0, NS8, 0);
  k_so8kA<<<dim3(2, 24,  NB), 256>>>(u1f, u1f4, u1f8, scr1, 24, 4);
  k_so8kB   <<<dim3(NS8-24, NB), 256>>>(scr0, sp2);
  k_so8kB_j3<<<dim3(24, NB), 256, 70656>>>(scr0, scr1, sp2);

  // second order, decimated: j2 in {6,7} at N'=4096 (fused)
  k_so4096<<<dim3(104, NB), 256, 69632>>>(u1f, u1f4, u1f8, sp2);

  // S0 + epilogue
  k_conv_x<<<dim3(8, NB), 256>>>(x, out);
  k_log   <<<2304, 256>>>(sp1, sp2, out);

  int half = out_size / 2;
  k_zero<<<(half + 255)/256, 256>>>(out + half, half);
}

// round 16
// speedup vs baseline: 3.5963x; 1.4415x over previous
#include <cuda_runtime.h>
#include <cuda_fp16.h>
#include <math.h>
#include <stdint.h>

#define NF 65536
#define NB 8
#define JQ 64
#define NSEC 224
#define NCHAN 289
#define LG 768
#define GTAPS 1537
#define KPHI 1024
#define INV_N (1.0f/65536.0f)
#define ZCUT 7.4395f
#define TS2 24             // full-res SO sections per batch (j2<=2)
#define NS8 96             // N'=8192 SO sections per batch (j2 in {3,4,5})
#define FCH 24             // full-res FO channels (ch<24)

// ---------------- static device storage ----------------
static __device__ float2  TW[NF];
static __device__ float   GF[GTAPS];
static __device__ float2  d_xtmp[  8u*65536u];
static __device__ float2  d_xf  [  8u*65536u];
static __device__ float2  d_p1a [ 256u*65536u];
static __device__ float2  d_p1b [ 256u*65536u];
static __device__ __half2 d_p2  [(size_t)320u*65536u];
static __device__ __half2 d_u1f [ 512u*65536u];
static __device__ float2  d_u1f4[ 256u*4096u];
static __device__ float2  d_u1f8[  64u*8192u];
static __device__ float   d_sp1 [  512u*4096u];
static __device__ float   d_sp2 [ 1792u*4096u];

static __device__ const float2 W16T[16] = {
  { 1.0f, 0.0f},
  { 0.9238795325112867f, 0.3826834323650898f},
  { 0.7071067811865476f, 0.7071067811865476f},
  { 0.3826834323650898f, 0.9238795325112867f},
  { 0.0f, 1.0f},
  {-0.3826834323650898f, 0.9238795325112867f},
  {-0.7071067811865476f, 0.7071067811865476f},
  {-0.9238795325112867f, 0.3826834323650898f},
  {-1.0f, 0.0f},
  {-0.9238795325112867f,-0.3826834323650898f},
  {-0.7071067811865476f,-0.7071067811865476f},
  {-0.3826834323650898f,-0.9238795325112867f},
  { 0.0f,-1.0f},
  { 0.3826834323650898f,-0.9238795325112867f},
  { 0.7071067811865476f,-0.7071067811865476f},
  { 0.9238795325112867f,-0.3826834323650898f}
};

// ---------------- helpers ----------------
__device__ __forceinline__ float2 cadd(float2 a, float2 b){ return make_float2(a.x+b.x, a.y+b.y); }
__device__ __forceinline__ float2 csub(float2 a, float2 b){ return make_float2(a.x-b.x, a.y-b.y); }
__device__ __forceinline__ float2 cmul(float2 a, float2 b){ return make_float2(a.x*b.x-a.y*b.y, a.x*b.y+a.y*b.x); }
__device__ __forceinline__ float2 h2f(__half2 h){ return __half22float2(h); }
__device__ __forceinline__ __half2 f2h(float2 v){ return __float22half2_rn(v); }
__device__ __forceinline__ float cmag(float2 z){
  float x2 = z.x*z.x + z.y*z.y + 1e-36f;
  return x2 * rsqrtf(x2);
}
template<int S> __device__ __forceinline__ float2 mul_i(float2 a){
  return (S>0) ? make_float2(-a.y, a.x) : make_float2(a.y, -a.x);
}
template<int S> __device__ __forceinline__ void dft4(float2&a, float2&b, float2&c, float2&d){
  float2 t0=cadd(a,c), t1=csub(a,c), t2=cadd(b,d), t3=mul_i<S>(csub(b,d));
  a=cadd(t0,t2); c=csub(t0,t2); b=cadd(t1,t3); d=csub(t1,t3);
}
template<int S> __device__ __forceinline__ float2 w16(int m){
  float2 w = W16T[m];
  if (S < 0) w.y = -w.y;
  return w;
}
template<int S> __device__ __forceinline__ void fft16(float2 v[16]){
  #pragma unroll
  for (int n0=0; n0<4; n0++) dft4<S>(v[n0], v[n0+4], v[n0+8], v[n0+12]);
  #pragma unroll
  for (int n0=1; n0<4; n0++)
    #pragma unroll
    for (int k1=1; k1<4; k1++)
      v[n0+4*k1] = cmul(v[n0+4*k1], w16<S>(n0*k1));
  float2 o[16];
  #pragma unroll
  for (int k1=0; k1<4; k1++){
    float2 a=v[4*k1+0], b=v[4*k1+1], c=v[4*k1+2], d=v[4*k1+3];
    dft4<S>(a,b,c,d);
    o[k1]=a; o[k1+4]=b; o[k1+8]=c; o[k1+12]=d;
  }
  #pragma unroll
  for (int i=0;i<16;i++) v[i]=o[i];
}

// load TW[e] with sign
template<int S> __device__ __forceinline__ float2 twld(int e){
  float2 w = TW[e & 65535];
  if (S < 0) w.y = -w.y;
  return w;
}

// inter-stage twiddles by recurrence: v[k1] *= W(i*k1/256)
template<int S> __device__ __forceinline__ void twiddle256(float2 v[16], int i){
  float2 wb = twld<S>(i << 8);
  float2 w = wb;
  v[1] = cmul(v[1], w);
  #pragma unroll
  for (int k1=2;k1<16;k1++){
    w = cmul(w, wb);
    v[k1] = cmul(v[k1], w);
  }
}

template<int S> __device__ __forceinline__ void fft256_pad(float2 v[16], int i, float2* sm){
  fft16<S>(v);
  twiddle256<S>(v, i);
  #pragma unroll
  for (int k1=0;k1<16;k1++) sm[k1*16+i] = v[k1];
  __syncthreads();
  #pragma unroll
  for (int n0=0;n0<16;n0++) v[n0] = sm[i*16+n0];
  fft16<S>(v);
}

template<int S> __device__ __forceinline__ void fft256_swz(float2 v[16], int i, float2* sm){
  fft16<S>(v);
  twiddle256<S>(v, i);
  #pragma unroll
  for (int k1=0;k1<16;k1++) sm[k1*16 + ((i+k1)&15)] = v[k1];
  __syncwarp();
  #pragma unroll
  for (int n0=0;n0<16;n0++) v[n0] = sm[i*16 + ((n0+i)&15)];
  fft16<S>(v);
}

__device__ __forceinline__ void conv_partial(const float* u_s, const float* gf_s,
                                             int bx, int m, float* sp)
{
  float acc = 0.0f;
  #pragma unroll
  for (int f2=0; f2<16; f2++){
    const int q = bx*16 + f2 + 768;
    #pragma unroll
    for (int d=-3; d<=3; d++){
      int tap = d*256 + q;
      if (tap >= 0 && tap <= 1536)
        acc += gf_s[tap] * u_s[f2*257 + ((m + d) & 255)];
    }
  }
  sp[bx*256 + m] = acc;
}

// ---------------- setup kernels ----------------
__global__ void k_tw(){
  int k = blockIdx.x*blockDim.x + threadIdx.x;
  double a = 6.283185307179586476925286766559 * (double)k / 65536.0;
  TW[k] = make_float2((float)cos(a), (float)sin(a));
}
__global__ void k_g(){
  __shared__ float ps[KPHI+1];
  const int tid = threadIdx.x;
  const float invden = 1.0f/(65536.0f*(0.35f/256.0f));
  for (int k=tid; k<=KPHI; k+=256){
    float z = (float)k * invden;
    ps[k] = 2.0f*expf(-0.5f*z*z);
  }
  __syncthreads();
  int i = blockIdx.x*256 + tid;
  if (i >= GTAPS) return;
  int tt = i - LG; if (tt < 0) tt = -tt;
  float acc = 1.0f;
  for (int k=1; k<=KPHI; k++)
    acc += ps[k] * TW[(k*tt) & 65535].x;
  GF[i] = acc * INV_N;
}

// ---------------- FFT pass kernels ----------------
__global__ void __launch_bounds__(256) k_fwd_col_x(const float* __restrict__ x,
                                                   float2* __restrict__ out)
{
  __shared__ float2 sm[16*257];
  const int f = threadIdx.x & 15, i = threadIdx.x >> 4;
  const int col = blockIdx.x*16 + f;
  const size_t base = (size_t)blockIdx.y * NF;
  float2 v[16];
  #pragma unroll
  for (int r=0;r<16;r++) v[r] = make_float2(x[base + (r*16+i)*256 + col], 0.0f);
  fft256_pad<-1>(v, i, sm + f*257);
  // output twiddle W^-(col*K1), K1 = k2*16+i: base TW[col*i], step TW[col*16]
  float2 w = twld<-1>(col*i);
  const float2 st = twld<-1>(col*16);
  #pragma unroll
  for (int k2=0;k2<16;k2++){
    int K1 = k2*16 + i;
    out[base + K1*256 + col] = cmul(v[k2], w);
    w = cmul(w, st);
  }
}

__global__ void __launch_bounds__(256) k_fwd_row(const float2* __restrict__ in,
                                                 float2* __restrict__ out)
{
  __shared__ float2 sm[16*256];
  const int i = threadIdx.x & 15, f = threadIdx.x >> 4;
  const int row = blockIdx.x*16 + f;
  const size_t base = (size_t)blockIdx.y * NF;
  float2 v[16];
  #pragma unroll
  for (int r=0;r<16;r++) v[r] = in[base + row*256 + r*16 + i];
  fft256_swz<-1>(v, i, sm + f*256);
  #pragma unroll
  for (int k2=0;k2<16;k2++) out[base + row*256 + k2*16 + i] = v[k2];
}

__global__ void __launch_bounds__(256) k_fwd_row_u1(const float2* __restrict__ in,
                                                    __half2* __restrict__ out)
{
  __shared__ float2 sm[16*256];
  const int i = threadIdx.x & 15, f = threadIdx.x >> 4;
  const int row = blockIdx.x*16 + f;
  const int ti = blockIdx.y;
  const int b = ti / FCH, ch = ti - b*FCH;
  const size_t obase = ((size_t)b*JQ + ch) * NF;
  float2 v[16];
  #pragma unroll
  for (int r=0;r<16;r++) v[r] = in[(size_t)ti*NF + row*256 + r*16 + i];
  fft256_swz<-1>(v, i, sm + f*256);
  #pragma unroll
  for (int k2=0;k2<16;k2++){
    float2 o = v[k2];
    out[obase + row*256 + k2*16 + i] = f2h(make_float2(o.x*0.25f, o.y*0.25f));
  }
}

__global__ void __launch_bounds__(256) k_invA1(const float2* __restrict__ in,
                                               float2* __restrict__ out)
{
  __shared__ float2 sm[16*256];
  const int i = threadIdx.x & 15, f = threadIdx.x >> 4;
  const int K1 = blockIdx.x*16 + f;
  const int ti = blockIdx.y;
  const int b = ti / FCH, ch = ti - b*FCH;
  const float xi   = 0.35f * exp2f(-(float)ch * 0.125f);
  const float invs = 8.0f / xi;
  const float2* src = in + (size_t)b*NF;

  float2 v[16];
  #pragma unroll
  for (int r=0;r<16;r++){
    int k = (r*16 + i)*256 + K1;
    float fn = (k < 32768) ? (float)k * INV_N : ((float)k - 65536.0f) * INV_N;
    float z = (fn - xi) * invs;
    if (fabsf(z) < ZCUT){
      float g = expf(-0.5f*z*z);
      float2 X = src[K1*256 + (r*16+i)];
      float s = g * INV_N;
      v[r] = make_float2(X.x*s, X.y*s);
    } else v[r] = make_float2(0.0f, 0.0f);
  }
  fft256_swz<1>(v, i, sm + f*256);
  // output twiddle W^+(n2*K1), n2 = k2*16+i: base TW[i*K1], step TW[16*K1]
  float2 w = twld<1>(i*K1);
  const float2 st = twld<1>(16*K1);
  #pragma unroll
  for (int k2=0;k2<16;k2++){
    int n2 = k2*16 + i;
    out[(size_t)ti*NF + K1*256 + n2] = cmul(v[k2], w);
    w = cmul(w, st);
  }
}

__global__ void __launch_bounds__(256) k_invA2(const __half2* __restrict__ in,
                                               __half2* __restrict__ out)
{
  __shared__ float2 sm[16*256];
  const int i = threadIdx.x & 15, f = threadIdx.x >> 4;
  const int K1 = blockIdx.x*16 + f;
  const int ti = blockIdx.y;
  const int b = ti / TS2;
  const int s0 = ti - b*TS2;
  const int j2 = (s0 >= 8) ? 2 : 1;
  const int ch = s0 - 4*j2*(j2-1);
  const float xi   = 0.35f * exp2f(-(float)j2);
  const float invs = 1.0f / (0.6f * xi);
  const __half2* src = in + ((size_t)b*JQ + ch)*NF;

  float2 v[16];
  #pragma unroll
  for (int r=0;r<16;r++){
    int k = (r*16 + i)*256 + K1;
    float fn = (k < 32768) ? (float)k * INV_N : ((float)k - 65536.0f) * INV_N;
    float z = (fn - xi) * invs;
    if (fabsf(z) < ZCUT){
      float g = expf(-0.5f*z*z);
      float2 X = h2f(src[K1*256 + (r*16+i)]);
      float s = g * (16.0f*INV_N);
      v[r] = make_float2(X.x*s, X.y*s);
    } else v[r] = make_float2(0.0f, 0.0f);
  }
  fft256_swz<1>(v, i, sm + f*256);
  float2 w = twld<1>(i*K1);
  const float2 st = twld<1>(16*K1);
  #pragma unroll
  for (int k2=0;k2<16;k2++){
    int n2 = k2*16 + i;
    out[(size_t)ti*NF + K1*256 + n2] = f2h(cmul(v[k2], w));
    w = cmul(w, st);
  }
}

__global__ void __launch_bounds__(256) k_fo_b(const float2* __restrict__ T,
                                              float2* __restrict__ out,
                                              float* __restrict__ sp1)
{
  __shared__ __align__(16) char smraw[16*257*sizeof(float2)];
  float2* sm   = (float2*)smraw;
  float*  u_s  = (float*)smraw;
  float*  gf_s = (float*)smraw + 16*257;

  const int f = threadIdx.x & 15, i = threadIdx.x >> 4;
  const int tid = threadIdx.x;
  const int n2 = blockIdx.x*16 + f;
  const int ti = blockIdx.y;
  const int b = ti / FCH, ch = ti - b*FCH;
  const size_t base = (size_t)ti * NF;
  const size_t spo  = ((size_t)b*JQ + ch) * 4096;
  float2 v[16];
  #pragma unroll
  for (int r=0;r<16;r++) v[r] = T[base + (r*16+i)*256 + n2];
  fft256_pad<1>(v, i, sm + f*257);
  __syncthreads();
  #pragma unroll
  for (int k2=0;k2<16;k2++)
    u_s[f*257 + k2*16 + i] = cmag(v[k2]);
  for (int t=tid; t<GTAPS; t+=256) gf_s[t] = GF[t];
  __syncthreads();
  conv_partial(u_s, gf_s, blockIdx.x, tid, sp1 + spo);
  __syncthreads();
  #pragma unroll
  for (int r=0;r<16;r++) v[r] = make_float2(u_s[f*257 + r*16 + i], 0.0f);
  __syncthreads();
  fft256_pad<-1>(v, i, sm + f*257);
  // output twiddle W^-(n2*K1), K1 = k2*16+i: base TW[n2*i], step TW[n2*16]
  float2 w = twld<-1>(n2*i);
  const float2 st = twld<-1>(n2*16);
  #pragma unroll
  for (int k2=0;k2<16;k2++){
    int K1 = k2*16 + i;
    out[base + K1*256 + n2] = cmul(v[k2], w);
    w = cmul(w, st);
  }
}

__global__ void __launch_bounds__(256) k_invB_abs(const __half2* __restrict__ T,
                                                  float* __restrict__ sp2)
{
  __shared__ __align__(16) char smraw[16*257*sizeof(float2)];
  float2* sm   = (float2*)smraw;
  float*  u_s  = (float*)smraw;
  float*  gf_s = (float*)smraw + 16*257;

  const int f = threadIdx.x & 15, i = threadIdx.x >> 4;
  const int tid = threadIdx.x;
  const int n2 = blockIdx.x*16 + f;
  const int ti = blockIdx.y;
  const int b = ti / TS2, s0 = ti - b*TS2;
  const size_t base = (size_t)ti * NF;
  float2 v[16];
  #pragma unroll
  for (int r=0;r<16;r++) v[r] = h2f(T[base + (r*16+i)*256 + n2]);
  fft256_pad<1>(v, i, sm + f*257);
  __syncthreads();
  #pragma unroll
  for (int k2=0;k2<16;k2++)
    u_s[f*257 + k2*16 + i] = 0.25f*cmag(v[k2]);
  for (int t=tid; t<GTAPS; t+=256) gf_s[t] = GF[t];
  __syncthreads();
  conv_partial(u_s, gf_s, blockIdx.x, tid, sp2 + (size_t)(b*NSEC + s0)*4096);
}

// Fused decimated FIRST ORDER for ch>=32 (N'=4096).
__global__ void __launch_bounds__(256) k_fo4096(const float2* __restrict__ xf,
                                                float* __restrict__ sp1,
                                                float2* __restrict__ u1f4)
{
  extern __shared__ char dyn[];
  float2* sm  = (float2*)dyn;
  float2* sA  = (float2*)dyn + 4112;
  float*  sU  = (float*)dyn;
  float*  g16 = (float*)dyn + 4300;

  const int t = threadIdx.x;
  const int f = t & 15, i = t >> 4;
  const int ch = 32 + blockIdx.x;
  const int b  = blockIdx.y;
  const float xi   = 0.35f * exp2f(-(float)ch * 0.125f);
  const float invs = 8.0f / xi;
  const float kcf  = xi * 65536.0f;
  const float2* src = xf + (size_t)b*NF;

  float2 v[16];
  #pragma unroll
  for (int r=0;r<16;r++){
    int kp = r*256 + i*16 + f;
    int d0 = (int)floorf((kcf - (float)kp) * (1.0f/4096.0f) + 0.5f);
    int k  = (kp + (d0 << 12)) & 65535;
    float fn = (k < 32768) ? (float)k*INV_N : ((float)k - 65536.0f)*INV_N;
    float z = (fn - xi)*invs;
    if (fabsf(z) < ZCUT){
      float g = expf(-0.5f*z*z) * INV_N;
      float2 X = src[(k & 255)*256 + (k >> 8)];
      v[r] = make_float2(X.x*g, X.y*g);
    } else v[r] = make_float2(0.0f, 0.0f);
  }
  fft256_pad<1>(v, i, sm + f*257);
  // store twiddle W^+(a*f*16), a = k2*16+i: base TW[i*f*16], step TW[f*256]
  {
    float2 w = twld<1>(i*f*16);
    const float2 st = twld<1>(f*256);
    #pragma unroll
    for (int k2=0;k2<16;k2++){
      int a = k2*16 + i;
      sA[a*17 + f] = cmul(v[k2], w);
      w = cmul(w, st);
    }
  }
  __syncthreads();

  {
    float2 w[16];
    #pragma unroll
    for (int kB=0;kB<16;kB++) w[kB] = sA[t*17 + kB];
    fft16<1>(w);
    #pragma unroll
    for (int bb=0;bb<16;bb++){
      int m = t + 256*bb;
      sU[m + (m>>5)] = cmag(w[bb]);
    }
  }
  if (t < 97) g16[t] = GF[16*t];
  __syncthreads();

  {
    float acc = 0.0f;
    for (int j=0;j<97;j++){
      int m = (16*t + j - 48) & 4095;
      acc += g16[j] * sU[m + (m>>5)];
    }
    sp1[((size_t)b*JQ + ch)*4096 + t] = 16.0f*acc;
  }

  float2 c[16];
  #pragma unroll
  for (int mB=0;mB<16;mB++){
    int m = t + 256*mB;
    c[mB] = make_float2(sU[m + (m>>5)], 0.0f);
  }
  fft16<-1>(c);
  {
    float2 w = make_float2(1.0f, 0.0f);
    const float2 st = twld<-1>(t*16);
    #pragma unroll
    for (int q=0;q<16;q++){
      sA[t*17 + q] = cmul(c[q], w);
      w = cmul(w, st);
    }
  }
  __syncthreads();

  float2 u[16];
  #pragma unroll
  for (int r=0;r<16;r++) u[r] = sA[(r*16+i)*17 + f];
  fft256_pad<-1>(u, i, sm + f*257);
  float2* dst = u1f4 + ((size_t)b*32 + (ch-32))*4096;
  #pragma unroll
  for (int k2=0;k2<16;k2++)
    dst[f + 16*(k2*16 + i)] = u[k2];
}

// Decimated FO for ch in [24,32), N'=8192, pass A.
__global__ void __launch_bounds__(256) k_fo8kA(const float2* __restrict__ xf,
                                               float2* __restrict__ scrA)
{
  __shared__ float2 sm[16*257];
  const int f = threadIdx.x & 15, i = threadIdx.x >> 4;
  const int h = blockIdx.x, idx8 = blockIdx.y, b = blockIdx.z;
  const int ch = 24 + idx8;
  const float xi   = 0.35f * exp2f(-(float)ch * 0.125f);
  const float invs = 8.0f / xi;
  const float kcf  = xi * 65536.0f;
  const float2* src = xf + (size_t)b*NF;
  const int kB = h*16 + f;

  float2 v[16];
  #pragma unroll
  for (int r=0;r<16;r++){
    int kA = r*16 + i;
    int kp = kA*32 + kB;
    int d0 = (int)floorf((kcf - (float)kp) * (1.0f/8192.0f) + 0.5f);
    int k  = (kp + (d0 << 13)) & 65535;
    float fn = (k < 32768) ? (float)k*INV_N : ((float)k - 65536.0f)*INV_N;
    float z = (fn - xi)*invs;
    if (fabsf(z) < ZCUT){
      float g = expf(-0.5f*z*z) * INV_N;
      float2 X = src[(k & 255)*256 + (k >> 8)];
      v[r] = make_float2(X.x*g, X.y*g);
    } else v[r] = make_float2(0.0f, 0.0f);
  }
  fft256_pad<1>(v, i, sm + f*257);
  float2* dst = scrA + ((size_t)(b*8 + idx8))*8192;
  // store twiddle W^+(a*kB*8), a = k2*16+i: base TW[i*kB*8], step TW[kB*128]
  float2 w = twld<1>(i*kB*8);
  const float2 st = twld<1>(kB*128);
  #pragma unroll
  for (int k2=0;k2<16;k2++){
    int a = k2*16 + i;
    dst[a*32 + kB] = cmul(v[k2], w);
    w = cmul(w, st);
  }
}

__global__ void __launch_bounds__(256) k_fo8kBC(const float2* __restrict__ scrA,
                                                float* __restrict__ sp1,
                                                float2* __restrict__ scrW)
{
  __shared__ float sU[8448];
  __shared__ float g8[193];
  const int t = threadIdx.x;
  const int idx8 = blockIdx.x, b = blockIdx.y;
  const float2* s = scrA + ((size_t)(b*8 + idx8))*8192 + (size_t)t*32;

  {
    float2 E[16], O[16];
    #pragma unroll
    for (int k=0;k<16;k++){ E[k] = s[2*k]; O[k] = s[2*k+1]; }
    fft16<1>(E); fft16<1>(O);
    #pragma unroll
    for (int k=0;k<16;k++){
      float2 w = TW[k*2048];
      float2 wo = cmul(w, O[k]);
      int m0 = k*256 + t;
      int m1 = (k+16)*256 + t;
      sU[m0 + (m0>>5)] = cmag(cadd(E[k], wo));
      sU[m1 + (m1>>5)] = cmag(csub(E[k], wo));
    }
  }
  if (t < 193) g8[t] = GF[8*t];
  __syncthreads();

  {
    float acc = 0.0f;
    for (int j=0;j<193;j++){
      int m = (32*t + j - 96) & 8191;
      acc += g8[j] * sU[m + (m>>5)];
    }
    sp1[((size_t)b*JQ + 24 + idx8)*4096 + t] = 8.0f*acc;
  }

  {
    float2 E[16], O[16];
    #pragma unroll
    for (int k=0;k<16;k++){
      int me = (2*k)*256 + t, mo = (2*k+1)*256 + t;
      E[k] = make_float2(sU[me + (me>>5)], 0.0f);
      O[k] = make_float2(sU[mo + (mo>>5)], 0.0f);
    }
    fft16<-1>(E); fft16<-1>(O);
    float2* dst = scrW + ((size_t)(b*8 + idx8))*8192;
    // w0 = W^-(t*k*8) by recurrence; w1 = w0 * W^-(t*128)
    float2 w0 = make_float2(1.0f, 0.0f);
    const float2 st  = twld<-1>(t*8);
    const float2 sh  = twld<-1>(t*128);
    #pragma unroll
    for (int k=0;k<16;k++){
      float2 w = TW[k*2048]; w.y = -w.y;
      float2 wo = cmul(w, O[k]);
      float2 X0 = cadd(E[k], wo);
      float2 X1 = csub(E[k], wo);
      dst[k*256 + t]      = cmul(X0, w0);
      dst[(k+16)*256 + t] = cmul(X1, cmul(w0, sh));
      w0 = cmul(w0, st);
    }
  }
}

__global__ void __launch_bounds__(256) k_fo8kC2(const float2* __restrict__ scrW,
                                                float2* __restrict__ u1f8)
{
  __shared__ float2 sm[16*256];
  const int i = threadIdx.x & 15, f = threadIdx.x >> 4;
  const int h = blockIdx.x, idx8 = blockIdx.y, b = blockIdx.z;
  const int kB = h*16 + f;
  const size_t base = (size_t)(b*8 + idx8)*8192;
  float2 v[16];
  #pragma unroll
  for (int r=0;r<16;r++) v[r] = scrW[base + kB*256 + r*16 + i];
  fft256_swz<-1>(v, i, sm + f*256);
  float2* dst = u1f8 + base;
  #pragma unroll
  for (int k2=0;k2<16;k2++)
    dst[(k2*16 + i)*32 + kB] = v[k2];
}

// Fused decimated SO, N'=4096, M=16 (j2 in {6,7}). 3-way source.
__global__ void __launch_bounds__(256) k_so4096(const __half2* __restrict__ u1f,
                                                const float2* __restrict__ u1f4,
                                                const float2* __restrict__ u1f8,
                                                float* __restrict__ sp2)
{
  extern __shared__ char dyn[];
  float2* sm  = (float2*)dyn;
  float2* sA  = (float2*)dyn + 4112;
  float*  sU  = (float*)dyn;
  float*  g16 = (float*)dyn + 4300;

  const int t = threadIdx.x;
  const int f = t & 15, i = t >> 4;
  const int s0 = 120 + blockIdx.x;
  const int b  = blockIdx.y;
  const int j2 = (s0 >= 168) ? 7 : 6;
  const int ch = s0 - 4*j2*(j2-1);
  const float xi   = 0.35f * exp2f(-(float)j2);
  const float invs = 1.0f/(0.6f*xi);
  const float kcf  = xi * 65536.0f;
  const __half2* src  = u1f  + ((size_t)b*JQ + ch)*NF;
  const float2*  src4 = u1f4 + ((size_t)b*32 + (ch-32))*4096;
  const float2*  src8 = u1f8 + ((size_t)(b*8 + (ch-24)))*8192;

  float2 v[16];
  #pragma unroll
  for (int r=0;r<16;r++){
    int kp = r*256 + i*16 + f;
    int d0 = (int)floorf((kcf - (float)kp) * (1.0f/4096.0f) + 0.5f);
    if (ch < 24){
      float2 a = make_float2(0.0f, 0.0f);
      #pragma unroll
      for (int dd=-1; dd<=1; dd++){
        int k  = (kp + ((d0+dd) << 12)) & 65535;
        float fn = (k < 32768) ? (float)k*INV_N : ((float)k - 65536.0f)*INV_N;
        float z = (fn - xi)*invs;
        if (fabsf(z) < ZCUT){
          float g = expf(-0.5f*z*z);
          float2 X = h2f(src[(k & 255)*256 + (k >> 8)]);
          float s = g * (4.0f*INV_N);
          a.x += X.x*s; a.y += X.y*s;
        }
      }
      v[r] = a;
    } else if (ch < 32){
      float2 a = make_float2(0.0f, 0.0f);
      #pragma unroll
      for (int dd=-1; dd<=1; dd++){
        int k  = (kp + ((d0+dd) << 12)) & 65535;
        float fn = (k < 32768) ? (float)k*INV_N : ((float)k - 65536.0f)*INV_N;
        float z = (fn - xi)*invs;
        if (fabsf(z) < ZCUT){
          float g = expf(-0.5f*z*z);
          float2 X = src8[k & 8191];
          float s = g * (8.0f*INV_N);
          a.x += X.x*s; a.y += X.y*s;
        }
      }
      v[r] = a;
    } else {
      float gsum = 0.0f;
      #pragma unroll
      for (int dd=-1; dd<=1; dd++){
        int k  = (kp + ((d0+dd) << 12)) & 65535;
        float fn = (k < 32768) ? (float)k*INV_N : ((float)k - 65536.0f)*INV_N;
        float z = (fn - xi)*invs;
        if (fabsf(z) < ZCUT) gsum += expf(-0.5f*z*z);
      }
      if (gsum != 0.0f){
        float2 X = src4[kp];
        float s = gsum * (16.0f*INV_N);
        v[r] = make_float2(X.x*s, X.y*s);
      } else v[r] = make_float2(0.0f, 0.0f);
    }
  }
  fft256_pad<1>(v, i, sm + f*257);
  {
    float2 w = twld<1>(i*f*16);
    const float2 st = twld<1>(f*256);
    #pragma unroll
    for (int k2=0;k2<16;k2++){
      int a = k2*16 + i;
      sA[a*17 + f] = cmul(v[k2], w);
      w = cmul(w, st);
    }
  }
  __syncthreads();

  {
    float2 w[16];
    #pragma unroll
    for (int kB=0;kB<16;kB++) w[kB] = sA[t*17 + kB];
    fft16<1>(w);
    #pragma unroll
    for (int bb=0;bb<16;bb++){
      int m = t + 256*bb;
      sU[m + (m>>5)] = cmag(w[bb]);
    }
  }
  if (t < 97) g16[t] = GF[16*t];
  __syncthreads();

  float acc = 0.0f;
  for (int j=0;j<97;j++){
    int m = (16*t + j - 48) & 4095;
    acc += g16[j] * sU[m + (m>>5)];
  }
  sp2[(size_t)(b*NSEC + s0)*4096 + t] = 16.0f*acc;
}

// Decimated SO at N'=8192 pass A (j2 in {3,4,5}), phase shift tau.
__global__ void __launch_bounds__(256) k_so8kA(const __half2* __restrict__ u1f,
                                               const float2* __restrict__ u1f4,
                                               const float2* __restrict__ u1f8,
                                               float2* __restrict__ scr,
                                               int nstride, int tau)
{
  __shared__ float2 sm[16*257];
  const int f = threadIdx.x & 15, i = threadIdx.x >> 4;
  const int h = blockIdx.x, idx = blockIdx.y, b = blockIdx.z;
  const int j2 = (idx < 24) ? 3 : ((idx < 56) ? 4 : 5);
  const int ch = (idx < 24) ? idx : ((idx < 56) ? idx-24 : idx-56);
  const int ext = (j2 == 3) ? 2 : 1;
  const float xi   = 0.35f * exp2f(-(float)j2);
  const float invs = 1.0f/(0.6f*xi);
  const float kcf  = xi * 65536.0f;
  const __half2* src  = u1f  + ((size_t)b*JQ + ch)*NF;
  const float2*  src4 = u1f4 + ((size_t)b*32 + (ch-32))*4096;
  const float2*  src8 = u1f8 + ((size_t)(b*8 + (ch-24)))*8192;
  const int kB = h*16 + f;

  float2 v[16];
  #pragma unroll
  for (int r=0;r<16;r++){
    int kA = r*16 + i;
    int kp = kA*32 + kB;
    int d0 = (int)floorf((kcf - (float)kp) * (1.0f/8192.0f) + 0.5f);
    if (ch < 24){
      float2 a = make_float2(0.0f, 0.0f);
      for (int dd=-ext; dd<=ext; dd++){
        int k  = (kp + ((d0+dd) << 13)) & 65535;
        float fn = (k < 32768) ? (float)k*INV_N : ((float)k - 65536.0f)*INV_N;
        float z = (fn - xi)*invs;
        if (fabsf(z) < ZCUT){
          float g = expf(-0.5f*z*z);
          float2 X = h2f(src[(k & 255)*256 + (k >> 8)]);
          if (tau){ X = cmul(X, TW[(k*tau)&65535]); }
          float s = g * (4.0f*INV_N);
          a.x += X.x*s; a.y += X.y*s;
        }
      }
      v[r] = a;
    } else {
      float gsum = 0.0f;
      #pragma unroll
      for (int dd=-1; dd<=1; dd++){
        int k  = (kp + ((d0+dd) << 13)) & 65535;
        float fn = (k < 32768) ? (float)k*INV_N : ((float)k - 65536.0f)*INV_N;
        float z = (fn - xi)*invs;
        if (fabsf(z) < ZCUT) gsum += expf(-0.5f*z*z);
      }
      if (gsum != 0.0f){
        if (ch < 32){
          float2 X = src8[kp];
          float s = gsum * (8.0f*INV_N);
          v[r] = make_float2(X.x*s, X.y*s);
        } else {
          float2 X = src4[kp & 4095];
          float s = gsum * (16.0f*INV_N);
          v[r] = make_float2(X.x*s, X.y*s);
        }
      } else v[r] = make_float2(0.0f, 0.0f);
    }
  }
  fft256_pad<1>(v, i, sm + f*257);
  float2* dst = scr + ((size_t)(b*nstride + idx))*8192;
  float2 w = twld<1>(i*kB*8);
  const float2 st = twld<1>(kB*128);
  #pragma unroll
  for (int k2=0;k2<16;k2++){
    int a = k2*16 + i;
    dst[a*32 + kB] = cmul(v[k2], w);
    w = cmul(w, st);
  }
}

__global__ void __launch_bounds__(256) k_so8kB(const float2* __restrict__ scr,
                                               float* __restrict__ sp2)
{
  __shared__ float sU[8448];
  __shared__ float g8[193];
  const int t = threadIdx.x;
  const int idx = blockIdx.x + 24, b = blockIdx.y;
  const float2* s = scr + ((size_t)(b*NS8 + idx))*8192 + (size_t)t*32;

  float2 E[16], O[16];
  #pragma unroll
  for (int k=0;k<16;k++){ E[k] = s[2*k]; O[k] = s[2*k+1]; }
  fft16<1>(E); fft16<1>(O);
  #pragma unroll
  for (int k=0;k<16;k++){
    float2 w = TW[k*2048];
    float2 wo = cmul(w, O[k]);
    int m0 = k*256 + t;
    int m1 = (k+16)*256 + t;
    sU[m0 + (m0>>5)] = cmag(cadd(E[k], wo));
    sU[m1 + (m1>>5)] = cmag(csub(E[k], wo));
  }
  if (t < 193) g8[t] = GF[8*t];
  __syncthreads();

  float acc = 0.0f;
  for (int j=0;j<193;j++){
    int m = (32*t + j - 96) & 8191;
    acc += g8[j] * sU[m + (m>>5)];
  }
  const int s0 = TS2 + idx;
  sp2[(size_t)(b*NSEC + s0)*4096 + t] = 8.0f*acc;
}

__global__ void __launch_bounds__(256) k_so8kB_j3(const float2* __restrict__ scr0,
                                                  const float2* __restrict__ scr1,
                                                  float* __restrict__ sp2)
{
  extern __shared__ char dyn[];
  float* sU0 = (float*)dyn;
  float* sU1 = (float*)dyn + 8448;
  float* ge  = (float*)dyn + 16896;
  float* go  = (float*)dyn + 17089;
  const int t = threadIdx.x;
  const int idx = blockIdx.x, b = blockIdx.y;

  #pragma unroll
  for (int ph=0; ph<2; ph++){
    const float2* s = (ph ? scr1 + ((size_t)(b*24 + idx))*8192
                          : scr0 + ((size_t)(b*NS8 + idx))*8192) + (size_t)t*32;
    float* sU = ph ? sU1 : sU0;
    float2 E[16], O[16];
    #pragma unroll
    for (int k=0;k<16;k++){ E[k] = s[2*k]; O[k] = s[2*k+1]; }
    fft16<1>(E); fft16<1>(O);
    #pragma unroll
    for (int k=0;k<16;k++){
      float2 w = TW[k*2048];
      float2 wo = cmul(w, O[k]);
      int m0 = k*256 + t;
      int m1 = (k+16)*256 + t;
      sU[m0 + (m0>>5)] = cmag(cadd(E[k], wo));
      sU[m1 + (m1>>5)] = cmag(csub(E[k], wo));
    }
  }
  if (t < 193) ge[t] = GF[8*t];
  if (t < 192) go[t] = GF[8*t+4];
  __syncthreads();

  float acc = 0.0f;
  for (int j=0;j<193;j++){
    int m = (32*t + j - 96) & 8191;
    int ms = m + (m>>5);
    acc += ge[j] * sU0[ms];
    if (j < 192) acc += go[j] * sU1[ms];
  }
  const int s0 = TS2 + idx;
  sp2[(size_t)(b*NSEC + s0)*4096 + t] = 4.0f*acc;
}

// ---------------- S0 conv ----------------
#define CONV_OUT 32
#define CONV_WIN ((CONV_OUT-1)*256 + GTAPS)
__global__ void __launch_bounds__(256) k_conv_x(const float* __restrict__ x,
                                                float* __restrict__ out)
{
  const int grp = blockIdx.x, b = blockIdx.y;
  const float* src = x + (size_t)b*NF;
  __shared__ float win[CONV_WIN + 3];
  __shared__ float gs[GTAPS];
  const int tid = threadIdx.x;
  const int w0 = grp*(CONV_OUT*256) - LG;
  for (int i=tid; i<CONV_WIN; i+=256) win[i] = src[(w0 + i) & 65535];
  for (int i=tid; i<GTAPS; i+=256) gs[i] = GF[i];
  __syncthreads();
  const int warp = tid >> 5, lane = tid & 31;
  #pragma unroll
  for (int oo=0; oo<CONV_OUT/8; oo++){
    const int o = warp*(CONV_OUT/8) + oo;
    const int off = o * 256;
    float acc = 0.0f;
    for (int i=lane; i<GTAPS; i+=32) acc += gs[i] * win[off + i];
    #pragma unroll
    for (int d=16; d; d>>=1) acc += __shfl_down_sync(0xffffffffu, acc, d);
    if (lane == 0){
      int n = grp*CONV_OUT + o;
      float mag = sqrtf(acc*acc + 1e-8f);
      out[(size_t)b*NCHAN*256 + n] = logf(mag + 1e-8f);
    }
  }
}

// ---------------- epilogue (slot-aware) ----------------
__global__ void __launch_bounds__(256) k_log(const float* __restrict__ sp1,
                                             const float* __restrict__ sp2,
                                             float* __restrict__ out)
{
  const int row = blockIdx.x;
  const int b = row / 288, cm1 = row - b*288;
  const int m = threadIdx.x;
  const float* base;
  bool full;
  if (cm1 < 64){
    base = sp1 + (size_t)(b*JQ + cm1)*4096;
    full = (cm1 < FCH);
  } else {
    int s0 = cm1 - 64;
    base = sp2 + (size_t)(b*NSEC + s0)*4096;
    full = (s0 < TS2);
  }
  float S = base[m];
  if (full){
    #pragma unroll
    for (int k=1;k<16;k++) S += base[k*256 + m];
  }
  float mag = sqrtf(S*S + 1e-8f);
  out[((size_t)b*NCHAN + 1 + cm1)*256 + m] = logf(mag + 1e-8f);
}

__global__ void k_zero(float* p, int n){
  int i = blockIdx.x*blockDim.x + threadIdx.x;
  if (i < n) p[i] = 0.0f;
}

// ---------------- launch ----------------
extern "C" void kernel_launch(void* const* d_in, const int* in_sizes, int n_in,
                              void* d_out, int out_size)
{
  (void)in_sizes; (void)n_in;
  const float* x = (const float*)d_in[0];
  float* out = (float*)d_out;

  float2 *xtmp, *xf, *p1a, *p1b, *u1f4, *u1f8;
  __half2 *p2, *u1f;
  float *sp1, *sp2;
  cudaGetSymbolAddress((void**)&xtmp, d_xtmp);
  cudaGetSymbolAddress((void**)&xf,   d_xf);
  cudaGetSymbolAddress((void**)&p1a,  d_p1a);
  cudaGetSymbolAddress((void**)&p1b,  d_p1b);
  cudaGetSymbolAddress((void**)&p2,   d_p2);
  cudaGetSymbolAddress((void**)&u1f,  d_u1f);
  cudaGetSymbolAddress((void**)&u1f4, d_u1f4);
  cudaGetSymbolAddress((void**)&u1f8, d_u1f8);
  cudaGetSymbolAddress((void**)&sp1,  d_sp1);
  cudaGetSymbolAddress((void**)&sp2,  d_sp2);
  float2* scrA = p1a;
  float2* scrW = p1a + (size_t)64*8192;
  float2* scr0 = p1a;
  float2* scr1 = p1a + (size_t)NS8*NB*8192;

  static int smem_set = 0;
  if (!smem_set){
    cudaFuncSetAttribute(k_so4096,   cudaFuncAttributeMaxDynamicSharedMemorySize, 69632);
    cudaFuncSetAttribute(k_fo4096,   cudaFuncAttributeMaxDynamicSharedMemorySize, 69632);
    cudaFuncSetAttribute(k_so8kB_j3, cudaFuncAttributeMaxDynamicSharedMemorySize, 70656);
    smem_set = 1;
  }

  k_tw<<<256, 256>>>();
  k_g <<<7,   256>>>();

  // forward FFT of x
  k_fwd_col_x<<<dim3(16,8), 256>>>(x, xtmp);
  k_fwd_row  <<<dim3(16,8), 256>>>(xtmp, xf);

  // first order, full-res channels ch<24
  k_invA1     <<<dim3(16,192), 256>>>(xf, p1a);
  k_fo_b      <<<dim3(16,192), 256>>>(p1a, p1b, sp1);
  k_fwd_row_u1<<<dim3(16,192), 256>>>(p1b, u1f);

  // first order, decimated: ch in [24,32) at N'=8192
  k_fo8kA <<<dim3(2, 8, NB), 256>>>(xf, scrA);
  k_fo8kBC<<<dim3(8, NB),    256>>>(scrA, sp1, scrW);
  k_fo8kC2<<<dim3(2, 8, NB), 256>>>(scrW, u1f8);

  // first order, decimated: ch>=32 at N'=4096 (fused)
  k_fo4096<<<dim3(32, NB), 256, 69632>>>(xf, sp1, u1f4);

  // second order, full-res sections (j2 <= 2)
  k_invA2   <<<dim3(16, 8*TS2), 256>>>(u1f, p2);
  k_invB_abs<<<dim3(16, 8*TS2), 256>>>(p2, sp2);

  // second order, decimated: j2 in {3,4,5} at N'=8192 (j2=3 two-phase)
  k_so8kA<<<dim3(2, NS8, NB), 256>>>(u1f, u1f4, u1f8, scr0, NS8, 0);
  k_so8kA<<<dim3(2, 24,  NB), 256>>>(u1f, u1f4, u1f8, scr1, 24, 4);
  k_so8kB   <<<dim3(NS8-24, NB), 256>>>(scr0, sp2);
  k_so8kB_j3<<<dim3(24, NB), 256, 70656>>>(scr0, scr1, sp2);

  // second order, decimated: j2 in {6,7} at N'=4096 (fused)
  k_so4096<<<dim3(104, NB), 256, 69632>>>(u1f, u1f4, u1f8, sp2);

  // S0 + epilogue
  k_conv_x<<<dim3(8, NB), 256>>>(x, out);
  k_log   <<<2304, 256>>>(sp1, sp2, out);

  int half = out_size / 2;
  k_zero<<<(half + 255)/256, 256>>>(out + half, half);
}

// round 17
// speedup vs baseline: 3.5975x; 1.0004x over previous
#include <cuda_runtime.h>
#include <cuda_fp16.h>
#include <math.h>
#include <stdint.h>

#define NF 65536
#define NB 8
#define JQ 64
#define NSEC 224
#define NCHAN 289
#define LG 768
#define GTAPS 1537
#define KPHI 1024
#define INV_N (1.0f/65536.0f)
#define ZCUT 7.4395f
#define TS2 24
#define NS8 96
#define FCH 24

// ---------------- static device storage ----------------
static __device__ float2  TW[NF];
static __device__ float   GF[GTAPS];
static __device__ float2  d_xtmp[  8u*65536u];
static __device__ float2  d_xf  [  8u*65536u];
static __device__ float2  d_p1a [ 256u*65536u];
static __device__ float2  d_p1b [ 256u*65536u];
static __device__ __half2 d_p2  [(size_t)320u*65536u];
static __device__ __half2 d_u1f [ 512u*65536u];
static __device__ float2  d_u1f4[ 256u*4096u];
static __device__ float2  d_u1f8[  64u*8192u];
static __device__ float   d_sp1 [  512u*4096u];
static __device__ float   d_sp2 [ 1792u*4096u];

// ---------------- helpers ----------------
__device__ __forceinline__ float2 cadd(float2 a, float2 b){ return make_float2(a.x+b.x, a.y+b.y); }
__device__ __forceinline__ float2 csub(float2 a, float2 b){ return make_float2(a.x-b.x, a.y-b.y); }
__device__ __forceinline__ float2 cmul(float2 a, float2 b){ return make_float2(a.x*b.x-a.y*b.y, a.x*b.y+a.y*b.x); }
__device__ __forceinline__ float2 h2f(__half2 h){ return __half22float2(h); }
__device__ __forceinline__ __half2 f2h(float2 v){ return __float22half2_rn(v); }
__device__ __forceinline__ float cmag(float2 z){
  float x2 = z.x*z.x + z.y*z.y + 1e-36f;
  return x2 * rsqrtf(x2);
}
template<int S> __device__ __forceinline__ float2 mul_i(float2 a){
  return (S>0) ? make_float2(-a.y, a.x) : make_float2(a.y, -a.x);
}
template<int S> __device__ __forceinline__ void dft4(float2&a, float2&b, float2&c, float2&d){
  float2 t0=cadd(a,c), t1=csub(a,c), t2=cadd(b,d), t3=mul_i<S>(csub(b,d));
  a=cadd(t0,t2); c=csub(t0,t2); b=cadd(t1,t3); d=csub(t1,t3);
}
// compile-time literal 16th roots (constant-folded; no memory traffic)
template<int S> __device__ __forceinline__ float2 w16(int m){
  float re, im;
  switch (m & 15){
    case 0:  re= 1.0f;                im= 0.0f;                break;
    case 1:  re= 0.9238795325112867f; im= 0.3826834323650898f; break;
    case 2:  re= 0.7071067811865476f; im= 0.7071067811865476f; break;
    case 3:  re= 0.3826834323650898f; im= 0.9238795325112867f; break;
    case 4:  re= 0.0f;                im= 1.0f;                break;
    case 5:  re=-0.3826834323650898f; im= 0.9238795325112867f; break;
    case 6:  re=-0.7071067811865476f; im= 0.7071067811865476f; break;
    case 7:  re=-0.9238795325112867f; im= 0.3826834323650898f; break;
    case 8:  re=-1.0f;                im= 0.0f;                break;
    case 9:  re=-0.9238795325112867f; im=-0.3826834323650898f; break;
    case 10: re=-0.7071067811865476f; im=-0.7071067811865476f; break;
    case 11: re=-0.3826834323650898f; im=-0.9238795325112867f; break;
    case 12: re= 0.0f;                im=-1.0f;                break;
    case 13: re= 0.3826834323650898f; im=-0.9238795325112867f; break;
    case 14: re= 0.7071067811865476f; im=-0.7071067811865476f; break;
    default: re= 0.9238795325112867f; im=-0.3826834323650898f; break;
  }
  return make_float2(re, (S<0) ? -im : im);
}
template<int S> __device__ __forceinline__ void fft16(float2 v[16]){
  #pragma unroll
  for (int n0=0; n0<4; n0++) dft4<S>(v[n0], v[n0+4], v[n0+8], v[n0+12]);
  #pragma unroll
  for (int n0=1; n0<4; n0++)
    #pragma unroll
    for (int k1=1; k1<4; k1++)
      v[n0+4*k1] = cmul(v[n0+4*k1], w16<S>(n0*k1));
  float2 o[16];
  #pragma unroll
  for (int k1=0; k1<4; k1++){
    float2 a=v[4*k1+0], b=v[4*k1+1], c=v[4*k1+2], d=v[4*k1+3];
    dft4<S>(a,b,c,d);
    o[k1]=a; o[k1+4]=b; o[k1+8]=c; o[k1+12]=d;
  }
  #pragma unroll
  for (int i=0;i<16;i++) v[i]=o[i];
}

template<int S> __device__ __forceinline__ float2 twld(int e){
  float2 w = TW[e & 65535];
  if (S < 0) w.y = -w.y;
  return w;
}

// powers p[k] = base^k via binary tree (depth 4, high ILP)
__device__ __forceinline__ void twpows(float2 base, float2 p[16]){
  p[0] = make_float2(1.0f, 0.0f);
  p[1] = base;
  p[2] = cmul(p[1],p[1]);
  p[3] = cmul(p[2],p[1]);
  p[4] = cmul(p[2],p[2]);
  p[5] = cmul(p[3],p[2]);
  p[6] = cmul(p[3],p[3]);
  p[7] = cmul(p[4],p[3]);
  p[8] = cmul(p[4],p[4]);
  p[9] = cmul(p[5],p[4]);
  p[10]= cmul(p[5],p[5]);
  p[11]= cmul(p[6],p[5]);
  p[12]= cmul(p[6],p[6]);
  p[13]= cmul(p[7],p[6]);
  p[14]= cmul(p[7],p[7]);
  p[15]= cmul(p[8],p[7]);
}

// inter-stage twiddles: v[k1] *= W(i*k1/256), tree powers
template<int S> __device__ __forceinline__ void twiddle256(float2 v[16], int i){
  float2 p[16];
  twpows(twld<S>(i << 8), p);
  #pragma unroll
  for (int k1=1;k1<16;k1++) v[k1] = cmul(v[k1], p[k1]);
}

template<int S> __device__ __forceinline__ void fft256_pad(float2 v[16], int i, float2* sm){
  fft16<S>(v);
  twiddle256<S>(v, i);
  #pragma unroll
  for (int k1=0;k1<16;k1++) sm[k1*16+i] = v[k1];
  __syncthreads();
  #pragma unroll
  for (int n0=0;n0<16;n0++) v[n0] = sm[i*16+n0];
  fft16<S>(v);
}

template<int S> __device__ __forceinline__ void fft256_swz(float2 v[16], int i, float2* sm){
  fft16<S>(v);
  twiddle256<S>(v, i);
  #pragma unroll
  for (int k1=0;k1<16;k1++) sm[k1*16 + ((i+k1)&15)] = v[k1];
  __syncwarp();
  #pragma unroll
  for (int n0=0;n0<16;n0++) v[n0] = sm[i*16 + ((n0+i)&15)];
  fft16<S>(v);
}

// apply out[k] = cmul(v[k], wbase * st^k) using tree powers
template<int S> __device__ __forceinline__ void twout(float2 v[16], int ebase, int estep){
  float2 p[16];
  twpows(twld<S>(estep), p);
  float2 wb = twld<S>(ebase);
  #pragma unroll
  for (int k=0;k<16;k++) v[k] = cmul(v[k], cmul(wb, p[k]));
}

__device__ __forceinline__ void conv_partial(const float* u_s, const float* gf_s,
                                             int bx, int m, float* sp)
{
  float acc = 0.0f;
  #pragma unroll
  for (int f2=0; f2<16; f2++){
    const int q = bx*16 + f2 + 768;
    #pragma unroll
    for (int d=-3; d<=3; d++){
      int tap = d*256 + q;
      if (tap >= 0 && tap <= 1536)
        acc += gf_s[tap] * u_s[f2*257 + ((m + d) & 255)];
    }
  }
  sp[bx*256 + m] = acc;
}

// ---------------- setup kernels ----------------
__global__ void k_tw(){
  int k = blockIdx.x*blockDim.x + threadIdx.x;
  double a = 6.283185307179586476925286766559 * (double)k / 65536.0;
  TW[k] = make_float2((float)cos(a), (float)sin(a));
}
__global__ void k_g(){
  __shared__ float ps[KPHI+1];
  const int tid = threadIdx.x;
  const float invden = 1.0f/(65536.0f*(0.35f/256.0f));
  for (int k=tid; k<=KPHI; k+=256){
    float z = (float)k * invden;
    ps[k] = 2.0f*expf(-0.5f*z*z);
  }
  __syncthreads();
  int i = blockIdx.x*256 + tid;
  if (i >= GTAPS) return;
  int tt = i - LG; if (tt < 0) tt = -tt;
  float acc = 1.0f;
  for (int k=1; k<=KPHI; k++)
    acc += ps[k] * TW[(k*tt) & 65535].x;
  GF[i] = acc * INV_N;
}

// ---------------- FFT pass kernels ----------------
__global__ void __launch_bounds__(256) k_fwd_col_x(const float* __restrict__ x,
                                                   float2* __restrict__ out)
{
  __shared__ float2 sm[16*257];
  const int f = threadIdx.x & 15, i = threadIdx.x >> 4;
  const int col = blockIdx.x*16 + f;
  const size_t base = (size_t)blockIdx.y * NF;
  float2 v[16];
  #pragma unroll
  for (int r=0;r<16;r++) v[r] = make_float2(x[base + (r*16+i)*256 + col], 0.0f);
  fft256_pad<-1>(v, i, sm + f*257);
  twout<-1>(v, col*i, col*16);
  #pragma unroll
  for (int k2=0;k2<16;k2++)
    out[base + (k2*16+i)*256 + col] = v[k2];
}

__global__ void __launch_bounds__(256) k_fwd_row(const float2* __restrict__ in,
                                                 float2* __restrict__ out)
{
  __shared__ float2 sm[16*256];
  const int i = threadIdx.x & 15, f = threadIdx.x >> 4;
  const int row = blockIdx.x*16 + f;
  const size_t base = (size_t)blockIdx.y * NF;
  float2 v[16];
  #pragma unroll
  for (int r=0;r<16;r++) v[r] = in[base + row*256 + r*16 + i];
  fft256_swz<-1>(v, i, sm + f*256);
  #pragma unroll
  for (int k2=0;k2<16;k2++) out[base + row*256 + k2*16 + i] = v[k2];
}

__global__ void __launch_bounds__(256) k_fwd_row_u1(const float2* __restrict__ in,
                                                    __half2* __restrict__ out)
{
  __shared__ float2 sm[16*256];
  const int i = threadIdx.x & 15, f = threadIdx.x >> 4;
  const int row = blockIdx.x*16 + f;
  const int ti = blockIdx.y;
  const int b = ti / FCH, ch = ti - b*FCH;
  const size_t obase = ((size_t)b*JQ + ch) * NF;
  float2 v[16];
  #pragma unroll
  for (int r=0;r<16;r++) v[r] = in[(size_t)ti*NF + row*256 + r*16 + i];
  fft256_swz<-1>(v, i, sm + f*256);
  #pragma unroll
  for (int k2=0;k2<16;k2++){
    float2 o = v[k2];
    out[obase + row*256 + k2*16 + i] = f2h(make_float2(o.x*0.25f, o.y*0.25f));
  }
}

__global__ void __launch_bounds__(256) k_invA1(const float2* __restrict__ in,
                                               float2* __restrict__ out)
{
  __shared__ float2 sm[16*256];
  const int i = threadIdx.x & 15, f = threadIdx.x >> 4;
  const int K1 = blockIdx.x*16 + f;
  const int ti = blockIdx.y;
  const int b = ti / FCH, ch = ti - b*FCH;
  const float xi   = 0.35f * exp2f(-(float)ch * 0.125f);
  const float invs = 8.0f / xi;
  const float2* src = in + (size_t)b*NF;

  float2 v[16];
  #pragma unroll
  for (int r=0;r<16;r++){
    int k = (r*16 + i)*256 + K1;
    float fn = (k < 32768) ? (float)k * INV_N : ((float)k - 65536.0f) * INV_N;
    float z = (fn - xi) * invs;
    if (fabsf(z) < ZCUT){
      float g = expf(-0.5f*z*z);
      float2 X = src[K1*256 + (r*16+i)];
      float s = g * INV_N;
      v[r] = make_float2(X.x*s, X.y*s);
    } else v[r] = make_float2(0.0f, 0.0f);
  }
  fft256_swz<1>(v, i, sm + f*256);
  twout<1>(v, i*K1, 16*K1);
  #pragma unroll
  for (int k2=0;k2<16;k2++)
    out[(size_t)ti*NF + K1*256 + k2*16 + i] = v[k2];
}

__global__ void __launch_bounds__(256) k_invA2(const __half2* __restrict__ in,
                                               __half2* __restrict__ out)
{
  __shared__ float2 sm[16*256];
  const int i = threadIdx.x & 15, f = threadIdx.x >> 4;
  const int K1 = blockIdx.x*16 + f;
  const int ti = blockIdx.y;
  const int b = ti / TS2;
  const int s0 = ti - b*TS2;
  const int j2 = (s0 >= 8) ? 2 : 1;
  const int ch = s0 - 4*j2*(j2-1);
  const float xi   = 0.35f * exp2f(-(float)j2);
  const float invs = 1.0f / (0.6f * xi);
  const __half2* src = in + ((size_t)b*JQ + ch)*NF;

  float2 v[16];
  #pragma unroll
  for (int r=0;r<16;r++){
    int k = (r*16 + i)*256 + K1;
    float fn = (k < 32768) ? (float)k * INV_N : ((float)k - 65536.0f) * INV_N;
    float z = (fn - xi) * invs;
    if (fabsf(z) < ZCUT){
      float g = expf(-0.5f*z*z);
      float2 X = h2f(src[K1*256 + (r*16+i)]);
      float s = g * (16.0f*INV_N);
      v[r] = make_float2(X.x*s, X.y*s);
    } else v[r] = make_float2(0.0f, 0.0f);
  }
  fft256_swz<1>(v, i, sm + f*256);
  twout<1>(v, i*K1, 16*K1);
  #pragma unroll
  for (int k2=0;k2<16;k2++)
    out[(size_t)ti*NF + K1*256 + k2*16 + i] = f2h(v[k2]);
}

__global__ void __launch_bounds__(256) k_fo_b(const float2* __restrict__ T,
                                              float2* __restrict__ out,
                                              float* __restrict__ sp1)
{
  __shared__ __align__(16) char smraw[16*257*sizeof(float2)];
  float2* sm   = (float2*)smraw;
  float*  u_s  = (float*)smraw;
  float*  gf_s = (float*)smraw + 16*257;

  const int f = threadIdx.x & 15, i = threadIdx.x >> 4;
  const int tid = threadIdx.x;
  const int n2 = blockIdx.x*16 + f;
  const int ti = blockIdx.y;
  const int b = ti / FCH, ch = ti - b*FCH;
  const size_t base = (size_t)ti * NF;
  const size_t spo  = ((size_t)b*JQ + ch) * 4096;
  float2 v[16];
  #pragma unroll
  for (int r=0;r<16;r++) v[r] = T[base + (r*16+i)*256 + n2];
  fft256_pad<1>(v, i, sm + f*257);
  __syncthreads();
  #pragma unroll
  for (int k2=0;k2<16;k2++)
    u_s[f*257 + k2*16 + i] = cmag(v[k2]);
  for (int t=tid; t<GTAPS; t+=256) gf_s[t] = GF[t];
  __syncthreads();
  conv_partial(u_s, gf_s, blockIdx.x, tid, sp1 + spo);
  __syncthreads();
  #pragma unroll
  for (int r=0;r<16;r++) v[r] = make_float2(u_s[f*257 + r*16 + i], 0.0f);
  __syncthreads();
  fft256_pad<-1>(v, i, sm + f*257);
  twout<-1>(v, n2*i, n2*16);
  #pragma unroll
  for (int k2=0;k2<16;k2++)
    out[base + (k2*16+i)*256 + n2] = v[k2];
}

__global__ void __launch_bounds__(256) k_invB_abs(const __half2* __restrict__ T,
                                                  float* __restrict__ sp2)
{
  __shared__ __align__(16) char smraw[16*257*sizeof(float2)];
  float2* sm   = (float2*)smraw;
  float*  u_s  = (float*)smraw;
  float*  gf_s = (float*)smraw + 16*257;

  const int f = threadIdx.x & 15, i = threadIdx.x >> 4;
  const int tid = threadIdx.x;
  const int n2 = blockIdx.x*16 + f;
  const int ti = blockIdx.y;
  const int b = ti / TS2, s0 = ti - b*TS2;
  const size_t base = (size_t)ti * NF;
  float2 v[16];
  #pragma unroll
  for (int r=0;r<16;r++) v[r] = h2f(T[base + (r*16+i)*256 + n2]);
  fft256_pad<1>(v, i, sm + f*257);
  __syncthreads();
  #pragma unroll
  for (int k2=0;k2<16;k2++)
    u_s[f*257 + k2*16 + i] = 0.25f*cmag(v[k2]);
  for (int t=tid; t<GTAPS; t+=256) gf_s[t] = GF[t];
  __syncthreads();
  conv_partial(u_s, gf_s, blockIdx.x, tid, sp2 + (size_t)(b*NSEC + s0)*4096);
}

// Fused decimated FIRST ORDER for ch>=32 (N'=4096).
__global__ void __launch_bounds__(256) k_fo4096(const float2* __restrict__ xf,
                                                float* __restrict__ sp1,
                                                float2* __restrict__ u1f4)
{
  extern __shared__ char dyn[];
  float2* sm  = (float2*)dyn;
  float2* sA  = (float2*)dyn + 4112;
  float*  sU  = (float*)dyn;
  float*  g16 = (float*)dyn + 4300;

  const int t = threadIdx.x;
  const int f = t & 15, i = t >> 4;
  const int ch = 32 + blockIdx.x;
  const int b  = blockIdx.y;
  const float xi   = 0.35f * exp2f(-(float)ch * 0.125f);
  const float invs = 8.0f / xi;
  const float kcf  = xi * 65536.0f;
  const float2* src = xf + (size_t)b*NF;

  float2 v[16];
  #pragma unroll
  for (int r=0;r<16;r++){
    int kp = r*256 + i*16 + f;
    int d0 = (int)floorf((kcf - (float)kp) * (1.0f/4096.0f) + 0.5f);
    int k  = (kp + (d0 << 12)) & 65535;
    float fn = (k < 32768) ? (float)k*INV_N : ((float)k - 65536.0f)*INV_N;
    float z = (fn - xi)*invs;
    if (fabsf(z) < ZCUT){
      float g = expf(-0.5f*z*z) * INV_N;
      float2 X = src[(k & 255)*256 + (k >> 8)];
      v[r] = make_float2(X.x*g, X.y*g);
    } else v[r] = make_float2(0.0f, 0.0f);
  }
  fft256_pad<1>(v, i, sm + f*257);
  twout<1>(v, i*f*16, f*256);
  #pragma unroll
  for (int k2=0;k2<16;k2++)
    sA[(k2*16+i)*17 + f] = v[k2];
  __syncthreads();

  {
    float2 w[16];
    #pragma unroll
    for (int kB=0;kB<16;kB++) w[kB] = sA[t*17 + kB];
    fft16<1>(w);
    #pragma unroll
    for (int bb=0;bb<16;bb++){
      int m = t + 256*bb;
      sU[m + (m>>5)] = cmag(w[bb]);
    }
  }
  if (t < 97) g16[t] = GF[16*t];
  __syncthreads();

  {
    float acc = 0.0f;
    for (int j=0;j<97;j++){
      int m = (16*t + j - 48) & 4095;
      acc += g16[j] * sU[m + (m>>5)];
    }
    sp1[((size_t)b*JQ + ch)*4096 + t] = 16.0f*acc;
  }

  float2 c[16];
  #pragma unroll
  for (int mB=0;mB<16;mB++){
    int m = t + 256*mB;
    c[mB] = make_float2(sU[m + (m>>5)], 0.0f);
  }
  fft16<-1>(c);
  twout<-1>(c, 0, t*16);
  #pragma unroll
  for (int q=0;q<16;q++) sA[t*17 + q] = c[q];
  __syncthreads();

  float2 u[16];
  #pragma unroll
  for (int r=0;r<16;r++) u[r] = sA[(r*16+i)*17 + f];
  fft256_pad<-1>(u, i, sm + f*257);
  float2* dst = u1f4 + ((size_t)b*32 + (ch-32))*4096;
  #pragma unroll
  for (int k2=0;k2<16;k2++)
    dst[f + 16*(k2*16 + i)] = u[k2];
}

// Decimated FO for ch in [24,32), N'=8192, pass A.
__global__ void __launch_bounds__(256) k_fo8kA(const float2* __restrict__ xf,
                                               float2* __restrict__ scrA)
{
  __shared__ float2 sm[16*257];
  const int f = threadIdx.x & 15, i = threadIdx.x >> 4;
  const int h = blockIdx.x, idx8 = blockIdx.y, b = blockIdx.z;
  const int ch = 24 + idx8;
  const float xi   = 0.35f * exp2f(-(float)ch * 0.125f);
  const float invs = 8.0f / xi;
  const float kcf  = xi * 65536.0f;
  const float2* src = xf + (size_t)b*NF;
  const int kB = h*16 + f;

  float2 v[16];
  #pragma unroll
  for (int r=0;r<16;r++){
    int kA = r*16 + i;
    int kp = kA*32 + kB;
    int d0 = (int)floorf((kcf - (float)kp) * (1.0f/8192.0f) + 0.5f);
    int k  = (kp + (d0 << 13)) & 65535;
    float fn = (k < 32768) ? (float)k*INV_N : ((float)k - 65536.0f)*INV_N;
    float z = (fn - xi)*invs;
    if (fabsf(z) < ZCUT){
      float g = expf(-0.5f*z*z) * INV_N;
      float2 X = src[(k & 255)*256 + (k >> 8)];
      v[r] = make_float2(X.x*g, X.y*g);
    } else v[r] = make_float2(0.0f, 0.0f);
  }
  fft256_pad<1>(v, i, sm + f*257);
  twout<1>(v, i*kB*8, kB*128);
  float2* dst = scrA + ((size_t)(b*8 + idx8))*8192;
  #pragma unroll
  for (int k2=0;k2<16;k2++)
    dst[(k2*16+i)*32 + kB] = v[k2];
}

__global__ void __launch_bounds__(256) k_fo8kBC(const float2* __restrict__ scrA,
                                                float* __restrict__ sp1,
                                                float2* __restrict__ scrW)
{
  __shared__ float sU[8448];
  __shared__ float g8[193];
  const int t = threadIdx.x;
  const int idx8 = blockIdx.x, b = blockIdx.y;
  const float2* s = scrA + ((size_t)(b*8 + idx8))*8192 + (size_t)t*32;

  {
    float2 E[16], O[16];
    #pragma unroll
    for (int k=0;k<16;k++){ E[k] = s[2*k]; O[k] = s[2*k+1]; }
    fft16<1>(E); fft16<1>(O);
    #pragma unroll
    for (int k=0;k<16;k++){
      float2 w = w16<1>(k);  // W32^k? no: TW[k*2048] = e^{2pi i k/32}
      w = TW[k*2048];
      float2 wo = cmul(w, O[k]);
      int m0 = k*256 + t;
      int m1 = (k+16)*256 + t;
      sU[m0 + (m0>>5)] = cmag(cadd(E[k], wo));
      sU[m1 + (m1>>5)] = cmag(csub(E[k], wo));
    }
  }
  if (t < 193) g8[t] = GF[8*t];
  __syncthreads();

  {
    float acc = 0.0f;
    for (int j=0;j<193;j++){
      int m = (32*t + j - 96) & 8191;
      acc += g8[j] * sU[m + (m>>5)];
    }
    sp1[((size_t)b*JQ + 24 + idx8)*4096 + t] = 8.0f*acc;
  }

  {
    float2 E[16], O[16];
    #pragma unroll
    for (int k=0;k<16;k++){
      int me = (2*k)*256 + t, mo = (2*k+1)*256 + t;
      E[k] = make_float2(sU[me + (me>>5)], 0.0f);
      O[k] = make_float2(sU[mo + (mo>>5)], 0.0f);
    }
    fft16<-1>(E); fft16<-1>(O);
    float2* dst = scrW + ((size_t)(b*8 + idx8))*8192;
    float2 p[16];
    twpows(twld<-1>(t*8), p);
    const float2 sh = twld<-1>(t*128);
    #pragma unroll
    for (int k=0;k<16;k++){
      float2 w = TW[k*2048]; w.y = -w.y;
      float2 wo = cmul(w, O[k]);
      float2 X0 = cadd(E[k], wo);
      float2 X1 = csub(E[k], wo);
      dst[k*256 + t]      = cmul(X0, p[k]);
      dst[(k+16)*256 + t] = cmul(X1, cmul(p[k], sh));
    }
  }
}

__global__ void __launch_bounds__(256) k_fo8kC2(const float2* __restrict__ scrW,
                                                float2* __restrict__ u1f8)
{
  __shared__ float2 sm[16*256];
  const int i = threadIdx.x & 15, f = threadIdx.x >> 4;
  const int h = blockIdx.x, idx8 = blockIdx.y, b = blockIdx.z;
  const int kB = h*16 + f;
  const size_t base = (size_t)(b*8 + idx8)*8192;
  float2 v[16];
  #pragma unroll
  for (int r=0;r<16;r++) v[r] = scrW[base + kB*256 + r*16 + i];
  fft256_swz<-1>(v, i, sm + f*256);
  float2* dst = u1f8 + base;
  #pragma unroll
  for (int k2=0;k2<16;k2++)
    dst[(k2*16 + i)*32 + kB] = v[k2];
}

// Fused decimated SO, N'=4096, M=16 (j2 in {6,7}). 3-way source.
__global__ void __launch_bounds__(256) k_so4096(const __half2* __restrict__ u1f,
                                                const float2* __restrict__ u1f4,
                                                const float2* __restrict__ u1f8,
                                                float* __restrict__ sp2)
{
  extern __shared__ char dyn[];
  float2* sm  = (float2*)dyn;
  float2* sA  = (float2*)dyn + 4112;
  float*  sU  = (float*)dyn;
  float*  g16 = (float*)dyn + 4300;

  const int t = threadIdx.x;
  const int f = t & 15, i = t >> 4;
  const int s0 = 120 + blockIdx.x;
  const int b  = blockIdx.y;
  const int j2 = (s0 >= 168) ? 7 : 6;
  const int ch = s0 - 4*j2*(j2-1);
  const float xi   = 0.35f * exp2f(-(float)j2);
  const float invs = 1.0f/(0.6f*xi);
  const float kcf  = xi * 65536.0f;
  const __half2* src  = u1f  + ((size_t)b*JQ + ch)*NF;
  const float2*  src4 = u1f4 + ((size_t)b*32 + (ch-32))*4096;
  const float2*  src8 = u1f8 + ((size_t)(b*8 + (ch-24)))*8192;

  float2 v[16];
  #pragma unroll
  for (int r=0;r<16;r++){
    int kp = r*256 + i*16 + f;
    int d0 = (int)floorf((kcf - (float)kp) * (1.0f/4096.0f) + 0.5f);
    if (ch < 24){
      float2 a = make_float2(0.0f, 0.0f);
      #pragma unroll
      for (int dd=-1; dd<=1; dd++){
        int k  = (kp + ((d0+dd) << 12)) & 65535;
        float fn = (k < 32768) ? (float)k*INV_N : ((float)k - 65536.0f)*INV_N;
        float z = (fn - xi)*invs;
        if (fabsf(z) < ZCUT){
          float g = expf(-0.5f*z*z);
          float2 X = h2f(src[(k & 255)*256 + (k >> 8)]);
          float s = g * (4.0f*INV_N);
          a.x += X.x*s; a.y += X.y*s;
        }
      }
      v[r] = a;
    } else if (ch < 32){
      float2 a = make_float2(0.0f, 0.0f);
      #pragma unroll
      for (int dd=-1; dd<=1; dd++){
        int k  = (kp + ((d0+dd) << 12)) & 65535;
        float fn = (k < 32768) ? (float)k*INV_N : ((float)k - 65536.0f)*INV_N;
        float z = (fn - xi)*invs;
        if (fabsf(z) < ZCUT){
          float g = expf(-0.5f*z*z);
          float2 X = src8[k & 8191];
          float s = g * (8.0f*INV_N);
          a.x += X.x*s; a.y += X.y*s;
        }
      }
      v[r] = a;
    } else {
      float gsum = 0.0f;
      #pragma unroll
      for (int dd=-1; dd<=1; dd++){
        int k  = (kp + ((d0+dd) << 12)) & 65535;
        float fn = (k < 32768) ? (float)k*INV_N : ((float)k - 65536.0f)*INV_N;
        float z = (fn - xi)*invs;
        if (fabsf(z) < ZCUT) gsum += expf(-0.5f*z*z);
      }
      if (gsum != 0.0f){
        float2 X = src4[kp];
        float s = gsum * (16.0f*INV_N);
        v[r] = make_float2(X.x*s, X.y*s);
      } else v[r] = make_float2(0.0f, 0.0f);
    }
  }
  fft256_pad<1>(v, i, sm + f*257);
  twout<1>(v, i*f*16, f*256);
  #pragma unroll
  for (int k2=0;k2<16;k2++)
    sA[(k2*16+i)*17 + f] = v[k2];
  __syncthreads();

  {
    float2 w[16];
    #pragma unroll
    for (int kB=0;kB<16;kB++) w[kB] = sA[t*17 + kB];
    fft16<1>(w);
    #pragma unroll
    for (int bb=0;bb<16;bb++){
      int m = t + 256*bb;
      sU[m + (m>>5)] = cmag(w[bb]);
    }
  }
  if (t < 97) g16[t] = GF[16*t];
  __syncthreads();

  float acc = 0.0f;
  for (int j=0;j<97;j++){
    int m = (16*t + j - 48) & 4095;
    acc += g16[j] * sU[m + (m>>5)];
  }
  sp2[(size_t)(b*NSEC + s0)*4096 + t] = 16.0f*acc;
}

// Decimated SO at N'=8192 pass A (j2 in {3,4,5}), phase shift tau.
__global__ void __launch_bounds__(256) k_so8kA(const __half2* __restrict__ u1f,
                                               const float2* __restrict__ u1f4,
                                               const float2* __restrict__ u1f8,
                                               float2* __restrict__ scr,
                                               int nstride, int tau)
{
  __shared__ float2 sm[16*257];
  const int f = threadIdx.x & 15, i = threadIdx.x >> 4;
  const int h = blockIdx.x, idx = blockIdx.y, b = blockIdx.z;
  const int j2 = (idx < 24) ? 3 : ((idx < 56) ? 4 : 5);
  const int ch = (idx < 24) ? idx : ((idx < 56) ? idx-24 : idx-56);
  const int ext = (j2 == 3) ? 2 : 1;
  const float xi   = 0.35f * exp2f(-(float)j2);
  const float invs = 1.0f/(0.6f*xi);
  const float kcf  = xi * 65536.0f;
  const __half2* src  = u1f  + ((size_t)b*JQ + ch)*NF;
  const float2*  src4 = u1f4 + ((size_t)b*32 + (ch-32))*4096;
  const float2*  src8 = u1f8 + ((size_t)(b*8 + (ch-24)))*8192;
  const int kB = h*16 + f;

  float2 v[16];
  #pragma unroll
  for (int r=0;r<16;r++){
    int kA = r*16 + i;
    int kp = kA*32 + kB;
    int d0 = (int)floorf((kcf - (float)kp) * (1.0f/8192.0f) + 0.5f);
    if (ch < 24){
      float2 a = make_float2(0.0f, 0.0f);
      for (int dd=-ext; dd<=ext; dd++){
        int k  = (kp + ((d0+dd) << 13)) & 65535;
        float fn = (k < 32768) ? (float)k*INV_N : ((float)k - 65536.0f)*INV_N;
        float z = (fn - xi)*invs;
        if (fabsf(z) < ZCUT){
          float g = expf(-0.5f*z*z);
          float2 X = h2f(src[(k & 255)*256 + (k >> 8)]);
          if (tau){ X = cmul(X, TW[(k*tau)&65535]); }
          float s = g * (4.0f*INV_N);
          a.x += X.x*s; a.y += X.y*s;
        }
      }
      v[r] = a;
    } else {
      float gsum = 0.0f;
      #pragma unroll
      for (int dd=-1; dd<=1; dd++){
        int k  = (kp + ((d0+dd) << 13)) & 65535;
        float fn = (k < 32768) ? (float)k*INV_N : ((float)k - 65536.0f)*INV_N;
        float z = (fn - xi)*invs;
        if (fabsf(z) < ZCUT) gsum += expf(-0.5f*z*z);
      }
      if (gsum != 0.0f){
        if (ch < 32){
          float2 X = src8[kp];
          float s = gsum * (8.0f*INV_N);
          v[r] = make_float2(X.x*s, X.y*s);
        } else {
          float2 X = src4[kp & 4095];
          float s = gsum * (16.0f*INV_N);
          v[r] = make_float2(X.x*s, X.y*s);
        }
      } else v[r] = make_float2(0.0f, 0.0f);
    }
  }
  fft256_pad<1>(v, i, sm + f*257);
  twout<1>(v, i*kB*8, kB*128);
  float2* dst = scr + ((size_t)(b*nstride + idx))*8192;
  #pragma unroll
  for (int k2=0;k2<16;k2++)
    dst[(k2*16+i)*32 + kB] = v[k2];
}

__global__ void __launch_bounds__(256) k_so8kB(const float2* __restrict__ scr,
                                               float* __restrict__ sp2)
{
  __shared__ float sU[8448];
  __shared__ float g8[193];
  const int t = threadIdx.x;
  const int idx = blockIdx.x + 24, b = blockIdx.y;
  const float2* s = scr + ((size_t)(b*NS8 + idx))*8192 + (size_t)t*32;

  float2 E[16], O[16];
  #pragma unroll
  for (int k=0;k<16;k++){ E[k] = s[2*k]; O[k] = s[2*k+1]; }
  fft16<1>(E); fft16<1>(O);
  #pragma unroll
  for (int k=0;k<16;k++){
    float2 w = TW[k*2048];
    float2 wo = cmul(w, O[k]);
    int m0 = k*256 + t;
    int m1 = (k+16)*256 + t;
    sU[m0 + (m0>>5)] = cmag(cadd(E[k], wo));
    sU[m1 + (m1>>5)] = cmag(csub(E[k], wo));
  }
  if (t < 193) g8[t] = GF[8*t];
  __syncthreads();

  float acc = 0.0f;
  for (int j=0;j<193;j++){
    int m = (32*t + j - 96) & 8191;
    acc += g8[j] * sU[m + (m>>5)];
  }
  const int s0 = TS2 + idx;
  sp2[(size_t)(b*NSEC + s0)*4096 + t] = 8.0f*acc;
}

__global__ void __launch_bounds__(256) k_so8kB_j3(const float2* __restrict__ scr0,
                                                  const float2* __restrict__ scr1,
                                                  float* __restrict__ sp2)
{
  extern __shared__ char dyn[];
  float* sU0 = (float*)dyn;
  float* sU1 = (float*)dyn + 8448;
  float* ge  = (float*)dyn + 16896;
  float* go  = (float*)dyn + 17089;
  const int t = threadIdx.x;
  const int idx = blockIdx.x, b = blockIdx.y;

  #pragma unroll
  for (int ph=0; ph<2; ph++){
    const float2* s = (ph ? scr1 + ((size_t)(b*24 + idx))*8192
                          : scr0 + ((size_t)(b*NS8 + idx))*8192) + (size_t)t*32;
    float* sU = ph ? sU1 : sU0;
    float2 E[16], O[16];
    #pragma unroll
    for (int k=0;k<16;k++){ E[k] = s[2*k]; O[k] = s[2*k+1]; }
    fft16<1>(E); fft16<1>(O);
    #pragma unroll
    for (int k=0;k<16;k++){
      float2 w = TW[k*2048];
      float2 wo = cmul(w, O[k]);
      int m0 = k*256 + t;
      int m1 = (k+16)*256 + t;
      sU[m0 + (m0>>5)] = cmag(cadd(E[k], wo));
      sU[m1 + (m1>>5)] = cmag(csub(E[k], wo));
    }
  }
  if (t < 193) ge[t] = GF[8*t];
  if (t < 192) go[t] = GF[8*t+4];
  __syncthreads();

  float acc = 0.0f;
  for (int j=0;j<193;j++){
    int m = (32*t + j - 96) & 8191;
    int ms = m + (m>>5);
    acc += ge[j] * sU0[ms];
    if (j < 192) acc += go[j] * sU1[ms];
  }
  const int s0 = TS2 + idx;
  sp2[(size_t)(b*NSEC + s0)*4096 + t] = 4.0f*acc;
}

// ---------------- S0 conv ----------------
#define CONV_OUT 32
#define CONV_WIN ((CONV_OUT-1)*256 + GTAPS)
__global__ void __launch_bounds__(256) k_conv_x(const float* __restrict__ x,
                                                float* __restrict__ out)
{
  const int grp = blockIdx.x, b = blockIdx.y;
  const float* src = x + (size_t)b*NF;
  __shared__ float win[CONV_WIN + 3];
  __shared__ float gs[GTAPS];
  const int tid = threadIdx.x;
  const int w0 = grp*(CONV_OUT*256) - LG;
  for (int i=tid; i<CONV_WIN; i+=256) win[i] = src[(w0 + i) & 65535];
  for (int i=tid; i<GTAPS; i+=256) gs[i] = GF[i];
  __syncthreads();
  const int warp = tid >> 5, lane = tid & 31;
  #pragma unroll
  for (int oo=0; oo<CONV_OUT/8; oo++){
    const int o = warp*(CONV_OUT/8) + oo;
    const int off = o * 256;
    float acc = 0.0f;
    for (int i=lane; i<GTAPS; i+=32) acc += gs[i] * win[off + i];
    #pragma unroll
    for (int d=16; d; d>>=1) acc += __shfl_down_sync(0xffffffffu, acc, d);
    if (lane == 0){
      int n = grp*CONV_OUT + o;
      float mag = sqrtf(acc*acc + 1e-8f);
      out[(size_t)b*NCHAN*256 + n] = logf(mag + 1e-8f);
    }
  }
}

// ---------------- epilogue (slot-aware) ----------------
__global__ void __launch_bounds__(256) k_log(const float* __restrict__ sp1,
                                             const float* __restrict__ sp2,
                                             float* __restrict__ out)
{
  const int row = blockIdx.x;
  const int b = row / 288, cm1 = row - b*288;
  const int m = threadIdx.x;
  const float* base;
  bool full;
  if (cm1 < 64){
    base = sp1 + (size_t)(b*JQ + cm1)*4096;
    full = (cm1 < FCH);
  } else {
    int s0 = cm1 - 64;
    base = sp2 + (size_t)(b*NSEC + s0)*4096;
    full = (s0 < TS2);
  }
  float S = base[m];
  if (full){
    #pragma unroll
    for (int k=1;k<16;k++) S += base[k*256 + m];
  }
  float mag = sqrtf(S*S + 1e-8f);
  out[((size_t)b*NCHAN + 1 + cm1)*256 + m] = logf(mag + 1e-8f);
}

__global__ void k_zero(float* p, int n){
  int i = blockIdx.x*blockDim.x + threadIdx.x;
  if (i < n) p[i] = 0.0f;
}

// ---------------- launch ----------------
extern "C" void kernel_launch(void* const* d_in, const int* in_sizes, int n_in,
                              void* d_out, int out_size)
{
  (void)in_sizes; (void)n_in;
  const float* x = (const float*)d_in[0];
  float* out = (float*)d_out;

  float2 *xtmp, *xf, *p1a, *p1b, *u1f4, *u1f8;
  __half2 *p2, *u1f;
  float *sp1, *sp2;
  cudaGetSymbolAddress((void**)&xtmp, d_xtmp);
  cudaGetSymbolAddress((void**)&xf,   d_xf);
  cudaGetSymbolAddress((void**)&p1a,  d_p1a);
  cudaGetSymbolAddress((void**)&p1b,  d_p1b);
  cudaGetSymbolAddress((void**)&p2,   d_p2);
  cudaGetSymbolAddress((void**)&u1f,  d_u1f);
  cudaGetSymbolAddress((void**)&u1f4, d_u1f4);
  cudaGetSymbolAddress((void**)&u1f8, d_u1f8);
  cudaGetSymbolAddress((void**)&sp1,  d_sp1);
  cudaGetSymbolAddress((void**)&sp2,  d_sp2);
  float2* scrA = p1a;
  float2* scrW = p1a + (size_t)64*8192;
  float2* scr0 = p1a;
  float2* scr1 = p1a + (size_t)NS8*NB*8192;

  static int smem_set = 0;
  if (!smem_set){
    cudaFuncSetAttribute(k_so4096,   cudaFuncAttributeMaxDynamicSharedMemorySize, 69632);
    cudaFuncSetAttribute(k_fo4096,   cudaFuncAttributeMaxDynamicSharedMemorySize, 69632);
    cudaFuncSetAttribute(k_so8kB_j3, cudaFuncAttributeMaxDynamicSharedMemorySize, 70656);
    smem_set = 1;
  }

  k_tw<<<256, 256>>>();
  k_g <<<7,   256>>>();

  // forward FFT of x
  k_fwd_col_x<<<dim3(16,8), 256>>>(x, xtmp);
  k_fwd_row  <<<dim3(16,8), 256>>>(xtmp, xf);

  // first order, full-res channels ch<24
  k_invA1     <<<dim3(16,192), 256>>>(xf, p1a);
  k_fo_b      <<<dim3(16,192), 256>>>(p1a, p1b, sp1);
  k_fwd_row_u1<<<dim3(16,192), 256>>>(p1b, u1f);

  // first order, decimated: ch in [24,32) at N'=8192
  k_fo8kA <<<dim3(2, 8, NB), 256>>>(xf, scrA);
  k_fo8kBC<<<dim3(8, NB),    256>>>(scrA, sp1, scrW);
  k_fo8kC2<<<dim3(2, 8, NB), 256>>>(scrW, u1f8);

  // first order, decimated: ch>=32 at N'=4096 (fused)
  k_fo4096<<<dim3(32, NB), 256, 69632>>>(xf, sp1, u1f4);

  // second order, full-res sections (j2 <= 2)
  k_invA2   <<<dim3(16, 8*TS2), 256>>>(u1f, p2);
  k_invB_abs<<<dim3(16, 8*TS2), 256>>>(p2, sp2);

  // second order, decimated: j2 in {3,4,5} at N'=8192 (j2=3 two-phase)
  k_so8kA<<<dim3(2, NS8, NB), 256>>>(u1f, u1f4, u1f8, scr0, NS8, 0);
  k_so8kA<<<dim3(2, 24,  NB), 256>>>(u1f, u1f4, u1f8, scr1, 24, 4);
  k_so8kB   <<<dim3(NS8-24, NB), 256>>>(scr0, sp2);
  k_so8kB_j3<<<dim3(24, NB), 256, 70656>>>(scr0, scr1, sp2);

  // second order, decimated: j2 in {6,7} at N'=4096 (fused)
  k_so4096<<<dim3(104, NB), 256, 69632>>>(u1f, u1f4, u1f8, sp2);

  // S0 + epilogue
  k_conv_x<<<dim3(8, NB), 256>>>(x, out);
  k_log   <<<2304, 256>>>(sp1, sp2, out);

  int half = out_size / 2;
  k_zero<<<(half + 255)/256, 256>>>(out + half, half);
}